// round 7
// baseline (speedup 1.0000x reference)
#include <cuda_runtime.h>
#include <cuda_bf16.h>
#include <math.h>
#include <stdint.h>

#define Nn0 2000
#define Nn1 6000
#define Nn2 4000
#define CC  128

// ================= static scratch (no allocation) =================
__device__ float g_h0[Nn0 * CC];
__device__ float g_h1[Nn1 * CC];
__device__ float g_h2[Nn2 * CC];
__device__ float g_X0f[Nn0 * 6  * CC];
__device__ float g_X1f[Nn1 * 12 * CC];
__device__ float g_X2f[Nn2 * 8  * CC];

// scale slots
__device__ float g_sc[32];
// 0 L0, 1 L1d, 2 L1u, 3 L2d, 4 L2u, 5 B1, 6 B2, 7-9 h0..h2,
// 10-13 first-hop slices, 14-18 second-hop slices, 19-21 X full, 22-27 weights

// int8 2-digit operators
__device__ int8_t g_L0a[Nn0 * Nn0],  g_L0b[Nn0 * Nn0];
__device__ int8_t g_L1da[Nn1 * Nn1], g_L1db[Nn1 * Nn1];
__device__ int8_t g_L1ua[Nn1 * Nn1], g_L1ub[Nn1 * Nn1];
__device__ int8_t g_L2da[Nn2 * Nn2], g_L2db[Nn2 * Nn2];
__device__ int8_t g_L2ua[Nn2 * Nn2], g_L2ub[Nn2 * Nn2];
__device__ int8_t g_B1a[Nn0 * Nn1],  g_B1b[Nn0 * Nn1];
__device__ int8_t g_B1ta[Nn1 * Nn0], g_B1tb[Nn1 * Nn0];
__device__ int8_t g_B2a[Nn1 * Nn2],  g_B2b[Nn1 * Nn2];
__device__ int8_t g_B2ta[Nn2 * Nn1], g_B2tb[Nn2 * Nn1];

// einsum A operands (quantized X)
__device__ int8_t g_X0qa[Nn0 * 6 * CC],  g_X0qb[Nn0 * 6 * CC];
__device__ int8_t g_X1qa[Nn1 * 12 * CC], g_X1qb[Nn1 * 12 * CC];
__device__ int8_t g_X2qa[Nn2 * 8 * CC],  g_X2qb[Nn2 * 8 * CC];

// transposed quantized B-operand buffers
__device__ int8_t g_bt0a[256 * Nn0],  g_bt0b[256 * Nn0];
__device__ int8_t g_bt1aa[256 * Nn1], g_bt1ab[256 * Nn1];
__device__ int8_t g_bt1ba[256 * Nn1], g_bt1bb[256 * Nn1];
__device__ int8_t g_bt2a[256 * Nn2],  g_bt2b[256 * Nn2];
__device__ int8_t g_bt2ba[128 * Nn2], g_bt2bb[128 * Nn2];
__device__ int8_t g_bh0a[CC * Nn0],   g_bh0b[CC * Nn0];
__device__ int8_t g_bh1a[CC * Nn1],   g_bh1b[CC * Nn1];
__device__ int8_t g_bh2a[CC * Nn2],   g_bh2b[CC * Nn2];

// einsum weights quantized, transposed [128, S*128]
__device__ int8_t g_W0qa[CC * 6 * CC],  g_W0qb[CC * 6 * CC];
__device__ int8_t g_W1qa[CC * 12 * CC], g_W1qb[CC * 12 * CC];
__device__ int8_t g_W2qa[CC * 8 * CC],  g_W2qb[CC * 8 * CC];

__constant__ int c_maps[3][12] = {
    {0, 3, 1, 4, 2, 5, -1, -1, -1, -1, -1, -1},
    {0, 5, -1, 8, 1, 6, 3, 9, 2, 7, 4, 10},
    {0, 5, 1, 6, 2, 7, 3, 4, -1, -1, -1, -1},
};

// ================= PTX helpers (plain sm_80+ PTX) =================
__device__ __forceinline__ uint32_t smem_u32(const void* p) {
    uint32_t a;
    asm("{ .reg .u64 t; cvta.to.shared.u64 t, %1; cvt.u32.u64 %0, t; }" : "=r"(a) : "l"(p));
    return a;
}
__device__ __forceinline__ void ldsm_x4(uint32_t* r, uint32_t a) {
    asm volatile("ldmatrix.sync.aligned.m8n8.x4.shared.b16 {%0,%1,%2,%3}, [%4];"
                 : "=r"(r[0]), "=r"(r[1]), "=r"(r[2]), "=r"(r[3]) : "r"(a));
}
__device__ __forceinline__ void imma_s8(int* c, const uint32_t* a, const uint32_t* b) {
    asm volatile(
        "mma.sync.aligned.m16n8k32.row.col.s32.s8.s8.s32 "
        "{%0,%1,%2,%3}, {%4,%5,%6,%7}, {%8,%9}, {%0,%1,%2,%3};"
        : "+r"(c[0]), "+r"(c[1]), "+r"(c[2]), "+r"(c[3])
        : "r"(a[0]), "r"(a[1]), "r"(a[2]), "r"(a[3]), "r"(b[0]), "r"(b[1]));
}
__device__ __forceinline__ void cp_async16(uint32_t dst, const void* src, int sz) {
    asm volatile("cp.async.cg.shared.global [%0], [%1], 16, %2;"
                 :: "r"(dst), "l"(src), "r"(sz));
}
// swizzled byte addr within a [128 rows x 32 int8] tile (32B rows, 16B chunks)
__device__ __forceinline__ uint32_t sw8(uint32_t tile_base, int r, int c) {
    return tile_base + (uint32_t)(r * 32) + (uint32_t)((c ^ ((r >> 2) & 1)) << 4);
}

// ================= batched 2-digit int8 IMMA GEMM =================
// C = sa*sb/127^2 * (Aq0 + Aq1/127)(Bq0 + Bq1/127)^T, digits int8 K-major [*,K].
// CTA tile 128x128, BK=32, 4-stage cp.async pipeline, 16KB/stage.
#define MM_SMEM (4 * 4 * 4096)
#define MAXJOB 6

struct MMJob {
    const int8_t *A0, *A1, *B0, *B1;
    float* C;
    int M, K, lda, ldb, ldc, tileStart, tilesX, slotA, slotB;
};
struct MMParams { MMJob j[MAXJOB]; int n; };

__global__ __launch_bounds__(256)
void mmq_kernel(MMParams P)
{
    extern __shared__ __align__(128) char smem[];
    const uint32_t sbase = smem_u32(smem);
    const int tid = threadIdx.x, lane = tid & 31, wid = tid >> 5;
    const int wm = wid & 1, wn = wid >> 1;

    int bt = blockIdx.x;
    int ji = 0;
#pragma unroll 1
    while (ji + 1 < P.n && bt >= P.j[ji + 1].tileStart) ji++;
    const MMJob jb = P.j[ji];
    const int rel = bt - jb.tileStart;
    const int m0 = (rel % jb.tilesX) * 128;
    const int n0 = (rel / jb.tilesX) * 128;
    const int M = jb.M, K = jb.K, lda = jb.lda, ldb = jb.ldb, ldc = jb.ldc;
    const int mrows = (M - m0 < 128) ? (M - m0) : 128;
    const int8_t* A0 = jb.A0 + (size_t)m0 * lda;
    const int8_t* A1 = jb.A1 + (size_t)m0 * lda;
    const int8_t* B0 = jb.B0 + (size_t)n0 * ldb;
    const int8_t* B1 = jb.B1 + (size_t)n0 * ldb;
    float* C = jb.C;
    const int nk = (K + 31) >> 5;

    int acc0[4][4][4], acc1[4][4][4];
#pragma unroll
    for (int i = 0; i < 4; i++)
#pragma unroll
        for (int j = 0; j < 4; j++)
#pragma unroll
            for (int v = 0; v < 4; v++) { acc0[i][j][v] = 0; acc1[i][j][v] = 0; }

    auto load_stage = [&](int t) {
        const uint32_t sb = sbase + (uint32_t)(t & 3) * 16384;
        const int k0 = t << 5;
        const int r = tid >> 1, c = tid & 1;
#pragma unroll
        for (int i = 0; i < 4; i++) {
            const int8_t* gp;
            int ok;
            if (i < 2) {
                gp = (i == 0 ? A0 : A1) + (size_t)r * lda + k0 + c * 16;
                ok = (r < mrows) && (k0 + c * 16 < K);
            } else {
                gp = (i == 2 ? B0 : B1) + (size_t)r * ldb + k0 + c * 16;
                ok = (k0 + c * 16 < K);
            }
            cp_async16(sw8(sb + (uint32_t)i * 4096, r, c), gp, ok ? 16 : 0);
        }
    };

#pragma unroll
    for (int s = 0; s < 3; s++) {
        if (s < nk) load_stage(s);
        asm volatile("cp.async.commit_group;" ::: "memory");
    }

    const int frag_r = lane & 15;
    const int frag_c = lane >> 4;   // 16B chunk within k32 row

    for (int t = 0; t < nk; t++) {
        asm volatile("cp.async.wait_group 2;" ::: "memory");
        __syncthreads();
        const uint32_t sb = sbase + (uint32_t)(t & 3) * 16384;
        const uint32_t tA0 = sb, tA1 = sb + 4096, tB0 = sb + 8192, tB1 = sb + 12288;

        uint32_t b0[4][2], b1[4][2];
#pragma unroll
        for (int j = 0; j < 2; j++) {
            int r = wn * 32 + j * 16 + frag_r;
            uint32_t rr[4];
            ldsm_x4(rr, sw8(tB0, r, frag_c));
            b0[2 * j][0] = rr[0]; b0[2 * j][1] = rr[2];
            b0[2 * j + 1][0] = rr[1]; b0[2 * j + 1][1] = rr[3];
            ldsm_x4(rr, sw8(tB1, r, frag_c));
            b1[2 * j][0] = rr[0]; b1[2 * j][1] = rr[2];
            b1[2 * j + 1][0] = rr[1]; b1[2 * j + 1][1] = rr[3];
        }
#pragma unroll
        for (int mt = 0; mt < 4; mt++) {
            int r = wm * 64 + mt * 16 + frag_r;
            uint32_t a0[4], a1[4];
            ldsm_x4(a0, sw8(tA0, r, frag_c));
            ldsm_x4(a1, sw8(tA1, r, frag_c));
#pragma unroll
            for (int nt = 0; nt < 4; nt++) {
                imma_s8(acc0[mt][nt], a0, b0[nt]);
                imma_s8(acc1[mt][nt], a0, b1[nt]);
                imma_s8(acc1[mt][nt], a1, b0[nt]);
            }
        }
        if (t + 3 < nk) load_stage(t + 3);
        asm volatile("cp.async.commit_group;" ::: "memory");
    }

    const float sab = g_sc[jb.slotA] * g_sc[jb.slotB] * (1.f / 16129.f);
    const int er = lane >> 2, ec = (lane & 3) * 2;
#pragma unroll
    for (int mt = 0; mt < 4; mt++) {
        int row0 = m0 + wm * 64 + mt * 16 + er;
#pragma unroll
        for (int nt = 0; nt < 4; nt++) {
            int col = n0 + wn * 32 + nt * 8 + ec;
            float f0 = ((float)acc0[mt][nt][0] + (float)acc1[mt][nt][0] * (1.f / 127.f)) * sab;
            float f1 = ((float)acc0[mt][nt][1] + (float)acc1[mt][nt][1] * (1.f / 127.f)) * sab;
            float f2 = ((float)acc0[mt][nt][2] + (float)acc1[mt][nt][2] * (1.f / 127.f)) * sab;
            float f3 = ((float)acc0[mt][nt][3] + (float)acc1[mt][nt][3] * (1.f / 127.f)) * sab;
            if (row0 < M)
                *(float2*)&C[(size_t)row0 * ldc + col] = make_float2(f0, f1);
            if (row0 + 8 < M)
                *(float2*)&C[(size_t)(row0 + 8) * ldc + col] = make_float2(f2, f3);
        }
    }
}

// ================= scale utilities =================
__global__ void clear_sc_kernel(int lo, int hi)
{
    int i = lo + (int)threadIdx.x;
    if (i < hi) g_sc[i] = 0.f;
}

struct AJob { const float* src; int rows, cols, ld, slot, blkStart; };
struct AParams { AJob j[16]; int n; };

__global__ void amaxb_kernel(AParams P)
{
    int b = blockIdx.x;
    int ji = 0;
#pragma unroll 1
    while (ji + 1 < P.n && b >= P.j[ji + 1].blkStart) ji++;
    const AJob jb = P.j[ji];
    const int rel = b - jb.blkStart;
    const int tot = jb.rows * jb.cols;
    const int base = rel * 4096;
    float m = 0.f;
    for (int i = threadIdx.x; i < 4096; i += 256) {
        int idx = base + i;
        if (idx < tot) {
            int r = idx / jb.cols, c = idx - r * jb.cols;
            m = fmaxf(m, fabsf(jb.src[(size_t)r * jb.ld + c]));
        }
    }
#pragma unroll
    for (int off = 16; off; off >>= 1)
        m = fmaxf(m, __shfl_xor_sync(0xFFFFFFFFu, m, off));
    __shared__ float wmax[8];
    if ((threadIdx.x & 31) == 0) wmax[threadIdx.x >> 5] = m;
    __syncthreads();
    if (threadIdx.x == 0) {
        float mm = wmax[0];
#pragma unroll
        for (int w = 1; w < 8; w++) mm = fmaxf(mm, wmax[w]);
        atomicMax((unsigned int*)&g_sc[jb.slot], __float_as_uint(mm));
    }
}

// ================= quantize helpers =================
__device__ __forceinline__ void quant2(float v, float inv, int& q0, int& q1)
{
    float x = v * inv;                 // |x| <= 127
    q0 = __float2int_rn(x);
    q1 = __float2int_rn((x - (float)q0) * 127.f);
}

// contiguous quantize, 8 elems/thread
struct QJob { const float* src; int8_t *q0, *q1; int n8, slot, blkStart; };
struct QParams { QJob j[8]; int n; };

__global__ void quantb_kernel(QParams P)
{
    int b = blockIdx.x;
    int ji = 0;
#pragma unroll 1
    while (ji + 1 < P.n && b >= P.j[ji + 1].blkStart) ji++;
    const QJob jb = P.j[ji];
    int i = (b - jb.blkStart) * 256 + threadIdx.x;
    if (i >= jb.n8) return;
    const float inv = 127.f / fmaxf(g_sc[jb.slot], 1e-30f);
    float4 v0 = ((const float4*)jb.src)[i * 2];
    float4 v1 = ((const float4*)jb.src)[i * 2 + 1];
    float vs[8] = { v0.x, v0.y, v0.z, v0.w, v1.x, v1.y, v1.z, v1.w };
    uint32_t p0[2] = { 0, 0 }, p1[2] = { 0, 0 };
#pragma unroll
    for (int k = 0; k < 8; k++) {
        int q0, q1;
        quant2(vs[k], inv, q0, q1);
        p0[k >> 2] |= ((uint32_t)q0 & 0xFFu) << ((k & 3) * 8);
        p1[k >> 2] |= ((uint32_t)q1 & 0xFFu) << ((k & 3) * 8);
    }
    ((uint2*)jb.q0)[i] = make_uint2(p0[0], p0[1]);
    ((uint2*)jb.q1)[i] = make_uint2(p1[0], p1[1]);
}

// transpose-quantize: dst[n*rows + k] = quant(src[k*lds + n])
struct TJob { const float* src; int8_t *q0, *q1; int lds, rows, cols, slot, tileStart, tilesR; };
struct TParams { TJob j[6]; int n; };

__global__ void tquantb_kernel(TParams P)
{
    __shared__ float tile[32][33];
    int b = blockIdx.x;
    int ji = 0;
#pragma unroll 1
    while (ji + 1 < P.n && b >= P.j[ji + 1].tileStart) ji++;
    const TJob jb = P.j[ji];
    int rel = b - jb.tileStart;
    int k0 = (rel % jb.tilesR) * 32, n0 = (rel / jb.tilesR) * 32;
    int tx = threadIdx.x, ty = threadIdx.y;
    const float inv = 127.f / fmaxf(g_sc[jb.slot], 1e-30f);
    for (int i = ty; i < 32; i += 8) {
        int k = k0 + i, n = n0 + tx;
        tile[i][tx] = (k < jb.rows && n < jb.cols) ? jb.src[(size_t)k * jb.lds + n] : 0.f;
    }
    __syncthreads();
    for (int i = ty; i < 32; i += 8) {
        int n = n0 + i, k = k0 + tx;
        if (n < jb.cols && k < jb.rows) {
            int q0, q1;
            quant2(tile[tx][i], inv, q0, q1);
            jb.q0[(size_t)n * jb.rows + k] = (int8_t)q0;
            jb.q1[(size_t)n * jb.rows + k] = (int8_t)q1;
        }
    }
}

// ================= misc small kernels =================
struct CJob { const float* src; float* dst; int rows, ldd, rowStart; };
struct CParams { CJob j[6]; int n; };

__global__ void copyb_kernel(CParams P)
{
    int b = blockIdx.x;
    int ji = 0;
#pragma unroll 1
    while (ji + 1 < P.n && b >= P.j[ji + 1].rowStart) ji++;
    const CJob jb = P.j[ji];
    int r = b - jb.rowStart;
    jb.dst[(size_t)r * jb.ldd + threadIdx.x] = jb.src[(size_t)r * CC + threadIdx.x];
}

struct LJob { const float *x, *W, *b; float* y; int rows, rowStart; };
struct LParams { LJob j[3]; int n; };

__global__ void linb_kernel(LParams P)
{
    __shared__ float xs[CC];
    int b = blockIdx.x;
    int ji = 0;
#pragma unroll 1
    while (ji + 1 < P.n && b >= P.j[ji + 1].rowStart) ji++;
    const LJob jb = P.j[ji];
    int n = b - jb.rowStart, o = threadIdx.x;
    xs[o] = jb.x[(size_t)n * CC + o];
    __syncthreads();
    float acc = jb.b[o];
    const float* wr = &jb.W[(size_t)o * CC];
#pragma unroll 8
    for (int i = 0; i < CC; i++) acc += xs[i] * wr[i];
    jb.y[(size_t)n * CC + o] = acc;
}

// build + quantize einsum weights: Wt[o, s*128+i] = w[i,o,map[s]]
__global__ void build_wtq_kernel(const float* __restrict__ w,
                                 int8_t* __restrict__ q0d, int8_t* __restrict__ q1d,
                                 int which, int korig, int S, int slot)
{
    int bi = blockIdx.x;
    int s = bi >> 7, o = bi & 127;
    int i = threadIdx.x;
    int k = c_maps[which][s];
    float v = (k >= 0) ? w[((size_t)i * CC + o) * korig + k] : 0.f;
    const float inv = 127.f / fmaxf(g_sc[slot], 1e-30f);
    int q0, q1;
    quant2(v, inv, q0, q1);
    size_t idx = (size_t)o * (S * CC) + s * CC + i;
    q0d[idx] = (int8_t)q0;
    q1d[idx] = (int8_t)q1;
}

__global__ void head_kernel(const float* __restrict__ h0, const float* __restrict__ ow,
                            const float* __restrict__ ob, float* __restrict__ out, int total)
{
    int idx = blockIdx.x * blockDim.x + threadIdx.x;
    if (idx >= total) return;
    int n = idx >> 1, c = idx & 1;
    float acc = ob[c];
    const float* hr = &h0[(size_t)n * CC];
    const float* wr = &ow[(size_t)c * CC];
#pragma unroll 8
    for (int i = 0; i < CC; i++) acc += hr[i] * wr[i];
    out[idx] = 1.f / (1.f + expf(-acc));
}

// ================= host-side batch builders =================
struct MMBatch { MMParams p; int tiles; };
static void mmAdd(MMBatch& b, const int8_t* A0, const int8_t* A1, int lda, int slotA,
                  const int8_t* B0, const int8_t* B1, int ldb, int slotB,
                  float* C, int ldc, int M, int N, int K)
{
    MMJob& j = b.p.j[b.p.n++];
    j.A0 = A0; j.A1 = A1; j.B0 = B0; j.B1 = B1; j.C = C;
    j.M = M; j.K = K; j.lda = lda; j.ldb = ldb; j.ldc = ldc;
    j.slotA = slotA; j.slotB = slotB;
    j.tileStart = b.tiles; j.tilesX = (M + 127) / 128;
    b.tiles += j.tilesX * (N / 128);
}
static void mmRun(MMBatch& b)
{
    if (b.p.n) mmq_kernel<<<b.tiles, 256, MM_SMEM>>>(b.p);
    b.p.n = 0; b.tiles = 0;
}

struct ABatch { AParams p; int blks; };
static void aAdd(ABatch& b, const float* src, int rows, int cols, int ld, int slot)
{
    AJob& j = b.p.j[b.p.n++];
    j.src = src; j.rows = rows; j.cols = cols; j.ld = ld; j.slot = slot; j.blkStart = b.blks;
    b.blks += (rows * cols + 4095) / 4096;
}
static void aRun(ABatch& b)
{
    if (b.p.n) amaxb_kernel<<<b.blks, 256>>>(b.p);
    b.p.n = 0; b.blks = 0;
}

struct QBatch { QParams p; int blks; };
static void qAdd(QBatch& b, const float* src, int8_t* q0, int8_t* q1, size_t cnt, int slot)
{
    QJob& j = b.p.j[b.p.n++];
    j.src = src; j.q0 = q0; j.q1 = q1; j.n8 = (int)(cnt / 8); j.slot = slot; j.blkStart = b.blks;
    b.blks += (j.n8 + 255) / 256;
}
static void qRun(QBatch& b)
{
    if (b.p.n) quantb_kernel<<<b.blks, 256>>>(b.p);
    b.p.n = 0; b.blks = 0;
}

struct TBatch { TParams p; int tiles; };
static void tAdd(TBatch& b, const float* src, int lds, int rows, int cols,
                 int8_t* q0, int8_t* q1, int slot)
{
    TJob& j = b.p.j[b.p.n++];
    j.src = src; j.q0 = q0; j.q1 = q1; j.lds = lds; j.rows = rows; j.cols = cols; j.slot = slot;
    j.tileStart = b.tiles; j.tilesR = (rows + 31) / 32;
    b.tiles += j.tilesR * ((cols + 31) / 32);
}
static void tRun(TBatch& b)
{
    if (b.p.n) tquantb_kernel<<<b.tiles, dim3(32, 8)>>>(b.p);
    b.p.n = 0; b.tiles = 0;
}

#define SYM(v, g) { void* p_; cudaGetSymbolAddress(&p_, g); v = (decltype(v))p_; }

extern "C" void kernel_launch(void* const* d_in, const int* in_sizes, int n_in,
                              void* d_out, int out_size)
{
    (void)in_sizes; (void)n_in; (void)out_size;
    const float* x0    = (const float*)d_in[0];
    const float* x1    = (const float*)d_in[1];
    const float* x2    = (const float*)d_in[2];
    const float* L0    = (const float*)d_in[3];
    const float* L1d   = (const float*)d_in[4];
    const float* L1u   = (const float*)d_in[5];
    const float* L2d   = (const float*)d_in[6];
    const float* L2u   = (const float*)d_in[7];
    const float* B1    = (const float*)d_in[8];
    const float* B2    = (const float*)d_in[9];
    const float* in_w0 = (const float*)d_in[10];
    const float* in_b0 = (const float*)d_in[11];
    const float* in_w1 = (const float*)d_in[12];
    const float* in_b1 = (const float*)d_in[13];
    const float* in_w2 = (const float*)d_in[14];
    const float* in_b2 = (const float*)d_in[15];
    const float* lw[2][3] = {
        {(const float*)d_in[16], (const float*)d_in[17], (const float*)d_in[18]},
        {(const float*)d_in[19], (const float*)d_in[20], (const float*)d_in[21]},
    };
    const float* out_w = (const float*)d_in[22];
    const float* out_b = (const float*)d_in[23];
    float* out = (float*)d_out;

    cudaFuncSetAttribute(mmq_kernel, cudaFuncAttributeMaxDynamicSharedMemorySize, MM_SMEM);

    float *h0, *h1, *h2, *X0f, *X1f, *X2f;
    SYM(h0, g_h0); SYM(h1, g_h1); SYM(h2, g_h2);
    SYM(X0f, g_X0f); SYM(X1f, g_X1f); SYM(X2f, g_X2f);
    int8_t *L0a, *L0b, *L1da, *L1db, *L1ua, *L1ub, *L2da, *L2db, *L2ua, *L2ub;
    int8_t *B1a, *B1b, *B1ta, *B1tb, *B2a, *B2b, *B2ta, *B2tb;
    SYM(L0a, g_L0a); SYM(L0b, g_L0b);
    SYM(L1da, g_L1da); SYM(L1db, g_L1db); SYM(L1ua, g_L1ua); SYM(L1ub, g_L1ub);
    SYM(L2da, g_L2da); SYM(L2db, g_L2db); SYM(L2ua, g_L2ua); SYM(L2ub, g_L2ub);
    SYM(B1a, g_B1a); SYM(B1b, g_B1b); SYM(B1ta, g_B1ta); SYM(B1tb, g_B1tb);
    SYM(B2a, g_B2a); SYM(B2b, g_B2b); SYM(B2ta, g_B2ta); SYM(B2tb, g_B2tb);
    int8_t *X0qa, *X0qb, *X1qa, *X1qb, *X2qa, *X2qb;
    SYM(X0qa, g_X0qa); SYM(X0qb, g_X0qb); SYM(X1qa, g_X1qa); SYM(X1qb, g_X1qb);
    SYM(X2qa, g_X2qa); SYM(X2qb, g_X2qb);
    int8_t *bt0a, *bt0b, *bt1aa, *bt1ab, *bt1ba, *bt1bb, *bt2a, *bt2b, *bt2ba, *bt2bb;
    SYM(bt0a, g_bt0a); SYM(bt0b, g_bt0b);
    SYM(bt1aa, g_bt1aa); SYM(bt1ab, g_bt1ab);
    SYM(bt1ba, g_bt1ba); SYM(bt1bb, g_bt1bb);
    SYM(bt2a, g_bt2a); SYM(bt2b, g_bt2b);
    SYM(bt2ba, g_bt2ba); SYM(bt2bb, g_bt2bb);
    int8_t *bh0a, *bh0b, *bh1a, *bh1b, *bh2a, *bh2b;
    SYM(bh0a, g_bh0a); SYM(bh0b, g_bh0b);
    SYM(bh1a, g_bh1a); SYM(bh1b, g_bh1b);
    SYM(bh2a, g_bh2a); SYM(bh2b, g_bh2b);
    int8_t *W0qa, *W0qb, *W1qa, *W1qb, *W2qa, *W2qb;
    SYM(W0qa, g_W0qa); SYM(W0qb, g_W0qb); SYM(W1qa, g_W1qa); SYM(W1qb, g_W1qb);
    SYM(W2qa, g_W2qa); SYM(W2qb, g_W2qb);

    const int LD0 = 6 * CC, LD1 = 12 * CC, LD2 = 8 * CC;

    MMBatch mb = {}; ABatch ab = {}; QBatch qb = {}; TBatch tb = {};

    // ---- clear all scale slots; amax of operators + all layer weights ----
    clear_sc_kernel<<<1, 32>>>(0, 32);
    aAdd(ab, L0,  1, Nn0 * Nn0, Nn0 * Nn0, 0);
    aAdd(ab, L1d, 1, Nn1 * Nn1, Nn1 * Nn1, 1);
    aAdd(ab, L1u, 1, Nn1 * Nn1, Nn1 * Nn1, 2);
    aAdd(ab, L2d, 1, Nn2 * Nn2, Nn2 * Nn2, 3);
    aAdd(ab, L2u, 1, Nn2 * Nn2, Nn2 * Nn2, 4);
    aAdd(ab, B1,  1, Nn0 * Nn1, Nn0 * Nn1, 5);
    aAdd(ab, B2,  1, Nn1 * Nn2, Nn1 * Nn2, 6);
    aAdd(ab, lw[0][0], 1, CC * CC * 6,  CC * CC * 6,  22);
    aAdd(ab, lw[0][1], 1, CC * CC * 11, CC * CC * 11, 23);
    aAdd(ab, lw[0][2], 1, CC * CC * 8,  CC * CC * 8,  24);
    aAdd(ab, lw[1][0], 1, CC * CC * 6,  CC * CC * 6,  25);
    aAdd(ab, lw[1][1], 1, CC * CC * 11, CC * CC * 11, 26);
    aAdd(ab, lw[1][2], 1, CC * CC * 8,  CC * CC * 8,  27);
    aRun(ab);

    // ---- quantize operators ----
    qAdd(qb, L0,  L0a,  L0b,  (size_t)Nn0 * Nn0, 0);
    qAdd(qb, L1d, L1da, L1db, (size_t)Nn1 * Nn1, 1);
    qAdd(qb, L1u, L1ua, L1ub, (size_t)Nn1 * Nn1, 2);
    qAdd(qb, L2d, L2da, L2db, (size_t)Nn2 * Nn2, 3);
    qAdd(qb, L2u, L2ua, L2ub, (size_t)Nn2 * Nn2, 4);
    qAdd(qb, B1,  B1a,  B1b,  (size_t)Nn0 * Nn1, 5);
    qAdd(qb, B2,  B2a,  B2b,  (size_t)Nn1 * Nn2, 6);
    qRun(qb);
    tAdd(tb, B1, Nn1, Nn0, Nn1, B1ta, B1tb, 5);
    tAdd(tb, B2, Nn2, Nn1, Nn2, B2ta, B2tb, 6);
    tRun(tb);

    // ---- input linears ----
    {
        LParams lp = {};
        lp.j[0] = { x0, in_w0, in_b0, h0, Nn0, 0 };
        lp.j[1] = { x1, in_w1, in_b1, h1, Nn1, Nn0 };
        lp.j[2] = { x2, in_w2, in_b2, h2, Nn2, Nn0 + Nn1 };
        lp.n = 3;
        linb_kernel<<<Nn0 + Nn1 + Nn2, CC>>>(lp);
    }

    for (int layer = 0; layer < 2; layer++) {
        const int ws = 22 + 3 * layer;
        // reset per-layer slots, amax of h
        clear_sc_kernel<<<1, 32>>>(7, 22);
        aAdd(ab, h0, 1, Nn0 * CC, Nn0 * CC, 7);
        aAdd(ab, h1, 1, Nn1 * CC, Nn1 * CC, 8);
        aAdd(ab, h2, 1, Nn2 * CC, Nn2 * CC, 9);
        aRun(ab);

        // weights (quantized transposed)
        build_wtq_kernel<<<6 * CC,  CC>>>(lw[layer][0], W0qa, W0qb, 0, 6,  6,  ws + 0);
        build_wtq_kernel<<<12 * CC, CC>>>(lw[layer][1], W1qa, W1qb, 1, 11, 12, ws + 1);
        build_wtq_kernel<<<8 * CC,  CC>>>(lw[layer][2], W2qa, W2qb, 2, 8,  8,  ws + 2);

        // h transposes (quantized)
        tAdd(tb, h0, CC, Nn0, CC, bh0a, bh0b, 7);
        tAdd(tb, h1, CC, Nn1, CC, bh1a, bh1b, 8);
        tAdd(tb, h2, CC, Nn2, CC, bh2a, bh2b, 9);
        tRun(tb);

        // base copies (fp32)
        {
            CParams cp = {};
            cp.j[0] = { h0, X0f + 0,   Nn0, LD0, 0 };
            cp.j[1] = { h1, X1f + 0,   Nn1, LD1, Nn0 };
            cp.j[2] = { h1, X1f + 256, Nn1, LD1, Nn0 + Nn1 };
            cp.j[3] = { h2, X2f + 0,   Nn2, LD2, Nn0 + 2 * Nn1 };
            cp.n = 4;
            copyb_kernel<<<Nn0 + 2 * Nn1 + Nn2, CC>>>(cp);
        }

        // projections
        mmAdd(mb, B1a,  B1b,  Nn1, 5, bh1a, bh1b, Nn1, 8, X0f + 128, LD0, Nn0, 128, Nn1);
        mmAdd(mb, B1ta, B1tb, Nn0, 5, bh0a, bh0b, Nn0, 7, X1f + 128, LD1, Nn1, 128, Nn0);
        mmAdd(mb, B2a,  B2b,  Nn2, 6, bh2a, bh2b, Nn2, 9, X1f + 384, LD1, Nn1, 128, Nn2);
        mmAdd(mb, B2ta, B2tb, Nn1, 6, bh1a, bh1b, Nn1, 8, X2f + 128, LD2, Nn2, 128, Nn1);
        mmRun(mb);

        // first-hop slice amax + transpose-quant
        aAdd(ab, X0f + 0,   Nn0, 256, LD0, 10);
        aAdd(ab, X1f + 0,   Nn1, 256, LD1, 11);
        aAdd(ab, X1f + 256, Nn1, 256, LD1, 12);
        aAdd(ab, X2f + 0,   Nn2, 256, LD2, 13);
        aRun(ab);
        tAdd(tb, X0f + 0,   LD0, Nn0, 256, bt0a,  bt0b,  10);
        tAdd(tb, X1f + 0,   LD1, Nn1, 256, bt1aa, bt1ab, 11);
        tAdd(tb, X1f + 256, LD1, Nn1, 256, bt1ba, bt1bb, 12);
        tAdd(tb, X2f + 0,   LD2, Nn2, 256, bt2a,  bt2b,  13);
        tRun(tb);

        // first hops
        mmAdd(mb, L0a,  L0b,  Nn0, 0, bt0a,  bt0b,  Nn0, 10, X0f + 256, LD0, Nn0, 256, Nn0);
        mmAdd(mb, L1da, L1db, Nn1, 1, bt1aa, bt1ab, Nn1, 11, X1f + 512, LD1, Nn1, 256, Nn1);
        mmAdd(mb, L1ua, L1ub, Nn1, 2, bt1ba, bt1bb, Nn1, 12, X1f + 768, LD1, Nn1, 256, Nn1);
        mmAdd(mb, L2da, L2db, Nn2, 3, bt2a,  bt2b,  Nn2, 13, X2f + 256, LD2, Nn2, 256, Nn2);
        mmAdd(mb, L2ua, L2ub, Nn2, 4, bh2a,  bh2b,  Nn2, 9,  X2f + 768, LD2, Nn2, 128, Nn2);
        mmRun(mb);

        // second-hop slice amax + transpose-quant
        aAdd(ab, X0f + 256, Nn0, 256, LD0, 14);
        aAdd(ab, X1f + 512, Nn1, 256, LD1, 15);
        aAdd(ab, X1f + 768, Nn1, 256, LD1, 16);
        aAdd(ab, X2f + 256, Nn2, 256, LD2, 17);
        aAdd(ab, X2f + 768, Nn2, 128, LD2, 18);
        aRun(ab);
        tAdd(tb, X0f + 256, LD0, Nn0, 256, bt0a,  bt0b,  14);
        tAdd(tb, X1f + 512, LD1, Nn1, 256, bt1aa, bt1ab, 15);
        tAdd(tb, X1f + 768, LD1, Nn1, 256, bt1ba, bt1bb, 16);
        tAdd(tb, X2f + 256, LD2, Nn2, 256, bt2a,  bt2b,  17);
        tAdd(tb, X2f + 768, LD2, Nn2, 128, bt2ba, bt2bb, 18);
        tRun(tb);

        // second hops
        mmAdd(mb, L0a,  L0b,  Nn0, 0, bt0a,  bt0b,  Nn0, 14, X0f + 512,  LD0, Nn0, 256, Nn0);
        mmAdd(mb, L1da, L1db, Nn1, 1, bt1aa, bt1ab, Nn1, 15, X1f + 1024, LD1, Nn1, 256, Nn1);
        mmAdd(mb, L1ua, L1ub, Nn1, 2, bt1ba, bt1bb, Nn1, 16, X1f + 1280, LD1, Nn1, 256, Nn1);
        mmAdd(mb, L2da, L2db, Nn2, 3, bt2a,  bt2b,  Nn2, 17, X2f + 512,  LD2, Nn2, 256, Nn2);
        mmAdd(mb, L2ua, L2ub, Nn2, 4, bt2ba, bt2bb, Nn2, 18, X2f + 896,  LD2, Nn2, 128, Nn2);
        mmRun(mb);

        // einsum: amax + quantize X (contiguous), then GEMM vs quantized W
        aAdd(ab, X0f, 1, Nn0 * LD0, Nn0 * LD0, 19);
        aAdd(ab, X1f, 1, Nn1 * LD1, Nn1 * LD1, 20);
        aAdd(ab, X2f, 1, Nn2 * LD2, Nn2 * LD2, 21);
        aRun(ab);
        qAdd(qb, X0f, X0qa, X0qb, (size_t)Nn0 * LD0, 19);
        qAdd(qb, X1f, X1qa, X1qb, (size_t)Nn1 * LD1, 20);
        qAdd(qb, X2f, X2qa, X2qb, (size_t)Nn2 * LD2, 21);
        qRun(qb);
        mmAdd(mb, X0qa, X0qb, LD0, 19, W0qa, W0qb, LD0, ws + 0, h0, CC, Nn0, 128, LD0);
        mmAdd(mb, X1qa, X1qb, LD1, 20, W1qa, W1qb, LD1, ws + 1, h1, CC, Nn1, 128, LD1);
        mmAdd(mb, X2qa, X2qb, LD2, 21, W2qa, W2qb, LD2, ws + 2, h2, CC, Nn2, 128, LD2);
        mmRun(mb);
    }

    head_kernel<<<(Nn0 * 2 + 255) / 256, 256>>>(h0, out_w, out_b, out, Nn0 * 2);
}

// round 9
// speedup vs baseline: 2.3012x; 2.3012x over previous
#include <cuda_runtime.h>
#include <cuda_bf16.h>
#include <math.h>
#include <stdint.h>

#define Nn0 2000
#define Nn1 6000
#define Nn2 4000
#define CC  128

// ================= static scratch (no allocation) =================
__device__ float g_h0[Nn0 * CC];
__device__ float g_h1[Nn1 * CC];
__device__ float g_h2[Nn2 * CC];

// operators bf16 hi/lo
__device__ __nv_bfloat16 g_L0h[Nn0 * Nn0],  g_L0l[Nn0 * Nn0];
__device__ __nv_bfloat16 g_L1dh[Nn1 * Nn1], g_L1dl[Nn1 * Nn1];
__device__ __nv_bfloat16 g_L1uh[Nn1 * Nn1], g_L1ul[Nn1 * Nn1];
__device__ __nv_bfloat16 g_L2dh[Nn2 * Nn2], g_L2dl[Nn2 * Nn2];
__device__ __nv_bfloat16 g_L2uh[Nn2 * Nn2], g_L2ul[Nn2 * Nn2];
__device__ __nv_bfloat16 g_B1h[Nn0 * Nn1],  g_B1l[Nn0 * Nn1];
__device__ __nv_bfloat16 g_B1th[Nn1 * Nn0], g_B1tl[Nn1 * Nn0];
__device__ __nv_bfloat16 g_B2h[Nn1 * Nn2],  g_B2l[Nn1 * Nn2];
__device__ __nv_bfloat16 g_B2th[Nn2 * Nn1], g_B2tl[Nn2 * Nn1];

// einsum A operands, row-major bf16 hi/lo (filled by epilogues + hconv)
__device__ __nv_bfloat16 g_X0qh[Nn0 * 6 * CC],  g_X0ql[Nn0 * 6 * CC];
__device__ __nv_bfloat16 g_X1qh[Nn1 * 12 * CC], g_X1ql[Nn1 * 12 * CC];
__device__ __nv_bfloat16 g_X2qh[Nn2 * 8 * CC],  g_X2ql[Nn2 * 8 * CC];

// transposed B-operand buffers: btA = inputs to hop1 ([h | proj]), btB = inputs to hop2
__device__ __nv_bfloat16 g_bt0h[256 * Nn0],  g_bt0l[256 * Nn0];
__device__ __nv_bfloat16 g_bt1ah[256 * Nn1], g_bt1al[256 * Nn1];
__device__ __nv_bfloat16 g_bt1bh[256 * Nn1], g_bt1bl[256 * Nn1];
__device__ __nv_bfloat16 g_bt2h[256 * Nn2],  g_bt2l[256 * Nn2];
__device__ __nv_bfloat16 g_bb0h[256 * Nn0],  g_bb0l[256 * Nn0];
__device__ __nv_bfloat16 g_bb1ah[256 * Nn1], g_bb1al[256 * Nn1];
__device__ __nv_bfloat16 g_bb1bh[256 * Nn1], g_bb1bl[256 * Nn1];
__device__ __nv_bfloat16 g_bb2h[256 * Nn2],  g_bb2l[256 * Nn2];
__device__ __nv_bfloat16 g_bb2uh[128 * Nn2], g_bb2ul[128 * Nn2];

// einsum weights, transposed [128, S*128] bf16 hi/lo
__device__ __nv_bfloat16 g_W0h[CC * 6 * CC],  g_W0l[CC * 6 * CC];
__device__ __nv_bfloat16 g_W1h[CC * 12 * CC], g_W1l[CC * 12 * CC];
__device__ __nv_bfloat16 g_W2h[CC * 8 * CC],  g_W2l[CC * 8 * CC];

__constant__ int c_maps[3][12] = {
    {0, 3, 1, 4, 2, 5, -1, -1, -1, -1, -1, -1},
    {0, 5, -1, 8, 1, 6, 3, 9, 2, 7, 4, 10},
    {0, 5, 1, 6, 2, 7, 3, 4, -1, -1, -1, -1},
};

// ================= PTX helpers (plain sm_80+ PTX) =================
__device__ __forceinline__ uint32_t smem_u32(const void* p) {
    uint32_t a;
    asm("{ .reg .u64 t; cvta.to.shared.u64 t, %1; cvt.u32.u64 %0, t; }" : "=r"(a) : "l"(p));
    return a;
}
__device__ __forceinline__ void ldsm_x4(uint32_t* r, uint32_t a) {
    asm volatile("ldmatrix.sync.aligned.m8n8.x4.shared.b16 {%0,%1,%2,%3}, [%4];"
                 : "=r"(r[0]), "=r"(r[1]), "=r"(r[2]), "=r"(r[3]) : "r"(a));
}
__device__ __forceinline__ void mma_bf16(float* c, const uint32_t* a, const uint32_t* b) {
    asm volatile(
        "mma.sync.aligned.m16n8k16.row.col.f32.bf16.bf16.f32 "
        "{%0,%1,%2,%3}, {%4,%5,%6,%7}, {%8,%9}, {%0,%1,%2,%3};"
        : "+f"(c[0]), "+f"(c[1]), "+f"(c[2]), "+f"(c[3])
        : "r"(a[0]), "r"(a[1]), "r"(a[2]), "r"(a[3]), "r"(b[0]), "r"(b[1]));
}
__device__ __forceinline__ void cp_async16(uint32_t dst, const void* src, int sz) {
    asm volatile("cp.async.cg.shared.global [%0], [%1], 16, %2;"
                 :: "r"(dst), "l"(src), "r"(sz));
}
// swizzled byte addr within a [128 rows x 32 bf16] tile (64B rows, 16B chunks)
__device__ __forceinline__ uint32_t sw_addr(uint32_t tile_base, int r, int chunk) {
    return tile_base + (uint32_t)(r * 64) + (uint32_t)((chunk ^ ((r >> 1) & 3)) << 4);
}

// ================= batched bf16x3 HMMA GEMM with fused-convert epilogue =====
#define MM_SMEM (3 * 4 * 8192)
#define MAXJOB 6

struct MMJob {
    const __nv_bfloat16 *Ah, *Al, *Bh, *Bl;
    float* Cf;                       // optional fp32 output
    __nv_bfloat16 *Rh, *Rl;          // optional row-major bf16 hi/lo output
    __nv_bfloat16 *Th, *Tl;          // optional transposed bf16 hi/lo output
    int M, K, lda, ldb, ldc, ldR, ldT, tileStart, tilesX;
};
struct MMParams { MMJob j[MAXJOB]; int n; };

__global__ __launch_bounds__(256, 2)
void mmb_kernel(MMParams P)
{
    extern __shared__ __align__(128) char smem[];
    const uint32_t sbase = smem_u32(smem);
    const int tid = threadIdx.x, lane = tid & 31, wid = tid >> 5;
    const int wm = wid & 1, wn = wid >> 1;

    int bt = blockIdx.x;
    int ji = 0;
#pragma unroll 1
    while (ji + 1 < P.n && bt >= P.j[ji + 1].tileStart) ji++;
    const MMJob jb = P.j[ji];
    const int rel = bt - jb.tileStart;
    const int m0 = (rel % jb.tilesX) * 128;
    const int n0 = (rel / jb.tilesX) * 128;
    const int M = jb.M, K = jb.K, lda = jb.lda, ldb = jb.ldb;
    const int mrows = (M - m0 < 128) ? (M - m0) : 128;
    const __nv_bfloat16* Ah = jb.Ah + (size_t)m0 * lda;
    const __nv_bfloat16* Al = jb.Al + (size_t)m0 * lda;
    const __nv_bfloat16* Bh = jb.Bh + (size_t)n0 * ldb;
    const __nv_bfloat16* Bl = jb.Bl + (size_t)n0 * ldb;
    const int nk = (K + 31) >> 5;

    float acc[4][4][4];
#pragma unroll
    for (int i = 0; i < 4; i++)
#pragma unroll
        for (int j = 0; j < 4; j++)
#pragma unroll
            for (int v = 0; v < 4; v++) acc[i][j][v] = 0.f;

    auto load_stage = [&](int t) {
        const uint32_t sb = sbase + (uint32_t)(t % 3) * 32768;
        const int k0 = t << 5;
#pragma unroll
        for (int i = 0; i < 8; i++) {
            int idx = tid + i * 256;
            int tile = idx >> 9;
            int rem  = idx & 511;
            int r = rem >> 2, c = rem & 3;
            const __nv_bfloat16* gp;
            int ok;
            if (tile < 2) {
                gp = (tile == 0 ? Ah : Al) + (size_t)r * lda + k0 + c * 8;
                ok = (r < mrows) && (k0 + c * 8 < K);
            } else {
                gp = (tile == 2 ? Bh : Bl) + (size_t)r * ldb + k0 + c * 8;
                ok = (k0 + c * 8 < K);
            }
            cp_async16(sb + (uint32_t)tile * 8192 + sw_addr(0, r, c), gp, ok ? 16 : 0);
        }
    };

#pragma unroll
    for (int s = 0; s < 2; s++) {
        if (s < nk) load_stage(s);
        asm volatile("cp.async.commit_group;" ::: "memory");
    }

    const int frag_r = lane & 15;
    const int frag_c = lane >> 4;

    for (int t = 0; t < nk; t++) {
        asm volatile("cp.async.wait_group 1;" ::: "memory");
        __syncthreads();
        const uint32_t sb = sbase + (uint32_t)(t % 3) * 32768;
        const uint32_t tAh = sb, tAl = sb + 8192, tBh = sb + 16384, tBl = sb + 24576;

#pragma unroll
        for (int ks = 0; ks < 2; ks++) {
            const int ch = ks * 2 + frag_c;
            uint32_t bh[4][2], bl[4][2];
#pragma unroll
            for (int j = 0; j < 2; j++) {
                int r = wn * 32 + j * 16 + frag_r;
                uint32_t rr[4];
                ldsm_x4(rr, sw_addr(tBh, r, ch));
                bh[2 * j][0] = rr[0]; bh[2 * j][1] = rr[2];
                bh[2 * j + 1][0] = rr[1]; bh[2 * j + 1][1] = rr[3];
                ldsm_x4(rr, sw_addr(tBl, r, ch));
                bl[2 * j][0] = rr[0]; bl[2 * j][1] = rr[2];
                bl[2 * j + 1][0] = rr[1]; bl[2 * j + 1][1] = rr[3];
            }
#pragma unroll
            for (int mt = 0; mt < 4; mt++) {
                int r = wm * 64 + mt * 16 + frag_r;
                uint32_t ah[4], al[4];
                ldsm_x4(ah, sw_addr(tAh, r, ch));
                ldsm_x4(al, sw_addr(tAl, r, ch));
#pragma unroll
                for (int nt = 0; nt < 4; nt++) {
                    mma_bf16(acc[mt][nt], ah, bh[nt]);
                    mma_bf16(acc[mt][nt], ah, bl[nt]);
                    mma_bf16(acc[mt][nt], al, bh[nt]);
                }
            }
        }
        __syncthreads();
        if (t + 2 < nk) load_stage(t + 2);
        asm volatile("cp.async.commit_group;" ::: "memory");
    }

    // ---- fused epilogue: fp32 / row-bf16 hi,lo / transposed-bf16 hi,lo ----
    const int er = lane >> 2, ec = (lane & 3) * 2;
    const bool doBF = (jb.Rh != nullptr) || (jb.Th != nullptr);
#pragma unroll
    for (int mt = 0; mt < 4; mt++) {
        int r0 = m0 + wm * 64 + mt * 16 + er;
        int r1 = r0 + 8;
#pragma unroll
        for (int nt = 0; nt < 4; nt++) {
            int col = n0 + wn * 32 + nt * 8 + ec;
            float f0 = acc[mt][nt][0], f1 = acc[mt][nt][1];
            float f2 = acc[mt][nt][2], f3 = acc[mt][nt][3];
            if (jb.Cf) {
                if (r0 < M) *(float2*)&jb.Cf[(size_t)r0 * jb.ldc + col] = make_float2(f0, f1);
                if (r1 < M) *(float2*)&jb.Cf[(size_t)r1 * jb.ldc + col] = make_float2(f2, f3);
            }
            if (doBF) {
                __nv_bfloat16 h0 = __float2bfloat16(f0), h1 = __float2bfloat16(f1);
                __nv_bfloat16 h2 = __float2bfloat16(f2), h3 = __float2bfloat16(f3);
                __nv_bfloat16 l0 = __float2bfloat16(f0 - __bfloat162float(h0));
                __nv_bfloat16 l1 = __float2bfloat16(f1 - __bfloat162float(h1));
                __nv_bfloat16 l2 = __float2bfloat16(f2 - __bfloat162float(h2));
                __nv_bfloat16 l3 = __float2bfloat16(f3 - __bfloat162float(h3));
                if (jb.Rh) {
                    if (r0 < M) {
                        *(__nv_bfloat162*)&jb.Rh[(size_t)r0 * jb.ldR + col] = __halves2bfloat162(h0, h1);
                        *(__nv_bfloat162*)&jb.Rl[(size_t)r0 * jb.ldR + col] = __halves2bfloat162(l0, l1);
                    }
                    if (r1 < M) {
                        *(__nv_bfloat162*)&jb.Rh[(size_t)r1 * jb.ldR + col] = __halves2bfloat162(h2, h3);
                        *(__nv_bfloat162*)&jb.Rl[(size_t)r1 * jb.ldR + col] = __halves2bfloat162(l2, l3);
                    }
                }
                if (jb.Th) {
                    size_t cA = (size_t)col * jb.ldT, cB = (size_t)(col + 1) * jb.ldT;
                    if (r0 < M) {
                        jb.Th[cA + r0] = h0; jb.Th[cB + r0] = h1;
                        jb.Tl[cA + r0] = l0; jb.Tl[cB + r0] = l1;
                    }
                    if (r1 < M) {
                        jb.Th[cA + r1] = h2; jb.Th[cB + r1] = h3;
                        jb.Tl[cA + r1] = l2; jb.Tl[cB + r1] = l3;
                    }
                }
            }
        }
    }
}

// ================= operator split (8 floats/thread) =================
struct SJob { const float* src; __nv_bfloat16 *dh, *dl; int n8, blkStart; };
struct SParams { SJob j[8]; int n; };

__global__ void splitb_kernel(SParams P)
{
    int b = blockIdx.x;
    int ji = 0;
#pragma unroll 1
    while (ji + 1 < P.n && b >= P.j[ji + 1].blkStart) ji++;
    const SJob jb = P.j[ji];
    int i = (b - jb.blkStart) * 256 + threadIdx.x;
    if (i >= jb.n8) return;
    float4 v0 = ((const float4*)jb.src)[i * 2];
    float4 v1 = ((const float4*)jb.src)[i * 2 + 1];
    __nv_bfloat162 h[4], l[4];
    h[0] = __floats2bfloat162_rn(v0.x, v0.y);
    h[1] = __floats2bfloat162_rn(v0.z, v0.w);
    h[2] = __floats2bfloat162_rn(v1.x, v1.y);
    h[3] = __floats2bfloat162_rn(v1.z, v1.w);
    l[0] = __floats2bfloat162_rn(v0.x - __bfloat162float(h[0].x), v0.y - __bfloat162float(h[0].y));
    l[1] = __floats2bfloat162_rn(v0.z - __bfloat162float(h[1].x), v0.w - __bfloat162float(h[1].y));
    l[2] = __floats2bfloat162_rn(v1.x - __bfloat162float(h[2].x), v1.y - __bfloat162float(h[2].y));
    l[3] = __floats2bfloat162_rn(v1.z - __bfloat162float(h[3].x), v1.w - __bfloat162float(h[3].y));
    ((uint4*)jb.dh)[i] = *(uint4*)h;
    ((uint4*)jb.dl)[i] = *(uint4*)l;
}

// ================= transpose-split (for B1^T / B2^T only) =================
struct TJob { const float* src; __nv_bfloat16 *dh, *dl; int lds, rows, cols, tileStart, tilesR; };
struct TParams { TJob j[4]; int n; };

__global__ void tsplitb_kernel(TParams P)
{
    __shared__ float tile[32][33];
    int b = blockIdx.x;
    int ji = 0;
#pragma unroll 1
    while (ji + 1 < P.n && b >= P.j[ji + 1].tileStart) ji++;
    const TJob jb = P.j[ji];
    int rel = b - jb.tileStart;
    int k0 = (rel % jb.tilesR) * 32, n0 = (rel / jb.tilesR) * 32;
    int tx = threadIdx.x, ty = threadIdx.y;
    for (int i = ty; i < 32; i += 8) {
        int k = k0 + i, n = n0 + tx;
        tile[i][tx] = (k < jb.rows && n < jb.cols) ? jb.src[(size_t)k * jb.lds + n] : 0.f;
    }
    __syncthreads();
    for (int i = ty; i < 32; i += 8) {
        int n = n0 + i, k = k0 + tx;
        if (n < jb.cols && k < jb.rows) {
            float v = tile[tx][i];
            __nv_bfloat16 h = __float2bfloat16(v);
            jb.dh[(size_t)n * jb.rows + k] = h;
            jb.dl[(size_t)n * jb.rows + k] = __float2bfloat16(v - __bfloat162float(h));
        }
    }
}

// ================= hconv: h fp32 -> row bf16 (X slices) + transposed bf16 =====
struct HJob {
    const float* src;
    __nv_bfloat16 *Rh, *Rl, *R2h, *R2l;   // row-major dests (R2 nullable)
    __nv_bfloat16 *Th, *Tl, *T2h, *T2l;   // transposed dests (T2 nullable)
    int rows, ldR, tileStart, tilesR;
};
struct HParams { HJob j[3]; int n; };

__global__ void hconv_kernel(HParams P)
{
    __shared__ float tile[32][33];
    int b = blockIdx.x;
    int ji = 0;
#pragma unroll 1
    while (ji + 1 < P.n && b >= P.j[ji + 1].tileStart) ji++;
    const HJob jb = P.j[ji];
    int rel = b - jb.tileStart;
    int r0 = (rel % jb.tilesR) * 32, c0 = (rel / jb.tilesR) * 32;
    int tx = threadIdx.x, ty = threadIdx.y;
    for (int i = ty; i < 32; i += 8) {
        int r = r0 + i, c = c0 + tx;
        float v = (r < jb.rows) ? jb.src[(size_t)r * CC + c] : 0.f;
        tile[i][tx] = v;
        if (r < jb.rows) {
            __nv_bfloat16 h = __float2bfloat16(v);
            __nv_bfloat16 l = __float2bfloat16(v - __bfloat162float(h));
            jb.Rh[(size_t)r * jb.ldR + c] = h;
            jb.Rl[(size_t)r * jb.ldR + c] = l;
            if (jb.R2h) { jb.R2h[(size_t)r * jb.ldR + c] = h; jb.R2l[(size_t)r * jb.ldR + c] = l; }
        }
    }
    __syncthreads();
    for (int i = ty; i < 32; i += 8) {
        int c = c0 + i, r = r0 + tx;
        if (r < jb.rows) {
            float v = tile[tx][i];
            __nv_bfloat16 h = __float2bfloat16(v);
            __nv_bfloat16 l = __float2bfloat16(v - __bfloat162float(h));
            size_t idx = (size_t)c * jb.rows + r;
            jb.Th[idx] = h; jb.Tl[idx] = l;
            if (jb.T2h) { jb.T2h[idx] = h; jb.T2l[idx] = l; }
        }
    }
}

// ================= small kernels =================
struct LJob { const float *x, *W, *b; float* y; int rows, rowStart; };
struct LParams { LJob j[3]; int n; };

__global__ void linb_kernel(LParams P)
{
    __shared__ float xs[CC];
    int b = blockIdx.x;
    int ji = 0;
#pragma unroll 1
    while (ji + 1 < P.n && b >= P.j[ji + 1].rowStart) ji++;
    const LJob jb = P.j[ji];
    int n = b - jb.rowStart, o = threadIdx.x;
    xs[o] = jb.x[(size_t)n * CC + o];
    __syncthreads();
    float acc = jb.b[o];
    const float* wr = &jb.W[(size_t)o * CC];
#pragma unroll 8
    for (int i = 0; i < CC; i++) acc += xs[i] * wr[i];
    jb.y[(size_t)n * CC + o] = acc;
}

__global__ void build_wt_kernel(const float* __restrict__ w,
                                __nv_bfloat16* __restrict__ dh, __nv_bfloat16* __restrict__ dl,
                                int which, int korig, int S)
{
    int bi = blockIdx.x;
    int s = bi >> 7, o = bi & 127;
    int i = threadIdx.x;
    int k = c_maps[which][s];
    float v = (k >= 0) ? w[((size_t)i * CC + o) * korig + k] : 0.f;
    __nv_bfloat16 h = __float2bfloat16(v);
    size_t idx = (size_t)o * (S * CC) + s * CC + i;
    dh[idx] = h;
    dl[idx] = __float2bfloat16(v - __bfloat162float(h));
}

__global__ void head_kernel(const float* __restrict__ h0, const float* __restrict__ ow,
                            const float* __restrict__ ob, float* __restrict__ out, int total)
{
    int idx = blockIdx.x * blockDim.x + threadIdx.x;
    if (idx >= total) return;
    int n = idx >> 1, c = idx & 1;
    float acc = ob[c];
    const float* hr = &h0[(size_t)n * CC];
    const float* wr = &ow[(size_t)c * CC];
#pragma unroll 8
    for (int i = 0; i < CC; i++) acc += hr[i] * wr[i];
    out[idx] = 1.f / (1.f + expf(-acc));
}

// ================= host-side batch builders =================
struct MMBatch { MMParams p; int tiles; };
static void mmAdd(MMBatch& b,
                  const __nv_bfloat16* Ah, const __nv_bfloat16* Al, int lda,
                  const __nv_bfloat16* Bh, const __nv_bfloat16* Bl, int ldb,
                  int M, int N, int K,
                  float* Cf, int ldc,
                  __nv_bfloat16* Rh, __nv_bfloat16* Rl, int ldR,
                  __nv_bfloat16* Th, __nv_bfloat16* Tl, int ldT)
{
    MMJob& j = b.p.j[b.p.n++];
    j.Ah = Ah; j.Al = Al; j.Bh = Bh; j.Bl = Bl;
    j.Cf = Cf; j.Rh = Rh; j.Rl = Rl; j.Th = Th; j.Tl = Tl;
    j.M = M; j.K = K; j.lda = lda; j.ldb = ldb; j.ldc = ldc; j.ldR = ldR; j.ldT = ldT;
    j.tileStart = b.tiles; j.tilesX = (M + 127) / 128;
    b.tiles += j.tilesX * (N / 128);
}
static void mmRun(MMBatch& b)
{
    if (b.p.n) mmb_kernel<<<b.tiles, 256, MM_SMEM>>>(b.p);
    b.p.n = 0; b.tiles = 0;
}

#define SYM(v, g) { void* p_; cudaGetSymbolAddress(&p_, g); v = (decltype(v))p_; }

extern "C" void kernel_launch(void* const* d_in, const int* in_sizes, int n_in,
                              void* d_out, int out_size)
{
    (void)in_sizes; (void)n_in; (void)out_size;
    const float* x0    = (const float*)d_in[0];
    const float* x1    = (const float*)d_in[1];
    const float* x2    = (const float*)d_in[2];
    const float* L0    = (const float*)d_in[3];
    const float* L1d   = (const float*)d_in[4];
    const float* L1u   = (const float*)d_in[5];
    const float* L2d   = (const float*)d_in[6];
    const float* L2u   = (const float*)d_in[7];
    const float* B1    = (const float*)d_in[8];
    const float* B2    = (const float*)d_in[9];
    const float* in_w0 = (const float*)d_in[10];
    const float* in_b0 = (const float*)d_in[11];
    const float* in_w1 = (const float*)d_in[12];
    const float* in_b1 = (const float*)d_in[13];
    const float* in_w2 = (const float*)d_in[14];
    const float* in_b2 = (const float*)d_in[15];
    const float* lw[2][3] = {
        {(const float*)d_in[16], (const float*)d_in[17], (const float*)d_in[18]},
        {(const float*)d_in[19], (const float*)d_in[20], (const float*)d_in[21]},
    };
    const float* out_w = (const float*)d_in[22];
    const float* out_b = (const float*)d_in[23];
    float* out = (float*)d_out;

    cudaFuncSetAttribute(mmb_kernel, cudaFuncAttributeMaxDynamicSharedMemorySize, MM_SMEM);

    float *h0, *h1, *h2;
    SYM(h0, g_h0); SYM(h1, g_h1); SYM(h2, g_h2);
    __nv_bfloat16 *L0h, *L0l, *L1dh, *L1dl, *L1uh, *L1ul, *L2dh, *L2dl, *L2uh, *L2ul;
    __nv_bfloat16 *B1h, *B1l, *B1th, *B1tl, *B2h, *B2l, *B2th, *B2tl;
    SYM(L0h, g_L0h); SYM(L0l, g_L0l);
    SYM(L1dh, g_L1dh); SYM(L1dl, g_L1dl); SYM(L1uh, g_L1uh); SYM(L1ul, g_L1ul);
    SYM(L2dh, g_L2dh); SYM(L2dl, g_L2dl); SYM(L2uh, g_L2uh); SYM(L2ul, g_L2ul);
    SYM(B1h, g_B1h); SYM(B1l, g_B1l); SYM(B1th, g_B1th); SYM(B1tl, g_B1tl);
    SYM(B2h, g_B2h); SYM(B2l, g_B2l); SYM(B2th, g_B2th); SYM(B2tl, g_B2tl);
    __nv_bfloat16 *X0qh, *X0ql, *X1qh, *X1ql, *X2qh, *X2ql;
    SYM(X0qh, g_X0qh); SYM(X0ql, g_X0ql); SYM(X1qh, g_X1qh); SYM(X1ql, g_X1ql);
    SYM(X2qh, g_X2qh); SYM(X2ql, g_X2ql);
    __nv_bfloat16 *bt0h, *bt0l, *bt1ah, *bt1al, *bt1bh, *bt1bl, *bt2h, *bt2l;
    SYM(bt0h, g_bt0h); SYM(bt0l, g_bt0l);
    SYM(bt1ah, g_bt1ah); SYM(bt1al, g_bt1al);
    SYM(bt1bh, g_bt1bh); SYM(bt1bl, g_bt1bl);
    SYM(bt2h, g_bt2h); SYM(bt2l, g_bt2l);
    __nv_bfloat16 *bb0h, *bb0l, *bb1ah, *bb1al, *bb1bh, *bb1bl, *bb2h, *bb2l, *bb2uh, *bb2ul;
    SYM(bb0h, g_bb0h); SYM(bb0l, g_bb0l);
    SYM(bb1ah, g_bb1ah); SYM(bb1al, g_bb1al);
    SYM(bb1bh, g_bb1bh); SYM(bb1bl, g_bb1bl);
    SYM(bb2h, g_bb2h); SYM(bb2l, g_bb2l);
    SYM(bb2uh, g_bb2uh); SYM(bb2ul, g_bb2ul);
    __nv_bfloat16 *W0h, *W0l, *W1h, *W1l, *W2h, *W2l;
    SYM(W0h, g_W0h); SYM(W0l, g_W0l); SYM(W1h, g_W1h); SYM(W1l, g_W1l);
    SYM(W2h, g_W2h); SYM(W2l, g_W2l);

    const int LD0 = 6 * CC, LD1 = 12 * CC, LD2 = 8 * CC;

    MMBatch mb = {};

    // ---- operator splits (one launch) ----
    {
        SParams sp = {};
        int blks = 0;
        auto add = [&](const float* s, __nv_bfloat16* dh, __nv_bfloat16* dl, size_t cnt) {
            SJob& j = sp.j[sp.n++];
            j.src = s; j.dh = dh; j.dl = dl; j.n8 = (int)(cnt / 8); j.blkStart = blks;
            blks += (j.n8 + 255) / 256;
        };
        add(L0,  L0h,  L0l,  (size_t)Nn0 * Nn0);
        add(L1d, L1dh, L1dl, (size_t)Nn1 * Nn1);
        add(L1u, L1uh, L1ul, (size_t)Nn1 * Nn1);
        add(L2d, L2dh, L2dl, (size_t)Nn2 * Nn2);
        add(L2u, L2uh, L2ul, (size_t)Nn2 * Nn2);
        add(B1,  B1h,  B1l,  (size_t)Nn0 * Nn1);
        add(B2,  B2h,  B2l,  (size_t)Nn1 * Nn2);
        splitb_kernel<<<blks, 256>>>(sp);
    }
    {
        TParams tp = {};
        int t0 = ((Nn0 + 31) / 32) * ((Nn1 + 31) / 32);
        tp.j[0] = TJob{ B1, B1th, B1tl, Nn1, Nn0, Nn1, 0, (Nn0 + 31) / 32 };
        tp.j[1] = TJob{ B2, B2th, B2tl, Nn2, Nn1, Nn2, t0, (Nn1 + 31) / 32 };
        int t1 = t0 + ((Nn1 + 31) / 32) * ((Nn2 + 31) / 32);
        tp.n = 2;
        tsplitb_kernel<<<t1, dim3(32, 8)>>>(tp);
    }

    // ---- input linears (one launch) ----
    {
        LParams lp = {};
        lp.j[0] = { x0, in_w0, in_b0, h0, Nn0, 0 };
        lp.j[1] = { x1, in_w1, in_b1, h1, Nn1, Nn0 };
        lp.j[2] = { x2, in_w2, in_b2, h2, Nn2, Nn0 + Nn1 };
        lp.n = 3;
        linb_kernel<<<Nn0 + Nn1 + Nn2, CC>>>(lp);
    }

    for (int layer = 0; layer < 2; layer++) {
        build_wt_kernel<<<6 * CC,  CC>>>(lw[layer][0], W0h, W0l, 0, 6,  6);
        build_wt_kernel<<<12 * CC, CC>>>(lw[layer][1], W1h, W1l, 1, 11, 12);
        build_wt_kernel<<<8 * CC,  CC>>>(lw[layer][2], W2h, W2l, 2, 8,  8);

        // h conversion: row bf16 into X slice 0 (+dup) and transposed into btA cols 0-127
        {
            HParams hp = {};
            int tiles = 0;
            int tr0 = (Nn0 + 31) / 32, tr1 = (Nn1 + 31) / 32, tr2 = (Nn2 + 31) / 32;
            hp.j[0] = { h0, X0qh, X0ql, nullptr, nullptr, bt0h, bt0l, nullptr, nullptr,
                        Nn0, LD0, tiles, tr0 };
            tiles += tr0 * 4;
            hp.j[1] = { h1, X1qh, X1ql, X1qh + 256, X1ql + 256, bt1ah, bt1al, bt1bh, bt1bl,
                        Nn1, LD1, tiles, tr1 };
            tiles += tr1 * 4;
            hp.j[2] = { h2, X2qh, X2ql, nullptr, nullptr, bt2h, bt2l, nullptr, nullptr,
                        Nn2, LD2, tiles, tr2 };
            tiles += tr2 * 4;
            hp.n = 3;
            hconv_kernel<<<tiles, dim3(32, 8)>>>(hp);
        }

        // projections: epilogue -> X slice (row) + btA cols 128-255 (transposed)
        mmAdd(mb, B1h,  B1l,  Nn1, bt1ah, bt1al, Nn1, Nn0, 128, Nn1,
              nullptr, 0, X0qh + 128, X0ql + 128, LD0, bt0h + 128 * Nn0, bt0l + 128 * Nn0, Nn0);
        mmAdd(mb, B1th, B1tl, Nn0, bt0h,  bt0l,  Nn0, Nn1, 128, Nn0,
              nullptr, 0, X1qh + 128, X1ql + 128, LD1, bt1ah + 128 * Nn1, bt1al + 128 * Nn1, Nn1);
        mmAdd(mb, B2h,  B2l,  Nn2, bt2h,  bt2l,  Nn2, Nn1, 128, Nn2,
              nullptr, 0, X1qh + 384, X1ql + 384, LD1, bt1bh + 128 * Nn1, bt1bl + 128 * Nn1, Nn1);
        mmAdd(mb, B2th, B2tl, Nn1, bt1ah, bt1al, Nn1, Nn2, 128, Nn1,
              nullptr, 0, X2qh + 128, X2ql + 128, LD2, bt2h + 128 * Nn2, bt2l + 128 * Nn2, Nn2);
        mmRun(mb);

        // first hops: epilogue -> X slices (row) + btB (transposed)
        mmAdd(mb, L0h,  L0l,  Nn0, bt0h,  bt0l,  Nn0, Nn0, 256, Nn0,
              nullptr, 0, X0qh + 256, X0ql + 256, LD0, bb0h, bb0l, Nn0);
        mmAdd(mb, L1dh, L1dl, Nn1, bt1ah, bt1al, Nn1, Nn1, 256, Nn1,
              nullptr, 0, X1qh + 512, X1ql + 512, LD1, bb1ah, bb1al, Nn1);
        mmAdd(mb, L1uh, L1ul, Nn1, bt1bh, bt1bl, Nn1, Nn1, 256, Nn1,
              nullptr, 0, X1qh + 768, X1ql + 768, LD1, bb1bh, bb1bl, Nn1);
        mmAdd(mb, L2dh, L2dl, Nn2, bt2h,  bt2l,  Nn2, Nn2, 256, Nn2,
              nullptr, 0, X2qh + 256, X2ql + 256, LD2, bb2h, bb2l, Nn2);
        mmAdd(mb, L2uh, L2ul, Nn2, bt2h,  bt2l,  Nn2, Nn2, 128, Nn2,
              nullptr, 0, X2qh + 768, X2ql + 768, LD2, bb2uh, bb2ul, Nn2);
        mmRun(mb);

        // second hops: epilogue -> X slices (row) only
        mmAdd(mb, L0h,  L0l,  Nn0, bb0h,  bb0l,  Nn0, Nn0, 256, Nn0,
              nullptr, 0, X0qh + 512, X0ql + 512, LD0, nullptr, nullptr, 0);
        mmAdd(mb, L1dh, L1dl, Nn1, bb1ah, bb1al, Nn1, Nn1, 256, Nn1,
              nullptr, 0, X1qh + 1024, X1ql + 1024, LD1, nullptr, nullptr, 0);
        mmAdd(mb, L1uh, L1ul, Nn1, bb1bh, bb1bl, Nn1, Nn1, 256, Nn1,
              nullptr, 0, X1qh + 1280, X1ql + 1280, LD1, nullptr, nullptr, 0);
        mmAdd(mb, L2dh, L2dl, Nn2, bb2h,  bb2l,  Nn2, Nn2, 256, Nn2,
              nullptr, 0, X2qh + 512, X2ql + 512, LD2, nullptr, nullptr, 0);
        mmAdd(mb, L2uh, L2ul, Nn2, bb2uh, bb2ul, Nn2, Nn2, 128, Nn2,
              nullptr, 0, X2qh + 896, X2ql + 896, LD2, nullptr, nullptr, 0);
        mmRun(mb);

        // einsums: fp32 h output
        mmAdd(mb, X0qh, X0ql, LD0, W0h, W0l, LD0, Nn0, 128, LD0,
              h0, CC, nullptr, nullptr, 0, nullptr, nullptr, 0);
        mmAdd(mb, X1qh, X1ql, LD1, W1h, W1l, LD1, Nn1, 128, LD1,
              h1, CC, nullptr, nullptr, 0, nullptr, nullptr, 0);
        mmAdd(mb, X2qh, X2ql, LD2, W2h, W2l, LD2, Nn2, 128, LD2,
              h2, CC, nullptr, nullptr, 0, nullptr, nullptr, 0);
        mmRun(mb);
    }

    head_kernel<<<(Nn0 * 2 + 255) / 256, 256>>>(h0, out_w, out_b, out, Nn0 * 2);
}

// round 10
// speedup vs baseline: 3.1012x; 1.3476x over previous
#include <cuda_runtime.h>
#include <cuda_bf16.h>
#include <math.h>
#include <stdint.h>

#define Nn0 2000
#define Nn1 6000
#define Nn2 4000
#define CC  128

// ================= static scratch (no allocation) =================
__device__ float g_h0[Nn0 * CC];
__device__ float g_h1[Nn1 * CC];
__device__ float g_h2[Nn2 * CC];

// operators bf16 hi/lo (only the ones on the live path get filled)
__device__ __nv_bfloat16 g_L0h[Nn0 * Nn0],  g_L0l[Nn0 * Nn0];
__device__ __nv_bfloat16 g_L1dh[Nn1 * Nn1], g_L1dl[Nn1 * Nn1];
__device__ __nv_bfloat16 g_L1uh[Nn1 * Nn1], g_L1ul[Nn1 * Nn1];
__device__ __nv_bfloat16 g_B1h[Nn0 * Nn1],  g_B1l[Nn0 * Nn1];
__device__ __nv_bfloat16 g_B1th[Nn1 * Nn0], g_B1tl[Nn1 * Nn0];
__device__ __nv_bfloat16 g_B2h[Nn1 * Nn2],  g_B2l[Nn1 * Nn2];

// einsum A operands, row-major bf16 hi/lo
__device__ __nv_bfloat16 g_X0qh[Nn0 * 6 * CC],  g_X0ql[Nn0 * 6 * CC];
__device__ __nv_bfloat16 g_X1qh[Nn1 * 12 * CC], g_X1ql[Nn1 * 12 * CC];

// transposed B-operand buffers
__device__ __nv_bfloat16 g_bt0h[256 * Nn0],  g_bt0l[256 * Nn0];
__device__ __nv_bfloat16 g_bt1ah[256 * Nn1], g_bt1al[256 * Nn1];
__device__ __nv_bfloat16 g_bt1bh[256 * Nn1], g_bt1bl[256 * Nn1];
__device__ __nv_bfloat16 g_bt2h[128 * Nn2],  g_bt2l[128 * Nn2];
__device__ __nv_bfloat16 g_bb0h[256 * Nn0],  g_bb0l[256 * Nn0];
__device__ __nv_bfloat16 g_bb1ah[256 * Nn1], g_bb1al[256 * Nn1];
__device__ __nv_bfloat16 g_bb1bh[256 * Nn1], g_bb1bl[256 * Nn1];

// einsum weights, transposed [128, S*128] bf16 hi/lo
__device__ __nv_bfloat16 g_W0h[CC * 6 * CC],  g_W0l[CC * 6 * CC];
__device__ __nv_bfloat16 g_W1h[CC * 12 * CC], g_W1l[CC * 12 * CC];

__constant__ int c_maps[3][12] = {
    {0, 3, 1, 4, 2, 5, -1, -1, -1, -1, -1, -1},
    {0, 5, -1, 8, 1, 6, 3, 9, 2, 7, 4, 10},
    {0, 5, 1, 6, 2, 7, 3, 4, -1, -1, -1, -1},
};

// ================= PTX helpers (plain sm_80+ PTX) =================
__device__ __forceinline__ uint32_t smem_u32(const void* p) {
    uint32_t a;
    asm("{ .reg .u64 t; cvta.to.shared.u64 t, %1; cvt.u32.u64 %0, t; }" : "=r"(a) : "l"(p));
    return a;
}
__device__ __forceinline__ void ldsm_x4(uint32_t* r, uint32_t a) {
    asm volatile("ldmatrix.sync.aligned.m8n8.x4.shared.b16 {%0,%1,%2,%3}, [%4];"
                 : "=r"(r[0]), "=r"(r[1]), "=r"(r[2]), "=r"(r[3]) : "r"(a));
}
__device__ __forceinline__ void mma_bf16(float* c, const uint32_t* a, const uint32_t* b) {
    asm volatile(
        "mma.sync.aligned.m16n8k16.row.col.f32.bf16.bf16.f32 "
        "{%0,%1,%2,%3}, {%4,%5,%6,%7}, {%8,%9}, {%0,%1,%2,%3};"
        : "+f"(c[0]), "+f"(c[1]), "+f"(c[2]), "+f"(c[3])
        : "r"(a[0]), "r"(a[1]), "r"(a[2]), "r"(a[3]), "r"(b[0]), "r"(b[1]));
}
__device__ __forceinline__ void cp_async16(uint32_t dst, const void* src, int sz) {
    asm volatile("cp.async.cg.shared.global [%0], [%1], 16, %2;"
                 :: "r"(dst), "l"(src), "r"(sz));
}
// swizzled byte addr within a [128 rows x 32 bf16] tile (64B rows, 16B chunks)
__device__ __forceinline__ uint32_t sw_addr(uint32_t tile_base, int r, int chunk) {
    return tile_base + (uint32_t)(r * 64) + (uint32_t)((chunk ^ ((r >> 1) & 3)) << 4);
}

// ================= batched bf16x3 HMMA GEMM with fused-convert epilogue =====
#define MM_SMEM (3 * 4 * 8192)
#define MAXJOB 6

struct MMJob {
    const __nv_bfloat16 *Ah, *Al, *Bh, *Bl;
    float* Cf;
    __nv_bfloat16 *Rh, *Rl;
    __nv_bfloat16 *Th, *Tl;
    int M, K, lda, ldb, ldc, ldR, ldT, tileStart, tilesX;
};
struct MMParams { MMJob j[MAXJOB]; int n; };

__global__ __launch_bounds__(256, 2)
void mmb_kernel(MMParams P)
{
    extern __shared__ __align__(128) char smem[];
    const uint32_t sbase = smem_u32(smem);
    const int tid = threadIdx.x, lane = tid & 31, wid = tid >> 5;
    const int wm = wid & 1, wn = wid >> 1;

    int bt = blockIdx.x;
    int ji = 0;
#pragma unroll 1
    while (ji + 1 < P.n && bt >= P.j[ji + 1].tileStart) ji++;
    const MMJob jb = P.j[ji];
    const int rel = bt - jb.tileStart;
    const int m0 = (rel % jb.tilesX) * 128;
    const int n0 = (rel / jb.tilesX) * 128;
    const int M = jb.M, K = jb.K, lda = jb.lda, ldb = jb.ldb;
    const int mrows = (M - m0 < 128) ? (M - m0) : 128;
    const __nv_bfloat16* Ah = jb.Ah + (size_t)m0 * lda;
    const __nv_bfloat16* Al = jb.Al + (size_t)m0 * lda;
    const __nv_bfloat16* Bh = jb.Bh + (size_t)n0 * ldb;
    const __nv_bfloat16* Bl = jb.Bl + (size_t)n0 * ldb;
    const int nk = (K + 31) >> 5;

    float acc[4][4][4];
#pragma unroll
    for (int i = 0; i < 4; i++)
#pragma unroll
        for (int j = 0; j < 4; j++)
#pragma unroll
            for (int v = 0; v < 4; v++) acc[i][j][v] = 0.f;

    auto load_stage = [&](int t) {
        const uint32_t sb = sbase + (uint32_t)(t % 3) * 32768;
        const int k0 = t << 5;
#pragma unroll
        for (int i = 0; i < 8; i++) {
            int idx = tid + i * 256;
            int tile = idx >> 9;
            int rem  = idx & 511;
            int r = rem >> 2, c = rem & 3;
            const __nv_bfloat16* gp;
            int ok;
            if (tile < 2) {
                gp = (tile == 0 ? Ah : Al) + (size_t)r * lda + k0 + c * 8;
                ok = (r < mrows) && (k0 + c * 8 < K);
            } else {
                gp = (tile == 2 ? Bh : Bl) + (size_t)r * ldb + k0 + c * 8;
                ok = (k0 + c * 8 < K);
            }
            cp_async16(sb + (uint32_t)tile * 8192 + sw_addr(0, r, c), gp, ok ? 16 : 0);
        }
    };

#pragma unroll
    for (int s = 0; s < 2; s++) {
        if (s < nk) load_stage(s);
        asm volatile("cp.async.commit_group;" ::: "memory");
    }

    const int frag_r = lane & 15;
    const int frag_c = lane >> 4;

    for (int t = 0; t < nk; t++) {
        asm volatile("cp.async.wait_group 1;" ::: "memory");
        __syncthreads();
        const uint32_t sb = sbase + (uint32_t)(t % 3) * 32768;
        const uint32_t tAh = sb, tAl = sb + 8192, tBh = sb + 16384, tBl = sb + 24576;

#pragma unroll
        for (int ks = 0; ks < 2; ks++) {
            const int ch = ks * 2 + frag_c;
            uint32_t bh[4][2], bl[4][2];
#pragma unroll
            for (int j = 0; j < 2; j++) {
                int r = wn * 32 + j * 16 + frag_r;
                uint32_t rr[4];
                ldsm_x4(rr, sw_addr(tBh, r, ch));
                bh[2 * j][0] = rr[0]; bh[2 * j][1] = rr[2];
                bh[2 * j + 1][0] = rr[1]; bh[2 * j + 1][1] = rr[3];
                ldsm_x4(rr, sw_addr(tBl, r, ch));
                bl[2 * j][0] = rr[0]; bl[2 * j][1] = rr[2];
                bl[2 * j + 1][0] = rr[1]; bl[2 * j + 1][1] = rr[3];
            }
#pragma unroll
            for (int mt = 0; mt < 4; mt++) {
                int r = wm * 64 + mt * 16 + frag_r;
                uint32_t ah[4], al[4];
                ldsm_x4(ah, sw_addr(tAh, r, ch));
                ldsm_x4(al, sw_addr(tAl, r, ch));
#pragma unroll
                for (int nt = 0; nt < 4; nt++) mma_bf16(acc[mt][nt], ah, bh[nt]);
#pragma unroll
                for (int nt = 0; nt < 4; nt++) mma_bf16(acc[mt][nt], ah, bl[nt]);
#pragma unroll
                for (int nt = 0; nt < 4; nt++) mma_bf16(acc[mt][nt], al, bh[nt]);
            }
        }
        // NOTE: no second __syncthreads needed — top-of-next-iter sync orders
        // buffer reuse (stage t+2 overwrites buffer consumed at t-1).
        if (t + 2 < nk) load_stage(t + 2);
        asm volatile("cp.async.commit_group;" ::: "memory");
    }

    // ---- fused epilogue ----
    const int er = lane >> 2, ec = (lane & 3) * 2;
    const bool doBF = (jb.Rh != nullptr) || (jb.Th != nullptr);
#pragma unroll
    for (int mt = 0; mt < 4; mt++) {
        int r0 = m0 + wm * 64 + mt * 16 + er;
        int r1 = r0 + 8;
#pragma unroll
        for (int nt = 0; nt < 4; nt++) {
            int col = n0 + wn * 32 + nt * 8 + ec;
            float f0 = acc[mt][nt][0], f1 = acc[mt][nt][1];
            float f2 = acc[mt][nt][2], f3 = acc[mt][nt][3];
            if (jb.Cf) {
                if (r0 < M) *(float2*)&jb.Cf[(size_t)r0 * jb.ldc + col] = make_float2(f0, f1);
                if (r1 < M) *(float2*)&jb.Cf[(size_t)r1 * jb.ldc + col] = make_float2(f2, f3);
            }
            if (doBF) {
                __nv_bfloat16 h0 = __float2bfloat16(f0), h1 = __float2bfloat16(f1);
                __nv_bfloat16 h2 = __float2bfloat16(f2), h3 = __float2bfloat16(f3);
                __nv_bfloat16 l0 = __float2bfloat16(f0 - __bfloat162float(h0));
                __nv_bfloat16 l1 = __float2bfloat16(f1 - __bfloat162float(h1));
                __nv_bfloat16 l2 = __float2bfloat16(f2 - __bfloat162float(h2));
                __nv_bfloat16 l3 = __float2bfloat16(f3 - __bfloat162float(h3));
                if (jb.Rh) {
                    if (r0 < M) {
                        *(__nv_bfloat162*)&jb.Rh[(size_t)r0 * jb.ldR + col] = __halves2bfloat162(h0, h1);
                        *(__nv_bfloat162*)&jb.Rl[(size_t)r0 * jb.ldR + col] = __halves2bfloat162(l0, l1);
                    }
                    if (r1 < M) {
                        *(__nv_bfloat162*)&jb.Rh[(size_t)r1 * jb.ldR + col] = __halves2bfloat162(h2, h3);
                        *(__nv_bfloat162*)&jb.Rl[(size_t)r1 * jb.ldR + col] = __halves2bfloat162(l2, l3);
                    }
                }
                if (jb.Th) {
                    size_t cA = (size_t)col * jb.ldT, cB = (size_t)(col + 1) * jb.ldT;
                    if (r0 < M) {
                        jb.Th[cA + r0] = h0; jb.Th[cB + r0] = h1;
                        jb.Tl[cA + r0] = l0; jb.Tl[cB + r0] = l1;
                    }
                    if (r1 < M) {
                        jb.Th[cA + r1] = h2; jb.Th[cB + r1] = h3;
                        jb.Tl[cA + r1] = l2; jb.Tl[cB + r1] = l3;
                    }
                }
            }
        }
    }
}

// ================= operator split (8 floats/thread) =================
struct SJob { const float* src; __nv_bfloat16 *dh, *dl; int n8, blkStart; };
struct SParams { SJob j[8]; int n; };

__global__ void splitb_kernel(SParams P)
{
    int b = blockIdx.x;
    int ji = 0;
#pragma unroll 1
    while (ji + 1 < P.n && b >= P.j[ji + 1].blkStart) ji++;
    const SJob jb = P.j[ji];
    int i = (b - jb.blkStart) * 256 + threadIdx.x;
    if (i >= jb.n8) return;
    float4 v0 = ((const float4*)jb.src)[i * 2];
    float4 v1 = ((const float4*)jb.src)[i * 2 + 1];
    __nv_bfloat162 h[4], l[4];
    h[0] = __floats2bfloat162_rn(v0.x, v0.y);
    h[1] = __floats2bfloat162_rn(v0.z, v0.w);
    h[2] = __floats2bfloat162_rn(v1.x, v1.y);
    h[3] = __floats2bfloat162_rn(v1.z, v1.w);
    l[0] = __floats2bfloat162_rn(v0.x - __bfloat162float(h[0].x), v0.y - __bfloat162float(h[0].y));
    l[1] = __floats2bfloat162_rn(v0.z - __bfloat162float(h[1].x), v0.w - __bfloat162float(h[1].y));
    l[2] = __floats2bfloat162_rn(v1.x - __bfloat162float(h[2].x), v1.y - __bfloat162float(h[2].y));
    l[3] = __floats2bfloat162_rn(v1.z - __bfloat162float(h[3].x), v1.w - __bfloat162float(h[3].y));
    ((uint4*)jb.dh)[i] = *(uint4*)h;
    ((uint4*)jb.dl)[i] = *(uint4*)l;
}

// ================= transpose-split (B1^T only) =================
__global__ void tsplit1_kernel(const float* __restrict__ src,
                               __nv_bfloat16* __restrict__ dh, __nv_bfloat16* __restrict__ dl,
                               int lds, int rows, int cols, int tilesR)
{
    __shared__ float tile[32][33];
    int rel = blockIdx.x;
    int k0 = (rel % tilesR) * 32, n0 = (rel / tilesR) * 32;
    int tx = threadIdx.x, ty = threadIdx.y;
    for (int i = ty; i < 32; i += 8) {
        int k = k0 + i, n = n0 + tx;
        tile[i][tx] = (k < rows && n < cols) ? src[(size_t)k * lds + n] : 0.f;
    }
    __syncthreads();
    for (int i = ty; i < 32; i += 8) {
        int n = n0 + i, k = k0 + tx;
        if (n < cols && k < rows) {
            float v = tile[tx][i];
            __nv_bfloat16 h = __float2bfloat16(v);
            dh[(size_t)n * rows + k] = h;
            dl[(size_t)n * rows + k] = __float2bfloat16(v - __bfloat162float(h));
        }
    }
}

// ================= hconv: h fp32 -> optional row bf16 + optional transposed ==
struct HJob {
    const float* src;
    __nv_bfloat16 *Rh, *Rl, *R2h, *R2l;
    __nv_bfloat16 *Th, *Tl, *T2h, *T2l;
    int rows, ldR, tileStart, tilesR;
};
struct HParams { HJob j[3]; int n; };

__global__ void hconv_kernel(HParams P)
{
    __shared__ float tile[32][33];
    int b = blockIdx.x;
    int ji = 0;
#pragma unroll 1
    while (ji + 1 < P.n && b >= P.j[ji + 1].tileStart) ji++;
    const HJob jb = P.j[ji];
    int rel = b - jb.tileStart;
    int r0 = (rel % jb.tilesR) * 32, c0 = (rel / jb.tilesR) * 32;
    int tx = threadIdx.x, ty = threadIdx.y;
    for (int i = ty; i < 32; i += 8) {
        int r = r0 + i, c = c0 + tx;
        float v = (r < jb.rows) ? jb.src[(size_t)r * CC + c] : 0.f;
        tile[i][tx] = v;
        if (r < jb.rows && jb.Rh) {
            __nv_bfloat16 h = __float2bfloat16(v);
            __nv_bfloat16 l = __float2bfloat16(v - __bfloat162float(h));
            jb.Rh[(size_t)r * jb.ldR + c] = h;
            jb.Rl[(size_t)r * jb.ldR + c] = l;
            if (jb.R2h) { jb.R2h[(size_t)r * jb.ldR + c] = h; jb.R2l[(size_t)r * jb.ldR + c] = l; }
        }
    }
    __syncthreads();
    if (!jb.Th) return;
    for (int i = ty; i < 32; i += 8) {
        int c = c0 + i, r = r0 + tx;
        if (r < jb.rows) {
            float v = tile[tx][i];
            __nv_bfloat16 h = __float2bfloat16(v);
            __nv_bfloat16 l = __float2bfloat16(v - __bfloat162float(h));
            size_t idx = (size_t)c * jb.rows + r;
            jb.Th[idx] = h; jb.Tl[idx] = l;
            if (jb.T2h) { jb.T2h[idx] = h; jb.T2l[idx] = l; }
        }
    }
}

// ================= small kernels =================
struct LJob { const float *x, *W, *b; float* y; int rows, rowStart; };
struct LParams { LJob j[3]; int n; };

__global__ void linb_kernel(LParams P)
{
    __shared__ float xs[CC];
    int b = blockIdx.x;
    int ji = 0;
#pragma unroll 1
    while (ji + 1 < P.n && b >= P.j[ji + 1].rowStart) ji++;
    const LJob jb = P.j[ji];
    int n = b - jb.rowStart, o = threadIdx.x;
    xs[o] = jb.x[(size_t)n * CC + o];
    __syncthreads();
    float acc = jb.b[o];
    const float* wr = &jb.W[(size_t)o * CC];
#pragma unroll 8
    for (int i = 0; i < CC; i++) acc += xs[i] * wr[i];
    jb.y[(size_t)n * CC + o] = acc;
}

__global__ void build_wt_kernel(const float* __restrict__ w,
                                __nv_bfloat16* __restrict__ dh, __nv_bfloat16* __restrict__ dl,
                                int which, int korig, int S)
{
    int bi = blockIdx.x;
    int s = bi >> 7, o = bi & 127;
    int i = threadIdx.x;
    int k = c_maps[which][s];
    float v = (k >= 0) ? w[((size_t)i * CC + o) * korig + k] : 0.f;
    __nv_bfloat16 h = __float2bfloat16(v);
    size_t idx = (size_t)o * (S * CC) + s * CC + i;
    dh[idx] = h;
    dl[idx] = __float2bfloat16(v - __bfloat162float(h));
}

__global__ void head_kernel(const float* __restrict__ h0, const float* __restrict__ ow,
                            const float* __restrict__ ob, float* __restrict__ out, int total)
{
    int idx = blockIdx.x * blockDim.x + threadIdx.x;
    if (idx >= total) return;
    int n = idx >> 1, c = idx & 1;
    float acc = ob[c];
    const float* hr = &h0[(size_t)n * CC];
    const float* wr = &ow[(size_t)c * CC];
#pragma unroll 8
    for (int i = 0; i < CC; i++) acc += hr[i] * wr[i];
    out[idx] = 1.f / (1.f + expf(-acc));
}

// ================= host-side batch builders =================
struct MMBatch { MMParams p; int tiles; };
static void mmAdd(MMBatch& b,
                  const __nv_bfloat16* Ah, const __nv_bfloat16* Al, int lda,
                  const __nv_bfloat16* Bh, const __nv_bfloat16* Bl, int ldb,
                  int M, int N, int K,
                  float* Cf, int ldc,
                  __nv_bfloat16* Rh, __nv_bfloat16* Rl, int ldR,
                  __nv_bfloat16* Th, __nv_bfloat16* Tl, int ldT)
{
    MMJob& j = b.p.j[b.p.n++];
    j.Ah = Ah; j.Al = Al; j.Bh = Bh; j.Bl = Bl;
    j.Cf = Cf; j.Rh = Rh; j.Rl = Rl; j.Th = Th; j.Tl = Tl;
    j.M = M; j.K = K; j.lda = lda; j.ldb = ldb; j.ldc = ldc; j.ldR = ldR; j.ldT = ldT;
    j.tileStart = b.tiles; j.tilesX = (M + 127) / 128;
    b.tiles += j.tilesX * (N / 128);
}
static void mmRun(MMBatch& b)
{
    if (b.p.n) mmb_kernel<<<b.tiles, 256, MM_SMEM>>>(b.p);
    b.p.n = 0; b.tiles = 0;
}

#define SYM(v, g) { void* p_; cudaGetSymbolAddress(&p_, g); v = (decltype(v))p_; }

extern "C" void kernel_launch(void* const* d_in, const int* in_sizes, int n_in,
                              void* d_out, int out_size)
{
    (void)in_sizes; (void)n_in; (void)out_size;
    const float* x0    = (const float*)d_in[0];
    const float* x1    = (const float*)d_in[1];
    const float* x2    = (const float*)d_in[2];
    const float* L0    = (const float*)d_in[3];
    const float* L1d   = (const float*)d_in[4];
    const float* L1u   = (const float*)d_in[5];
    const float* B1    = (const float*)d_in[8];
    const float* B2    = (const float*)d_in[9];
    const float* in_w0 = (const float*)d_in[10];
    const float* in_b0 = (const float*)d_in[11];
    const float* in_w1 = (const float*)d_in[12];
    const float* in_b1 = (const float*)d_in[13];
    const float* in_w2 = (const float*)d_in[14];
    const float* in_b2 = (const float*)d_in[15];
    const float* l0_w0 = (const float*)d_in[16];
    const float* l0_w1 = (const float*)d_in[17];
    const float* l1_w0 = (const float*)d_in[19];
    const float* out_w = (const float*)d_in[22];
    const float* out_b = (const float*)d_in[23];
    float* out = (float*)d_out;

    cudaFuncSetAttribute(mmb_kernel, cudaFuncAttributeMaxDynamicSharedMemorySize, MM_SMEM);

    float *h0, *h1, *h2;
    SYM(h0, g_h0); SYM(h1, g_h1); SYM(h2, g_h2);
    __nv_bfloat16 *L0h, *L0l, *L1dh, *L1dl, *L1uh, *L1ul;
    __nv_bfloat16 *B1h, *B1l, *B1th, *B1tl, *B2h, *B2l;
    SYM(L0h, g_L0h); SYM(L0l, g_L0l);
    SYM(L1dh, g_L1dh); SYM(L1dl, g_L1dl); SYM(L1uh, g_L1uh); SYM(L1ul, g_L1ul);
    SYM(B1h, g_B1h); SYM(B1l, g_B1l); SYM(B1th, g_B1th); SYM(B1tl, g_B1tl);
    SYM(B2h, g_B2h); SYM(B2l, g_B2l);
    __nv_bfloat16 *X0qh, *X0ql, *X1qh, *X1ql;
    SYM(X0qh, g_X0qh); SYM(X0ql, g_X0ql); SYM(X1qh, g_X1qh); SYM(X1ql, g_X1ql);
    __nv_bfloat16 *bt0h, *bt0l, *bt1ah, *bt1al, *bt1bh, *bt1bl, *bt2h, *bt2l;
    SYM(bt0h, g_bt0h); SYM(bt0l, g_bt0l);
    SYM(bt1ah, g_bt1ah); SYM(bt1al, g_bt1al);
    SYM(bt1bh, g_bt1bh); SYM(bt1bl, g_bt1bl);
    SYM(bt2h, g_bt2h); SYM(bt2l, g_bt2l);
    __nv_bfloat16 *bb0h, *bb0l, *bb1ah, *bb1al, *bb1bh, *bb1bl;
    SYM(bb0h, g_bb0h); SYM(bb0l, g_bb0l);
    SYM(bb1ah, g_bb1ah); SYM(bb1al, g_bb1al);
    SYM(bb1bh, g_bb1bh); SYM(bb1bl, g_bb1bl);
    __nv_bfloat16 *W0h, *W0l, *W1h, *W1l;
    SYM(W0h, g_W0h); SYM(W0l, g_W0l); SYM(W1h, g_W1h); SYM(W1l, g_W1l);

    const int LD0 = 6 * CC, LD1 = 12 * CC;

    MMBatch mb = {};

    // ---- operator splits (live path only) ----
    {
        SParams sp = {};
        int blks = 0;
        auto add = [&](const float* s, __nv_bfloat16* dh, __nv_bfloat16* dl, size_t cnt) {
            SJob& j = sp.j[sp.n++];
            j.src = s; j.dh = dh; j.dl = dl; j.n8 = (int)(cnt / 8); j.blkStart = blks;
            blks += (j.n8 + 255) / 256;
        };
        add(L1d, L1dh, L1dl, (size_t)Nn1 * Nn1);
        add(L1u, L1uh, L1ul, (size_t)Nn1 * Nn1);
        add(B1,  B1h,  B1l,  (size_t)Nn0 * Nn1);
        add(B2,  B2h,  B2l,  (size_t)Nn1 * Nn2);
        add(L0,  L0h,  L0l,  (size_t)Nn0 * Nn0);
        splitb_kernel<<<blks, 256>>>(sp);
    }
    tsplit1_kernel<<<((Nn0 + 31) / 32) * ((Nn1 + 31) / 32), dim3(32, 8)>>>(
        B1, B1th, B1tl, Nn1, Nn0, Nn1, (Nn0 + 31) / 32);

    // ---- input linears ----
    {
        LParams lp = {};
        lp.j[0] = { x0, in_w0, in_b0, h0, Nn0, 0 };
        lp.j[1] = { x1, in_w1, in_b1, h1, Nn1, Nn0 };
        lp.j[2] = { x2, in_w2, in_b2, h2, Nn2, Nn0 + Nn1 };
        lp.n = 3;
        linb_kernel<<<Nn0 + Nn1 + Nn2, CC>>>(lp);
    }

    // ============ LAYER 0 (needs h0', h1' only) ============
    build_wt_kernel<<<6 * CC,  CC>>>(l0_w0, W0h, W0l, 0, 6,  6);
    build_wt_kernel<<<12 * CC, CC>>>(l0_w1, W1h, W1l, 1, 11, 12);

    // hconv: h0 -> X0 row slice0 + bt0[0:128]; h1 -> X1 slice0+dup + bt1a/bt1b[0:128];
    //        h2 -> transposed only bt2[0:128]
    {
        HParams hp = {};
        int tiles = 0;
        int tr0 = (Nn0 + 31) / 32, tr1 = (Nn1 + 31) / 32, tr2 = (Nn2 + 31) / 32;
        hp.j[0] = { h0, X0qh, X0ql, nullptr, nullptr, bt0h, bt0l, nullptr, nullptr,
                    Nn0, LD0, tiles, tr0 };
        tiles += tr0 * 4;
        hp.j[1] = { h1, X1qh, X1ql, X1qh + 256, X1ql + 256, bt1ah, bt1al, bt1bh, bt1bl,
                    Nn1, LD1, tiles, tr1 };
        tiles += tr1 * 4;
        hp.j[2] = { h2, nullptr, nullptr, nullptr, nullptr, bt2h, bt2l, nullptr, nullptr,
                    Nn2, 0, tiles, tr2 };
        tiles += tr2 * 4;
        hp.n = 3;
        hconv_kernel<<<tiles, dim3(32, 8)>>>(hp);
    }

    // projections (LPT: K=6000, 4000, 2000)
    mmAdd(mb, B1h,  B1l,  Nn1, bt1ah, bt1al, Nn1, Nn0, 128, Nn1,
          nullptr, 0, X0qh + 128, X0ql + 128, LD0, bt0h + 128 * Nn0, bt0l + 128 * Nn0, Nn0);
    mmAdd(mb, B2h,  B2l,  Nn2, bt2h,  bt2l,  Nn2, Nn1, 128, Nn2,
          nullptr, 0, X1qh + 384, X1ql + 384, LD1, bt1bh + 128 * Nn1, bt1bl + 128 * Nn1, Nn1);
    mmAdd(mb, B1th, B1tl, Nn0, bt0h,  bt0l,  Nn0, Nn1, 128, Nn0,
          nullptr, 0, X1qh + 128, X1ql + 128, LD1, bt1ah + 128 * Nn1, bt1al + 128 * Nn1, Nn1);
    mmRun(mb);

    // first hops (LPT: L1d, L1u K=6000 first, then L0)
    mmAdd(mb, L1dh, L1dl, Nn1, bt1ah, bt1al, Nn1, Nn1, 256, Nn1,
          nullptr, 0, X1qh + 512, X1ql + 512, LD1, bb1ah, bb1al, Nn1);
    mmAdd(mb, L1uh, L1ul, Nn1, bt1bh, bt1bl, Nn1, Nn1, 256, Nn1,
          nullptr, 0, X1qh + 768, X1ql + 768, LD1, bb1bh, bb1bl, Nn1);
    mmAdd(mb, L0h,  L0l,  Nn0, bt0h,  bt0l,  Nn0, Nn0, 256, Nn0,
          nullptr, 0, X0qh + 256, X0ql + 256, LD0, bb0h, bb0l, Nn0);
    mmRun(mb);

    // second hops
    mmAdd(mb, L1dh, L1dl, Nn1, bb1ah, bb1al, Nn1, Nn1, 256, Nn1,
          nullptr, 0, X1qh + 1024, X1ql + 1024, LD1, nullptr, nullptr, 0);
    mmAdd(mb, L1uh, L1ul, Nn1, bb1bh, bb1bl, Nn1, Nn1, 256, Nn1,
          nullptr, 0, X1qh + 1280, X1ql + 1280, LD1, nullptr, nullptr, 0);
    mmAdd(mb, L0h,  L0l,  Nn0, bb0h,  bb0l,  Nn0, Nn0, 256, Nn0,
          nullptr, 0, X0qh + 512, X0ql + 512, LD0, nullptr, nullptr, 0);
    mmRun(mb);

    // einsums (h0', h1'; LPT: X1 K=1536 first)
    mmAdd(mb, X1qh, X1ql, LD1, W1h, W1l, LD1, Nn1, 128, LD1,
          h1, CC, nullptr, nullptr, 0, nullptr, nullptr, 0);
    mmAdd(mb, X0qh, X0ql, LD0, W0h, W0l, LD0, Nn0, 128, LD0,
          h0, CC, nullptr, nullptr, 0, nullptr, nullptr, 0);
    mmRun(mb);

    // ============ LAYER 1 (needs h0'' only) ============
    build_wt_kernel<<<6 * CC, CC>>>(l1_w0, W0h, W0l, 0, 6, 6);

    // hconv: h0 -> X0 slice0 + bt0[0:128]; h1 -> transposed only bt1a[0:128]
    {
        HParams hp = {};
        int tiles = 0;
        int tr0 = (Nn0 + 31) / 32, tr1 = (Nn1 + 31) / 32;
        hp.j[0] = { h0, X0qh, X0ql, nullptr, nullptr, bt0h, bt0l, nullptr, nullptr,
                    Nn0, LD0, tiles, tr0 };
        tiles += tr0 * 4;
        hp.j[1] = { h1, nullptr, nullptr, nullptr, nullptr, bt1ah, bt1al, nullptr, nullptr,
                    Nn1, 0, tiles, tr1 };
        tiles += tr1 * 4;
        hp.n = 2;
        hconv_kernel<<<tiles, dim3(32, 8)>>>(hp);
    }

    // p = B1 @ h1
    mmAdd(mb, B1h, B1l, Nn1, bt1ah, bt1al, Nn1, Nn0, 128, Nn1,
          nullptr, 0, X0qh + 128, X0ql + 128, LD0, bt0h + 128 * Nn0, bt0l + 128 * Nn0, Nn0);
    mmRun(mb);
    // L0 hop1
    mmAdd(mb, L0h, L0l, Nn0, bt0h, bt0l, Nn0, Nn0, 256, Nn0,
          nullptr, 0, X0qh + 256, X0ql + 256, LD0, bb0h, bb0l, Nn0);
    mmRun(mb);
    // L0 hop2
    mmAdd(mb, L0h, L0l, Nn0, bb0h, bb0l, Nn0, Nn0, 256, Nn0,
          nullptr, 0, X0qh + 512, X0ql + 512, LD0, nullptr, nullptr, 0);
    mmRun(mb);
    // einsum0 -> h0''
    mmAdd(mb, X0qh, X0ql, LD0, W0h, W0l, LD0, Nn0, 128, LD0,
          h0, CC, nullptr, nullptr, 0, nullptr, nullptr, 0);
    mmRun(mb);

    head_kernel<<<(Nn0 * 2 + 255) / 256, 256>>>(h0, out_w, out_b, out, Nn0 * 2);
}

// round 11
// speedup vs baseline: 4.1203x; 1.3286x over previous
#include <cuda_runtime.h>
#include <cuda_bf16.h>
#include <math.h>
#include <stdint.h>

#define Nn0 2000
#define Nn1 6000
#define Nn2 4000
#define CC  128

// ================= static scratch (no allocation) =================
__device__ float g_h0[Nn0 * CC];
__device__ float g_h1[Nn1 * CC];
__device__ float g_h2[Nn2 * CC];

// split-K partial pool (max concurrent: 4+4 chains @6000x256 + 2 @2000x256 = 13.3M floats)
__device__ float g_part[14 * 1024 * 1024];

// operators bf16 hi/lo (live path only)
__device__ __nv_bfloat16 g_L0h[Nn0 * Nn0],  g_L0l[Nn0 * Nn0];
__device__ __nv_bfloat16 g_L1dh[Nn1 * Nn1], g_L1dl[Nn1 * Nn1];
__device__ __nv_bfloat16 g_L1uh[Nn1 * Nn1], g_L1ul[Nn1 * Nn1];
__device__ __nv_bfloat16 g_B1h[Nn0 * Nn1],  g_B1l[Nn0 * Nn1];
__device__ __nv_bfloat16 g_B1th[Nn1 * Nn0], g_B1tl[Nn1 * Nn0];
__device__ __nv_bfloat16 g_B2h[Nn1 * Nn2],  g_B2l[Nn1 * Nn2];

// einsum A operands, row-major bf16 hi/lo
__device__ __nv_bfloat16 g_X0qh[Nn0 * 6 * CC],  g_X0ql[Nn0 * 6 * CC];
__device__ __nv_bfloat16 g_X1qh[Nn1 * 12 * CC], g_X1ql[Nn1 * 12 * CC];

// transposed B-operand buffers
__device__ __nv_bfloat16 g_bt0h[256 * Nn0],  g_bt0l[256 * Nn0];
__device__ __nv_bfloat16 g_bt1ah[256 * Nn1], g_bt1al[256 * Nn1];
__device__ __nv_bfloat16 g_bt1bh[256 * Nn1], g_bt1bl[256 * Nn1];
__device__ __nv_bfloat16 g_bt2h[128 * Nn2],  g_bt2l[128 * Nn2];
__device__ __nv_bfloat16 g_bb0h[256 * Nn0],  g_bb0l[256 * Nn0];
__device__ __nv_bfloat16 g_bb1ah[256 * Nn1], g_bb1al[256 * Nn1];
__device__ __nv_bfloat16 g_bb1bh[256 * Nn1], g_bb1bl[256 * Nn1];

// einsum weights, transposed [128, S*128] bf16 hi/lo
__device__ __nv_bfloat16 g_W0h[CC * 6 * CC],  g_W0l[CC * 6 * CC];
__device__ __nv_bfloat16 g_W1h[CC * 12 * CC], g_W1l[CC * 12 * CC];

__constant__ int c_maps[3][12] = {
    {0, 3, 1, 4, 2, 5, -1, -1, -1, -1, -1, -1},
    {0, 5, -1, 8, 1, 6, 3, 9, 2, 7, 4, 10},
    {0, 5, 1, 6, 2, 7, 3, 4, -1, -1, -1, -1},
};

// ================= PTX helpers (plain sm_80+ PTX) =================
__device__ __forceinline__ uint32_t smem_u32(const void* p) {
    uint32_t a;
    asm("{ .reg .u64 t; cvta.to.shared.u64 t, %1; cvt.u32.u64 %0, t; }" : "=r"(a) : "l"(p));
    return a;
}
__device__ __forceinline__ void ldsm_x4(uint32_t* r, uint32_t a) {
    asm volatile("ldmatrix.sync.aligned.m8n8.x4.shared.b16 {%0,%1,%2,%3}, [%4];"
                 : "=r"(r[0]), "=r"(r[1]), "=r"(r[2]), "=r"(r[3]) : "r"(a));
}
__device__ __forceinline__ void mma_bf16(float* c, const uint32_t* a, const uint32_t* b) {
    asm volatile(
        "mma.sync.aligned.m16n8k16.row.col.f32.bf16.bf16.f32 "
        "{%0,%1,%2,%3}, {%4,%5,%6,%7}, {%8,%9}, {%0,%1,%2,%3};"
        : "+f"(c[0]), "+f"(c[1]), "+f"(c[2]), "+f"(c[3])
        : "r"(a[0]), "r"(a[1]), "r"(a[2]), "r"(a[3]), "r"(b[0]), "r"(b[1]));
}
__device__ __forceinline__ void cp_async16(uint32_t dst, const void* src, int sz) {
    asm volatile("cp.async.cg.shared.global [%0], [%1], 16, %2;"
                 :: "r"(dst), "l"(src), "r"(sz));
}
__device__ __forceinline__ uint32_t sw_addr(uint32_t tile_base, int r, int chunk) {
    return tile_base + (uint32_t)(r * 64) + (uint32_t)((chunk ^ ((r >> 1) & 3)) << 4);
}

// ================= batched bf16x3 HMMA GEMM with fused-convert epilogue =====
#define MM_SMEM (3 * 4 * 8192)
#define MAXJOB 12

struct MMJob {
    const __nv_bfloat16 *Ah, *Al, *Bh, *Bl;
    float* Cf;
    __nv_bfloat16 *Rh, *Rl;
    __nv_bfloat16 *Th, *Tl;
    int M, K, lda, ldb, ldc, ldR, ldT, tileStart, tilesX;
};
struct MMParams { MMJob j[MAXJOB]; int n; };

__global__ __launch_bounds__(256, 2)
void mmb_kernel(MMParams P)
{
    extern __shared__ __align__(128) char smem[];
    const uint32_t sbase = smem_u32(smem);
    const int tid = threadIdx.x, lane = tid & 31, wid = tid >> 5;
    const int wm = wid & 1, wn = wid >> 1;

    int bt = blockIdx.x;
    int ji = 0;
#pragma unroll 1
    while (ji + 1 < P.n && bt >= P.j[ji + 1].tileStart) ji++;
    const MMJob jb = P.j[ji];
    const int rel = bt - jb.tileStart;
    const int m0 = (rel % jb.tilesX) * 128;
    const int n0 = (rel / jb.tilesX) * 128;
    const int M = jb.M, K = jb.K, lda = jb.lda, ldb = jb.ldb;
    const int mrows = (M - m0 < 128) ? (M - m0) : 128;
    const __nv_bfloat16* Ah = jb.Ah + (size_t)m0 * lda;
    const __nv_bfloat16* Al = jb.Al + (size_t)m0 * lda;
    const __nv_bfloat16* Bh = jb.Bh + (size_t)n0 * ldb;
    const __nv_bfloat16* Bl = jb.Bl + (size_t)n0 * ldb;
    const int nk = (K + 31) >> 5;

    float acc[4][4][4];
#pragma unroll
    for (int i = 0; i < 4; i++)
#pragma unroll
        for (int j = 0; j < 4; j++)
#pragma unroll
            for (int v = 0; v < 4; v++) acc[i][j][v] = 0.f;

    auto load_stage = [&](int t) {
        const uint32_t sb = sbase + (uint32_t)(t % 3) * 32768;
        const int k0 = t << 5;
#pragma unroll
        for (int i = 0; i < 8; i++) {
            int idx = tid + i * 256;
            int tile = idx >> 9;
            int rem  = idx & 511;
            int r = rem >> 2, c = rem & 3;
            const __nv_bfloat16* gp;
            int ok;
            if (tile < 2) {
                gp = (tile == 0 ? Ah : Al) + (size_t)r * lda + k0 + c * 8;
                ok = (r < mrows) && (k0 + c * 8 < K);
            } else {
                gp = (tile == 2 ? Bh : Bl) + (size_t)r * ldb + k0 + c * 8;
                ok = (k0 + c * 8 < K);
            }
            cp_async16(sb + (uint32_t)tile * 8192 + sw_addr(0, r, c), gp, ok ? 16 : 0);
        }
    };

#pragma unroll
    for (int s = 0; s < 2; s++) {
        if (s < nk) load_stage(s);
        asm volatile("cp.async.commit_group;" ::: "memory");
    }

    const int frag_r = lane & 15;
    const int frag_c = lane >> 4;

    for (int t = 0; t < nk; t++) {
        asm volatile("cp.async.wait_group 1;" ::: "memory");
        __syncthreads();
        const uint32_t sb = sbase + (uint32_t)(t % 3) * 32768;
        const uint32_t tAh = sb, tAl = sb + 8192, tBh = sb + 16384, tBl = sb + 24576;

#pragma unroll
        for (int ks = 0; ks < 2; ks++) {
            const int ch = ks * 2 + frag_c;
            uint32_t bh[4][2], bl[4][2];
#pragma unroll
            for (int j = 0; j < 2; j++) {
                int r = wn * 32 + j * 16 + frag_r;
                uint32_t rr[4];
                ldsm_x4(rr, sw_addr(tBh, r, ch));
                bh[2 * j][0] = rr[0]; bh[2 * j][1] = rr[2];
                bh[2 * j + 1][0] = rr[1]; bh[2 * j + 1][1] = rr[3];
                ldsm_x4(rr, sw_addr(tBl, r, ch));
                bl[2 * j][0] = rr[0]; bl[2 * j][1] = rr[2];
                bl[2 * j + 1][0] = rr[1]; bl[2 * j + 1][1] = rr[3];
            }
#pragma unroll
            for (int mt = 0; mt < 4; mt++) {
                int r = wm * 64 + mt * 16 + frag_r;
                uint32_t ah[4], al[4];
                ldsm_x4(ah, sw_addr(tAh, r, ch));
                ldsm_x4(al, sw_addr(tAl, r, ch));
#pragma unroll
                for (int nt = 0; nt < 4; nt++) mma_bf16(acc[mt][nt], ah, bh[nt]);
#pragma unroll
                for (int nt = 0; nt < 4; nt++) mma_bf16(acc[mt][nt], ah, bl[nt]);
#pragma unroll
                for (int nt = 0; nt < 4; nt++) mma_bf16(acc[mt][nt], al, bh[nt]);
            }
        }
        if (t + 2 < nk) load_stage(t + 2);
        asm volatile("cp.async.commit_group;" ::: "memory");
    }

    // ---- fused epilogue ----
    const int er = lane >> 2, ec = (lane & 3) * 2;
    const bool doBF = (jb.Rh != nullptr) || (jb.Th != nullptr);
#pragma unroll
    for (int mt = 0; mt < 4; mt++) {
        int r0 = m0 + wm * 64 + mt * 16 + er;
        int r1 = r0 + 8;
#pragma unroll
        for (int nt = 0; nt < 4; nt++) {
            int col = n0 + wn * 32 + nt * 8 + ec;
            float f0 = acc[mt][nt][0], f1 = acc[mt][nt][1];
            float f2 = acc[mt][nt][2], f3 = acc[mt][nt][3];
            if (jb.Cf) {
                if (r0 < M) *(float2*)&jb.Cf[(size_t)r0 * jb.ldc + col] = make_float2(f0, f1);
                if (r1 < M) *(float2*)&jb.Cf[(size_t)r1 * jb.ldc + col] = make_float2(f2, f3);
            }
            if (doBF) {
                __nv_bfloat16 h0 = __float2bfloat16(f0), h1 = __float2bfloat16(f1);
                __nv_bfloat16 h2 = __float2bfloat16(f2), h3 = __float2bfloat16(f3);
                __nv_bfloat16 l0 = __float2bfloat16(f0 - __bfloat162float(h0));
                __nv_bfloat16 l1 = __float2bfloat16(f1 - __bfloat162float(h1));
                __nv_bfloat16 l2 = __float2bfloat16(f2 - __bfloat162float(h2));
                __nv_bfloat16 l3 = __float2bfloat16(f3 - __bfloat162float(h3));
                if (jb.Rh) {
                    if (r0 < M) {
                        *(__nv_bfloat162*)&jb.Rh[(size_t)r0 * jb.ldR + col] = __halves2bfloat162(h0, h1);
                        *(__nv_bfloat162*)&jb.Rl[(size_t)r0 * jb.ldR + col] = __halves2bfloat162(l0, l1);
                    }
                    if (r1 < M) {
                        *(__nv_bfloat162*)&jb.Rh[(size_t)r1 * jb.ldR + col] = __halves2bfloat162(h2, h3);
                        *(__nv_bfloat162*)&jb.Rl[(size_t)r1 * jb.ldR + col] = __halves2bfloat162(l2, l3);
                    }
                }
                if (jb.Th) {
                    size_t cA = (size_t)col * jb.ldT, cB = (size_t)(col + 1) * jb.ldT;
                    if (r0 < M) {
                        jb.Th[cA + r0] = h0; jb.Th[cB + r0] = h1;
                        jb.Tl[cA + r0] = l0; jb.Tl[cB + r0] = l1;
                    }
                    if (r1 < M) {
                        jb.Th[cA + r1] = h2; jb.Th[cB + r1] = h3;
                        jb.Tl[cA + r1] = l2; jb.Tl[cB + r1] = l3;
                    }
                }
            }
        }
    }
}

// ================= reduce-convert: sum split-K partials -> bf16 row/T =======
struct RJob {
    const float* base; int nP, pStride, M, N;
    __nv_bfloat16 *Rh, *Rl; int ldR;
    __nv_bfloat16 *Th, *Tl; int ldT;
    int tileStart, tilesR;
};
struct RParams { RJob j[4]; int n; };

__global__ void rcvt_kernel(RParams P)
{
    __shared__ float tile[32][33];
    int b = blockIdx.x;
    int ji = 0;
#pragma unroll 1
    while (ji + 1 < P.n && b >= P.j[ji + 1].tileStart) ji++;
    const RJob jb = P.j[ji];
    int rel = b - jb.tileStart;
    int r0 = (rel % jb.tilesR) * 32, c0 = (rel / jb.tilesR) * 32;
    int tx = threadIdx.x, ty = threadIdx.y;
    for (int i = ty; i < 32; i += 8) {
        int r = r0 + i, c = c0 + tx;
        float v = 0.f;
        if (r < jb.M) {
            size_t off = (size_t)r * jb.N + c;
#pragma unroll 1
            for (int s = 0; s < jb.nP; s++) v += jb.base[off + (size_t)s * jb.pStride];
        }
        tile[i][tx] = v;
        if (r < jb.M && jb.Rh) {
            __nv_bfloat16 h = __float2bfloat16(v);
            __nv_bfloat16 l = __float2bfloat16(v - __bfloat162float(h));
            jb.Rh[(size_t)r * jb.ldR + c] = h;
            jb.Rl[(size_t)r * jb.ldR + c] = l;
        }
    }
    __syncthreads();
    if (!jb.Th) return;
    for (int i = ty; i < 32; i += 8) {
        int c = c0 + i, r = r0 + tx;
        if (r < jb.M) {
            float v = tile[tx][i];
            __nv_bfloat16 h = __float2bfloat16(v);
            __nv_bfloat16 l = __float2bfloat16(v - __bfloat162float(h));
            size_t idx = (size_t)c * jb.ldT + r;
            jb.Th[idx] = h; jb.Tl[idx] = l;
        }
    }
}

// ================= operator split (8 floats/thread) =================
struct SJob { const float* src; __nv_bfloat16 *dh, *dl; int n8, blkStart; };
struct SParams { SJob j[8]; int n; };

__global__ void splitb_kernel(SParams P)
{
    int b = blockIdx.x;
    int ji = 0;
#pragma unroll 1
    while (ji + 1 < P.n && b >= P.j[ji + 1].blkStart) ji++;
    const SJob jb = P.j[ji];
    int i = (b - jb.blkStart) * 256 + threadIdx.x;
    if (i >= jb.n8) return;
    float4 v0 = ((const float4*)jb.src)[i * 2];
    float4 v1 = ((const float4*)jb.src)[i * 2 + 1];
    __nv_bfloat162 h[4], l[4];
    h[0] = __floats2bfloat162_rn(v0.x, v0.y);
    h[1] = __floats2bfloat162_rn(v0.z, v0.w);
    h[2] = __floats2bfloat162_rn(v1.x, v1.y);
    h[3] = __floats2bfloat162_rn(v1.z, v1.w);
    l[0] = __floats2bfloat162_rn(v0.x - __bfloat162float(h[0].x), v0.y - __bfloat162float(h[0].y));
    l[1] = __floats2bfloat162_rn(v0.z - __bfloat162float(h[1].x), v0.w - __bfloat162float(h[1].y));
    l[2] = __floats2bfloat162_rn(v1.x - __bfloat162float(h[2].x), v1.y - __bfloat162float(h[2].y));
    l[3] = __floats2bfloat162_rn(v1.z - __bfloat162float(h[3].x), v1.w - __bfloat162float(h[3].y));
    ((uint4*)jb.dh)[i] = *(uint4*)h;
    ((uint4*)jb.dl)[i] = *(uint4*)l;
}

// ================= transpose-split (B1^T only) =================
__global__ void tsplit1_kernel(const float* __restrict__ src,
                               __nv_bfloat16* __restrict__ dh, __nv_bfloat16* __restrict__ dl,
                               int lds, int rows, int cols, int tilesR)
{
    __shared__ float tile[32][33];
    int rel = blockIdx.x;
    int k0 = (rel % tilesR) * 32, n0 = (rel / tilesR) * 32;
    int tx = threadIdx.x, ty = threadIdx.y;
    for (int i = ty; i < 32; i += 8) {
        int k = k0 + i, n = n0 + tx;
        tile[i][tx] = (k < rows && n < cols) ? src[(size_t)k * lds + n] : 0.f;
    }
    __syncthreads();
    for (int i = ty; i < 32; i += 8) {
        int n = n0 + i, k = k0 + tx;
        if (n < cols && k < rows) {
            float v = tile[tx][i];
            __nv_bfloat16 h = __float2bfloat16(v);
            dh[(size_t)n * rows + k] = h;
            dl[(size_t)n * rows + k] = __float2bfloat16(v - __bfloat162float(h));
        }
    }
}

// ================= hconv (layer-0 bases) =================
struct HJob {
    const float* src;
    __nv_bfloat16 *Rh, *Rl, *R2h, *R2l;
    __nv_bfloat16 *Th, *Tl, *T2h, *T2l;
    int rows, ldR, tileStart, tilesR;
};
struct HParams { HJob j[3]; int n; };

__global__ void hconv_kernel(HParams P)
{
    __shared__ float tile[32][33];
    int b = blockIdx.x;
    int ji = 0;
#pragma unroll 1
    while (ji + 1 < P.n && b >= P.j[ji + 1].tileStart) ji++;
    const HJob jb = P.j[ji];
    int rel = b - jb.tileStart;
    int r0 = (rel % jb.tilesR) * 32, c0 = (rel / jb.tilesR) * 32;
    int tx = threadIdx.x, ty = threadIdx.y;
    for (int i = ty; i < 32; i += 8) {
        int r = r0 + i, c = c0 + tx;
        float v = (r < jb.rows) ? jb.src[(size_t)r * CC + c] : 0.f;
        tile[i][tx] = v;
        if (r < jb.rows && jb.Rh) {
            __nv_bfloat16 h = __float2bfloat16(v);
            __nv_bfloat16 l = __float2bfloat16(v - __bfloat162float(h));
            jb.Rh[(size_t)r * jb.ldR + c] = h;
            jb.Rl[(size_t)r * jb.ldR + c] = l;
            if (jb.R2h) { jb.R2h[(size_t)r * jb.ldR + c] = h; jb.R2l[(size_t)r * jb.ldR + c] = l; }
        }
    }
    __syncthreads();
    if (!jb.Th) return;
    for (int i = ty; i < 32; i += 8) {
        int c = c0 + i, r = r0 + tx;
        if (r < jb.rows) {
            float v = tile[tx][i];
            __nv_bfloat16 h = __float2bfloat16(v);
            __nv_bfloat16 l = __float2bfloat16(v - __bfloat162float(h));
            size_t idx = (size_t)c * jb.rows + r;
            jb.Th[idx] = h; jb.Tl[idx] = l;
            if (jb.T2h) { jb.T2h[idx] = h; jb.T2l[idx] = l; }
        }
    }
}

// ================= small kernels =================
struct LJob { const float *x, *W, *b; float* y; int rows, rowStart; };
struct LParams { LJob j[3]; int n; };

__global__ void linb_kernel(LParams P)
{
    __shared__ float xs[CC];
    int b = blockIdx.x;
    int ji = 0;
#pragma unroll 1
    while (ji + 1 < P.n && b >= P.j[ji + 1].rowStart) ji++;
    const LJob jb = P.j[ji];
    int n = b - jb.rowStart, o = threadIdx.x;
    xs[o] = jb.x[(size_t)n * CC + o];
    __syncthreads();
    float acc = jb.b[o];
    const float* wr = &jb.W[(size_t)o * CC];
#pragma unroll 8
    for (int i = 0; i < CC; i++) acc += xs[i] * wr[i];
    jb.y[(size_t)n * CC + o] = acc;
}

__global__ void build_wt_kernel(const float* __restrict__ w,
                                __nv_bfloat16* __restrict__ dh, __nv_bfloat16* __restrict__ dl,
                                int which, int korig, int S)
{
    int bi = blockIdx.x;
    int s = bi >> 7, o = bi & 127;
    int i = threadIdx.x;
    int k = c_maps[which][s];
    float v = (k >= 0) ? w[((size_t)i * CC + o) * korig + k] : 0.f;
    __nv_bfloat16 h = __float2bfloat16(v);
    size_t idx = (size_t)o * (S * CC) + s * CC + i;
    dh[idx] = h;
    dl[idx] = __float2bfloat16(v - __bfloat162float(h));
}

__global__ void head_kernel(const float* __restrict__ h0, const float* __restrict__ ow,
                            const float* __restrict__ ob, float* __restrict__ out, int total)
{
    int idx = blockIdx.x * blockDim.x + threadIdx.x;
    if (idx >= total) return;
    int n = idx >> 1, c = idx & 1;
    float acc = ob[c];
    const float* hr = &h0[(size_t)n * CC];
    const float* wr = &ow[(size_t)c * CC];
#pragma unroll 8
    for (int i = 0; i < CC; i++) acc += hr[i] * wr[i];
    out[idx] = 1.f / (1.f + expf(-acc));
}

// ================= host-side batch builders =================
struct MMBatch { MMParams p; int tiles; };
static void mmAdd(MMBatch& b,
                  const __nv_bfloat16* Ah, const __nv_bfloat16* Al, int lda,
                  const __nv_bfloat16* Bh, const __nv_bfloat16* Bl, int ldb,
                  int M, int N, int K,
                  float* Cf, int ldc,
                  __nv_bfloat16* Rh, __nv_bfloat16* Rl, int ldR,
                  __nv_bfloat16* Th, __nv_bfloat16* Tl, int ldT)
{
    MMJob& j = b.p.j[b.p.n++];
    j.Ah = Ah; j.Al = Al; j.Bh = Bh; j.Bl = Bl;
    j.Cf = Cf; j.Rh = Rh; j.Rl = Rl; j.Th = Th; j.Tl = Tl;
    j.M = M; j.K = K; j.lda = lda; j.ldb = ldb; j.ldc = ldc; j.ldR = ldR; j.ldT = ldT;
    j.tileStart = b.tiles; j.tilesX = (M + 127) / 128;
    b.tiles += j.tilesX * (N / 128);
}
// split-K: nsp jobs writing fp32 partials [M,N] each to part + s*M*N
static void mmAddSplit(MMBatch& b,
                       const __nv_bfloat16* Ah, const __nv_bfloat16* Al, int lda,
                       const __nv_bfloat16* Bh, const __nv_bfloat16* Bl, int ldb,
                       int M, int N, int K, int nsp, float* part)
{
    int chunk = (((K + nsp - 1) / nsp) + 7) & ~7;
    for (int s = 0; s < nsp; s++) {
        int k0 = s * chunk;
        int kl = (K - k0 < chunk) ? (K - k0) : chunk;
        mmAdd(b, Ah + k0, Al + k0, lda, Bh + k0, Bl + k0, ldb, M, N, kl,
              part + (size_t)s * M * N, N,
              nullptr, nullptr, 0, nullptr, nullptr, 0);
    }
}
static void mmRun(MMBatch& b)
{
    if (b.p.n) mmb_kernel<<<b.tiles, 256, MM_SMEM>>>(b.p);
    b.p.n = 0; b.tiles = 0;
}

struct RBatch { RParams p; int tiles; };
static void rAdd(RBatch& b, const float* base, int nP, int M, int N,
                 __nv_bfloat16* Rh, __nv_bfloat16* Rl, int ldR,
                 __nv_bfloat16* Th, __nv_bfloat16* Tl, int ldT)
{
    RJob& j = b.p.j[b.p.n++];
    j.base = base; j.nP = nP; j.pStride = M * N; j.M = M; j.N = N;
    j.Rh = Rh; j.Rl = Rl; j.ldR = ldR; j.Th = Th; j.Tl = Tl; j.ldT = ldT;
    j.tileStart = b.tiles; j.tilesR = (M + 31) / 32;
    b.tiles += j.tilesR * (N / 32);
}
static void rRun(RBatch& b)
{
    if (b.p.n) rcvt_kernel<<<b.tiles, dim3(32, 8)>>>(b.p);
    b.p.n = 0; b.tiles = 0;
}

#define SYM(v, g) { void* p_; cudaGetSymbolAddress(&p_, g); v = (decltype(v))p_; }

extern "C" void kernel_launch(void* const* d_in, const int* in_sizes, int n_in,
                              void* d_out, int out_size)
{
    (void)in_sizes; (void)n_in; (void)out_size;
    const float* x0    = (const float*)d_in[0];
    const float* x1    = (const float*)d_in[1];
    const float* x2    = (const float*)d_in[2];
    const float* L0    = (const float*)d_in[3];
    const float* L1d   = (const float*)d_in[4];
    const float* L1u   = (const float*)d_in[5];
    const float* B1    = (const float*)d_in[8];
    const float* B2    = (const float*)d_in[9];
    const float* in_w0 = (const float*)d_in[10];
    const float* in_b0 = (const float*)d_in[11];
    const float* in_w1 = (const float*)d_in[12];
    const float* in_b1 = (const float*)d_in[13];
    const float* in_w2 = (const float*)d_in[14];
    const float* in_b2 = (const float*)d_in[15];
    const float* l0_w0 = (const float*)d_in[16];
    const float* l0_w1 = (const float*)d_in[17];
    const float* l1_w0 = (const float*)d_in[19];
    const float* out_w = (const float*)d_in[22];
    const float* out_b = (const float*)d_in[23];
    float* out = (float*)d_out;

    cudaFuncSetAttribute(mmb_kernel, cudaFuncAttributeMaxDynamicSharedMemorySize, MM_SMEM);

    float *h0, *h1, *h2, *pool;
    SYM(h0, g_h0); SYM(h1, g_h1); SYM(h2, g_h2); SYM(pool, g_part);
    __nv_bfloat16 *L0h, *L0l, *L1dh, *L1dl, *L1uh, *L1ul;
    __nv_bfloat16 *B1h, *B1l, *B1th, *B1tl, *B2h, *B2l;
    SYM(L0h, g_L0h); SYM(L0l, g_L0l);
    SYM(L1dh, g_L1dh); SYM(L1dl, g_L1dl); SYM(L1uh, g_L1uh); SYM(L1ul, g_L1ul);
    SYM(B1h, g_B1h); SYM(B1l, g_B1l); SYM(B1th, g_B1th); SYM(B1tl, g_B1tl);
    SYM(B2h, g_B2h); SYM(B2l, g_B2l);
    __nv_bfloat16 *X0qh, *X0ql, *X1qh, *X1ql;
    SYM(X0qh, g_X0qh); SYM(X0ql, g_X0ql); SYM(X1qh, g_X1qh); SYM(X1ql, g_X1ql);
    __nv_bfloat16 *bt0h, *bt0l, *bt1ah, *bt1al, *bt1bh, *bt1bl, *bt2h, *bt2l;
    SYM(bt0h, g_bt0h); SYM(bt0l, g_bt0l);
    SYM(bt1ah, g_bt1ah); SYM(bt1al, g_bt1al);
    SYM(bt1bh, g_bt1bh); SYM(bt1bl, g_bt1bl);
    SYM(bt2h, g_bt2h); SYM(bt2l, g_bt2l);
    __nv_bfloat16 *bb0h, *bb0l, *bb1ah, *bb1al, *bb1bh, *bb1bl;
    SYM(bb0h, g_bb0h); SYM(bb0l, g_bb0l);
    SYM(bb1ah, g_bb1ah); SYM(bb1al, g_bb1al);
    SYM(bb1bh, g_bb1bh); SYM(bb1bl, g_bb1bl);
    __nv_bfloat16 *W0h, *W0l, *W1h, *W1l;
    SYM(W0h, g_W0h); SYM(W0l, g_W0l); SYM(W1h, g_W1h); SYM(W1l, g_W1l);

    const int LD0 = 6 * CC, LD1 = 12 * CC;

    MMBatch mb = {}; RBatch rb = {};

    // ---- operator splits ----
    {
        SParams sp = {};
        int blks = 0;
        auto add = [&](const float* s, __nv_bfloat16* dh, __nv_bfloat16* dl, size_t cnt) {
            SJob& j = sp.j[sp.n++];
            j.src = s; j.dh = dh; j.dl = dl; j.n8 = (int)(cnt / 8); j.blkStart = blks;
            blks += (j.n8 + 255) / 256;
        };
        add(L1d, L1dh, L1dl, (size_t)Nn1 * Nn1);
        add(L1u, L1uh, L1ul, (size_t)Nn1 * Nn1);
        add(B1,  B1h,  B1l,  (size_t)Nn0 * Nn1);
        add(B2,  B2h,  B2l,  (size_t)Nn1 * Nn2);
        add(L0,  L0h,  L0l,  (size_t)Nn0 * Nn0);
        splitb_kernel<<<blks, 256>>>(sp);
    }
    tsplit1_kernel<<<((Nn0 + 31) / 32) * ((Nn1 + 31) / 32), dim3(32, 8)>>>(
        B1, B1th, B1tl, Nn1, Nn0, Nn1, (Nn0 + 31) / 32);

    // ---- input linears ----
    {
        LParams lp = {};
        lp.j[0] = { x0, in_w0, in_b0, h0, Nn0, 0 };
        lp.j[1] = { x1, in_w1, in_b1, h1, Nn1, Nn0 };
        lp.j[2] = { x2, in_w2, in_b2, h2, Nn2, Nn0 + Nn1 };
        lp.n = 3;
        linb_kernel<<<Nn0 + Nn1 + Nn2, CC>>>(lp);
    }

    // ============ LAYER 0 ============
    build_wt_kernel<<<6 * CC,  CC>>>(l0_w0, W0h, W0l, 0, 6,  6);
    build_wt_kernel<<<12 * CC, CC>>>(l0_w1, W1h, W1l, 1, 11, 12);

    // hconv: bases + transposed h
    {
        HParams hp = {};
        int tiles = 0;
        int tr0 = (Nn0 + 31) / 32, tr1 = (Nn1 + 31) / 32, tr2 = (Nn2 + 31) / 32;
        hp.j[0] = { h0, X0qh, X0ql, nullptr, nullptr, bt0h, bt0l, nullptr, nullptr,
                    Nn0, LD0, tiles, tr0 };
        tiles += tr0 * 4;
        hp.j[1] = { h1, X1qh, X1ql, X1qh + 256, X1ql + 256, bt1ah, bt1al, bt1bh, bt1bl,
                    Nn1, LD1, tiles, tr1 };
        tiles += tr1 * 4;
        hp.j[2] = { h2, nullptr, nullptr, nullptr, nullptr, bt2h, bt2l, nullptr, nullptr,
                    Nn2, 0, tiles, tr2 };
        tiles += tr2 * 4;
        hp.n = 3;
        hconv_kernel<<<tiles, dim3(32, 8)>>>(hp);
    }

    // projections (split-K): p=B1@h1t(4), r=B2@h2t(3), q=B1t@h0t(2)
    float* pp = pool;
    float* pr = pp + (size_t)4 * Nn0 * 128;
    float* pq = pr + (size_t)3 * Nn1 * 128;
    mmAddSplit(mb, B1h,  B1l,  Nn1, bt1ah, bt1al, Nn1, Nn0, 128, Nn1, 4, pp);
    mmAddSplit(mb, B2h,  B2l,  Nn2, bt2h,  bt2l,  Nn2, Nn1, 128, Nn2, 3, pr);
    mmAddSplit(mb, B1th, B1tl, Nn0, bt0h,  bt0l,  Nn0, Nn1, 128, Nn0, 2, pq);
    mmRun(mb);
    rAdd(rb, pp, 4, Nn0, 128, X0qh + 128, X0ql + 128, LD0, bt0h + 128 * Nn0, bt0l + 128 * Nn0, Nn0);
    rAdd(rb, pr, 3, Nn1, 128, X1qh + 384, X1ql + 384, LD1, bt1bh + 128 * Nn1, bt1bl + 128 * Nn1, Nn1);
    rAdd(rb, pq, 2, Nn1, 128, X1qh + 128, X1ql + 128, LD1, bt1ah + 128 * Nn1, bt1al + 128 * Nn1, Nn1);
    rRun(rb);

    // first hops (split-K 4/4/2)
    float* pd = pool;
    float* pu = pd + (size_t)4 * Nn1 * 256;
    float* p0 = pu + (size_t)4 * Nn1 * 256;
    mmAddSplit(mb, L1dh, L1dl, Nn1, bt1ah, bt1al, Nn1, Nn1, 256, Nn1, 4, pd);
    mmAddSplit(mb, L1uh, L1ul, Nn1, bt1bh, bt1bl, Nn1, Nn1, 256, Nn1, 4, pu);
    mmAddSplit(mb, L0h,  L0l,  Nn0, bt0h,  bt0l,  Nn0, Nn0, 256, Nn0, 2, p0);
    mmRun(mb);
    rAdd(rb, pd, 4, Nn1, 256, X1qh + 512, X1ql + 512, LD1, bb1ah, bb1al, Nn1);
    rAdd(rb, pu, 4, Nn1, 256, X1qh + 768, X1ql + 768, LD1, bb1bh, bb1bl, Nn1);
    rAdd(rb, p0, 2, Nn0, 256, X0qh + 256, X0ql + 256, LD0, bb0h, bb0l, Nn0);
    rRun(rb);

    // second hops (split-K)
    mmAddSplit(mb, L1dh, L1dl, Nn1, bb1ah, bb1al, Nn1, Nn1, 256, Nn1, 4, pd);
    mmAddSplit(mb, L1uh, L1ul, Nn1, bb1bh, bb1bl, Nn1, Nn1, 256, Nn1, 4, pu);
    mmAddSplit(mb, L0h,  L0l,  Nn0, bb0h,  bb0l,  Nn0, Nn0, 256, Nn0, 2, p0);
    mmRun(mb);
    rAdd(rb, pd, 4, Nn1, 256, X1qh + 1024, X1ql + 1024, LD1, nullptr, nullptr, 0);
    rAdd(rb, pu, 4, Nn1, 256, X1qh + 1280, X1ql + 1280, LD1, nullptr, nullptr, 0);
    rAdd(rb, p0, 2, Nn0, 256, X0qh + 512,  X0ql + 512,  LD0, nullptr, nullptr, 0);
    rRun(rb);

    // einsums: h1' (split 2 -> rcvt to bt1a transposed), h0' (direct epilogue)
    float* pe = pool;
    mmAddSplit(mb, X1qh, X1ql, LD1, W1h, W1l, LD1, Nn1, 128, LD1, 2, pe);
    mmAdd(mb, X0qh, X0ql, LD0, W0h, W0l, LD0, Nn0, 128, LD0,
          nullptr, 0, X0qh, X0ql, LD0, bt0h, bt0l, Nn0);
    mmRun(mb);
    rAdd(rb, pe, 2, Nn1, 128, nullptr, nullptr, 0, bt1ah, bt1al, Nn1);
    rRun(rb);

    // ============ LAYER 1 (h0'' only) ============
    build_wt_kernel<<<6 * CC, CC>>>(l1_w0, W0h, W0l, 0, 6, 6);

    // p = B1 @ h1' (split 6)
    mmAddSplit(mb, B1h, B1l, Nn1, bt1ah, bt1al, Nn1, Nn0, 128, Nn1, 6, pool);
    mmRun(mb);
    rAdd(rb, pool, 6, Nn0, 128, X0qh + 128, X0ql + 128, LD0, bt0h + 128 * Nn0, bt0l + 128 * Nn0, Nn0);
    rRun(rb);
    // L0 hop1 (split 2)
    mmAddSplit(mb, L0h, L0l, Nn0, bt0h, bt0l, Nn0, Nn0, 256, Nn0, 2, pool);
    mmRun(mb);
    rAdd(rb, pool, 2, Nn0, 256, X0qh + 256, X0ql + 256, LD0, bb0h, bb0l, Nn0);
    rRun(rb);
    // L0 hop2 (split 2)
    mmAddSplit(mb, L0h, L0l, Nn0, bb0h, bb0l, Nn0, Nn0, 256, Nn0, 2, pool);
    mmRun(mb);
    rAdd(rb, pool, 2, Nn0, 256, X0qh + 512, X0ql + 512, LD0, nullptr, nullptr, 0);
    rRun(rb);
    // einsum -> h0'' fp32
    mmAdd(mb, X0qh, X0ql, LD0, W0h, W0l, LD0, Nn0, 128, LD0,
          h0, CC, nullptr, nullptr, 0, nullptr, nullptr, 0);
    mmRun(mb);

    head_kernel<<<(Nn0 * 2 + 255) / 256, 256>>>(h0, out_w, out_b, out, Nn0 * 2);
}

// round 12
// speedup vs baseline: 5.1189x; 1.2424x over previous
#include <cuda_runtime.h>
#include <cuda_bf16.h>
#include <math.h>
#include <stdint.h>

#define Nn0 2000
#define Nn1 6000
#define Nn2 4000
#define CC  128

// ================= static scratch (no allocation) =================
__device__ float g_h0[Nn0 * CC];
__device__ float g_h1[Nn1 * CC];
__device__ float g_h2[Nn2 * CC];

__device__ float g_part[16 * 1024 * 1024];   // fp32 partial pool

// operators bf16 hi/lo
__device__ __nv_bfloat16 g_L0h[Nn0 * Nn0],  g_L0l[Nn0 * Nn0];
__device__ __nv_bfloat16 g_L1dh[Nn1 * Nn1], g_L1dl[Nn1 * Nn1];
__device__ __nv_bfloat16 g_L1uh[Nn1 * Nn1], g_L1ul[Nn1 * Nn1];
__device__ __nv_bfloat16 g_B1h[Nn0 * Nn1],  g_B1l[Nn0 * Nn1];
__device__ __nv_bfloat16 g_B1th[Nn1 * Nn0], g_B1tl[Nn1 * Nn0];
__device__ __nv_bfloat16 g_B2h[Nn1 * Nn2],  g_B2l[Nn1 * Nn2];

// row-major bf16 A operands: X0 = [h0|p] (ld 256), X1 = [h1|q|h1|r] (ld 512)
__device__ __nv_bfloat16 g_X0qh[Nn0 * 256], g_X0ql[Nn0 * 256];
__device__ __nv_bfloat16 g_X1qh[Nn1 * 512], g_X1ql[Nn1 * 512];

// transposed bf16 buffers
__device__ __nv_bfloat16 g_bt0h[128 * Nn0],  g_bt0l[128 * Nn0];   // h0^T
__device__ __nv_bfloat16 g_bt1ah[128 * Nn1], g_bt1al[128 * Nn1];  // h1^T / h1'^T
__device__ __nv_bfloat16 g_bt2h[128 * Nn2],  g_bt2l[128 * Nn2];   // h2^T
__device__ __nv_bfloat16 g_bb0h[128 * Nn0],  g_bb0l[128 * Nn0];   // node chain T
__device__ __nv_bfloat16 g_bb1ah[128 * Nn1], g_bb1al[128 * Nn1];  // D chain T
__device__ __nv_bfloat16 g_bb1bh[128 * Nn1], g_bb1bl[128 * Nn1];  // U chain T

// combined Horner weights, transposed [128, S*128] bf16 hi/lo
#define WSZ (2 * 128 * 128)
__device__ __nv_bfloat16 g_Wn0h[WSZ], g_Wn0l[WSZ];
__device__ __nv_bfloat16 g_Wn1h[WSZ], g_Wn1l[WSZ];
__device__ __nv_bfloat16 g_Wn2h[WSZ], g_Wn2l[WSZ];
__device__ __nv_bfloat16 g_We0h[WSZ], g_We0l[WSZ];
__device__ __nv_bfloat16 g_WeD1h[WSZ], g_WeD1l[WSZ];
__device__ __nv_bfloat16 g_WeD2h[WSZ], g_WeD2l[WSZ];
__device__ __nv_bfloat16 g_WeU1h[WSZ], g_WeU1l[WSZ];
__device__ __nv_bfloat16 g_WeU2h[WSZ], g_WeU2l[WSZ];
__device__ __nv_bfloat16 g_Werh[128 * 128], g_Werl[128 * 128];

// ================= PTX helpers =================
__device__ __forceinline__ uint32_t smem_u32(const void* p) {
    uint32_t a;
    asm("{ .reg .u64 t; cvta.to.shared.u64 t, %1; cvt.u32.u64 %0, t; }" : "=r"(a) : "l"(p));
    return a;
}
__device__ __forceinline__ void ldsm_x4(uint32_t* r, uint32_t a) {
    asm volatile("ldmatrix.sync.aligned.m8n8.x4.shared.b16 {%0,%1,%2,%3}, [%4];"
                 : "=r"(r[0]), "=r"(r[1]), "=r"(r[2]), "=r"(r[3]) : "r"(a));
}
__device__ __forceinline__ void mma_bf16(float* c, const uint32_t* a, const uint32_t* b) {
    asm volatile(
        "mma.sync.aligned.m16n8k16.row.col.f32.bf16.bf16.f32 "
        "{%0,%1,%2,%3}, {%4,%5,%6,%7}, {%8,%9}, {%0,%1,%2,%3};"
        : "+f"(c[0]), "+f"(c[1]), "+f"(c[2]), "+f"(c[3])
        : "r"(a[0]), "r"(a[1]), "r"(a[2]), "r"(a[3]), "r"(b[0]), "r"(b[1]));
}
__device__ __forceinline__ void cp_async16(uint32_t dst, const void* src, int sz) {
    asm volatile("cp.async.cg.shared.global [%0], [%1], 16, %2;"
                 :: "r"(dst), "l"(src), "r"(sz));
}
__device__ __forceinline__ uint32_t sw_addr(uint32_t tile_base, int r, int chunk) {
    return tile_base + (uint32_t)(r * 64) + (uint32_t)((chunk ^ ((r >> 1) & 3)) << 4);
}

// ================= batched bf16x3 HMMA GEMM =================
#define MM_SMEM (3 * 4 * 8192)
#define MAXJOB 14

struct MMJob {
    const __nv_bfloat16 *Ah, *Al, *Bh, *Bl;
    float* Cf;
    int M, K, lda, ldb, ldc, tileStart, tilesX;
};
struct MMParams { MMJob j[MAXJOB]; int n; };

__global__ __launch_bounds__(256, 2)
void mmb_kernel(MMParams P)
{
    extern __shared__ __align__(128) char smem[];
    const uint32_t sbase = smem_u32(smem);
    const int tid = threadIdx.x, lane = tid & 31, wid = tid >> 5;
    const int wm = wid & 1, wn = wid >> 1;

    int bt = blockIdx.x;
    int ji = 0;
#pragma unroll 1
    while (ji + 1 < P.n && bt >= P.j[ji + 1].tileStart) ji++;
    const MMJob jb = P.j[ji];
    const int rel = bt - jb.tileStart;
    const int m0 = (rel % jb.tilesX) * 128;
    const int n0 = (rel / jb.tilesX) * 128;
    const int M = jb.M, K = jb.K, lda = jb.lda, ldb = jb.ldb;
    const int mrows = (M - m0 < 128) ? (M - m0) : 128;
    const __nv_bfloat16* Ah = jb.Ah + (size_t)m0 * lda;
    const __nv_bfloat16* Al = jb.Al + (size_t)m0 * lda;
    const __nv_bfloat16* Bh = jb.Bh + (size_t)n0 * ldb;
    const __nv_bfloat16* Bl = jb.Bl + (size_t)n0 * ldb;
    const int nk = (K + 31) >> 5;

    float acc[4][4][4];
#pragma unroll
    for (int i = 0; i < 4; i++)
#pragma unroll
        for (int j = 0; j < 4; j++)
#pragma unroll
            for (int v = 0; v < 4; v++) acc[i][j][v] = 0.f;

    auto load_stage = [&](int t) {
        const uint32_t sb = sbase + (uint32_t)(t % 3) * 32768;
        const int k0 = t << 5;
#pragma unroll
        for (int i = 0; i < 8; i++) {
            int idx = tid + i * 256;
            int tile = idx >> 9;
            int rem  = idx & 511;
            int r = rem >> 2, c = rem & 3;
            const __nv_bfloat16* gp;
            int ok;
            if (tile < 2) {
                gp = (tile == 0 ? Ah : Al) + (size_t)r * lda + k0 + c * 8;
                ok = (r < mrows) && (k0 + c * 8 < K);
            } else {
                gp = (tile == 2 ? Bh : Bl) + (size_t)r * ldb + k0 + c * 8;
                ok = (k0 + c * 8 < K);
            }
            cp_async16(sb + (uint32_t)tile * 8192 + sw_addr(0, r, c), gp, ok ? 16 : 0);
        }
    };

#pragma unroll
    for (int s = 0; s < 2; s++) {
        if (s < nk) load_stage(s);
        asm volatile("cp.async.commit_group;" ::: "memory");
    }

    const int frag_r = lane & 15;
    const int frag_c = lane >> 4;

    for (int t = 0; t < nk; t++) {
        asm volatile("cp.async.wait_group 1;" ::: "memory");
        __syncthreads();
        const uint32_t sb = sbase + (uint32_t)(t % 3) * 32768;
        const uint32_t tAh = sb, tAl = sb + 8192, tBh = sb + 16384, tBl = sb + 24576;

#pragma unroll
        for (int ks = 0; ks < 2; ks++) {
            const int ch = ks * 2 + frag_c;
            uint32_t bh[4][2], bl[4][2];
#pragma unroll
            for (int j = 0; j < 2; j++) {
                int r = wn * 32 + j * 16 + frag_r;
                uint32_t rr[4];
                ldsm_x4(rr, sw_addr(tBh, r, ch));
                bh[2 * j][0] = rr[0]; bh[2 * j][1] = rr[2];
                bh[2 * j + 1][0] = rr[1]; bh[2 * j + 1][1] = rr[3];
                ldsm_x4(rr, sw_addr(tBl, r, ch));
                bl[2 * j][0] = rr[0]; bl[2 * j][1] = rr[2];
                bl[2 * j + 1][0] = rr[1]; bl[2 * j + 1][1] = rr[3];
            }
#pragma unroll
            for (int mt = 0; mt < 4; mt++) {
                int r = wm * 64 + mt * 16 + frag_r;
                uint32_t ah[4], al[4];
                ldsm_x4(ah, sw_addr(tAh, r, ch));
                ldsm_x4(al, sw_addr(tAl, r, ch));
#pragma unroll
                for (int nt = 0; nt < 4; nt++) mma_bf16(acc[mt][nt], ah, bh[nt]);
#pragma unroll
                for (int nt = 0; nt < 4; nt++) mma_bf16(acc[mt][nt], ah, bl[nt]);
#pragma unroll
                for (int nt = 0; nt < 4; nt++) mma_bf16(acc[mt][nt], al, bh[nt]);
            }
        }
        if (t + 2 < nk) load_stage(t + 2);
        asm volatile("cp.async.commit_group;" ::: "memory");
    }

    const int er = lane >> 2, ec = (lane & 3) * 2;
#pragma unroll
    for (int mt = 0; mt < 4; mt++) {
        int r0 = m0 + wm * 64 + mt * 16 + er;
        int r1 = r0 + 8;
#pragma unroll
        for (int nt = 0; nt < 4; nt++) {
            int col = n0 + wn * 32 + nt * 8 + ec;
            if (r0 < M) *(float2*)&jb.Cf[(size_t)r0 * jb.ldc + col] =
                make_float2(acc[mt][nt][0], acc[mt][nt][1]);
            if (r1 < M) *(float2*)&jb.Cf[(size_t)r1 * jb.ldc + col] =
                make_float2(acc[mt][nt][2], acc[mt][nt][3]);
        }
    }
}

// ================= reduce-convert: sum partials -> bf16 row / T / fp32 ======
struct RJob {
    const float* base; int nP, pStride, M, N;
    __nv_bfloat16 *Rh, *Rl; int ldR;
    __nv_bfloat16 *Th, *Tl; int ldT;
    float* Cf; int ldc;
    int tileStart, tilesR;
};
struct RParams { RJob j[4]; int n; };

__global__ void rcvt_kernel(RParams P)
{
    __shared__ float tile[32][33];
    int b = blockIdx.x;
    int ji = 0;
#pragma unroll 1
    while (ji + 1 < P.n && b >= P.j[ji + 1].tileStart) ji++;
    const RJob jb = P.j[ji];
    int rel = b - jb.tileStart;
    int r0 = (rel % jb.tilesR) * 32, c0 = (rel / jb.tilesR) * 32;
    int tx = threadIdx.x, ty = threadIdx.y;
    for (int i = ty; i < 32; i += 8) {
        int r = r0 + i, c = c0 + tx;
        float v = 0.f;
        if (r < jb.M) {
            size_t off = (size_t)r * jb.N + c;
#pragma unroll 1
            for (int s = 0; s < jb.nP; s++) v += jb.base[off + (size_t)s * jb.pStride];
        }
        tile[i][tx] = v;
        if (r < jb.M) {
            if (jb.Cf) jb.Cf[(size_t)r * jb.ldc + c] = v;
            if (jb.Rh) {
                __nv_bfloat16 h = __float2bfloat16(v);
                jb.Rh[(size_t)r * jb.ldR + c] = h;
                jb.Rl[(size_t)r * jb.ldR + c] = __float2bfloat16(v - __bfloat162float(h));
            }
        }
    }
    __syncthreads();
    if (!jb.Th) return;
    for (int i = ty; i < 32; i += 8) {
        int c = c0 + i, r = r0 + tx;
        if (r < jb.M) {
            float v = tile[tx][i];
            __nv_bfloat16 h = __float2bfloat16(v);
            size_t idx = (size_t)c * jb.ldT + r;
            jb.Th[idx] = h;
            jb.Tl[idx] = __float2bfloat16(v - __bfloat162float(h));
        }
    }
}

// ================= operator split =================
struct SJob { const float* src; __nv_bfloat16 *dh, *dl; int n8, blkStart; };
struct SParams { SJob j[8]; int n; };

__global__ void splitb_kernel(SParams P)
{
    int b = blockIdx.x;
    int ji = 0;
#pragma unroll 1
    while (ji + 1 < P.n && b >= P.j[ji + 1].blkStart) ji++;
    const SJob jb = P.j[ji];
    int i = (b - jb.blkStart) * 256 + threadIdx.x;
    if (i >= jb.n8) return;
    float4 v0 = ((const float4*)jb.src)[i * 2];
    float4 v1 = ((const float4*)jb.src)[i * 2 + 1];
    __nv_bfloat162 h[4], l[4];
    h[0] = __floats2bfloat162_rn(v0.x, v0.y);
    h[1] = __floats2bfloat162_rn(v0.z, v0.w);
    h[2] = __floats2bfloat162_rn(v1.x, v1.y);
    h[3] = __floats2bfloat162_rn(v1.z, v1.w);
    l[0] = __floats2bfloat162_rn(v0.x - __bfloat162float(h[0].x), v0.y - __bfloat162float(h[0].y));
    l[1] = __floats2bfloat162_rn(v0.z - __bfloat162float(h[1].x), v0.w - __bfloat162float(h[1].y));
    l[2] = __floats2bfloat162_rn(v1.x - __bfloat162float(h[2].x), v1.y - __bfloat162float(h[2].y));
    l[3] = __floats2bfloat162_rn(v1.z - __bfloat162float(h[3].x), v1.w - __bfloat162float(h[3].y));
    ((uint4*)jb.dh)[i] = *(uint4*)h;
    ((uint4*)jb.dl)[i] = *(uint4*)l;
}

// ================= transpose-split (B1^T) =================
__global__ void tsplit1_kernel(const float* __restrict__ src,
                               __nv_bfloat16* __restrict__ dh, __nv_bfloat16* __restrict__ dl,
                               int lds, int rows, int cols, int tilesR)
{
    __shared__ float tile[32][33];
    int rel = blockIdx.x;
    int k0 = (rel % tilesR) * 32, n0 = (rel / tilesR) * 32;
    int tx = threadIdx.x, ty = threadIdx.y;
    for (int i = ty; i < 32; i += 8) {
        int k = k0 + i, n = n0 + tx;
        tile[i][tx] = (k < rows && n < cols) ? src[(size_t)k * lds + n] : 0.f;
    }
    __syncthreads();
    for (int i = ty; i < 32; i += 8) {
        int n = n0 + i, k = k0 + tx;
        if (n < cols && k < rows) {
            float v = tile[tx][i];
            __nv_bfloat16 h = __float2bfloat16(v);
            dh[(size_t)n * rows + k] = h;
            dl[(size_t)n * rows + k] = __float2bfloat16(v - __bfloat162float(h));
        }
    }
}

// ================= hconv =================
struct HJob {
    const float* src;
    __nv_bfloat16 *Rh, *Rl, *R2h, *R2l;
    __nv_bfloat16 *Th, *Tl;
    int rows, ldR, tileStart, tilesR;
};
struct HParams { HJob j[3]; int n; };

__global__ void hconv_kernel(HParams P)
{
    __shared__ float tile[32][33];
    int b = blockIdx.x;
    int ji = 0;
#pragma unroll 1
    while (ji + 1 < P.n && b >= P.j[ji + 1].tileStart) ji++;
    const HJob jb = P.j[ji];
    int rel = b - jb.tileStart;
    int r0 = (rel % jb.tilesR) * 32, c0 = (rel / jb.tilesR) * 32;
    int tx = threadIdx.x, ty = threadIdx.y;
    for (int i = ty; i < 32; i += 8) {
        int r = r0 + i, c = c0 + tx;
        float v = (r < jb.rows) ? jb.src[(size_t)r * CC + c] : 0.f;
        tile[i][tx] = v;
        if (r < jb.rows && jb.Rh) {
            __nv_bfloat16 h = __float2bfloat16(v);
            __nv_bfloat16 l = __float2bfloat16(v - __bfloat162float(h));
            jb.Rh[(size_t)r * jb.ldR + c] = h;
            jb.Rl[(size_t)r * jb.ldR + c] = l;
            if (jb.R2h) { jb.R2h[(size_t)r * jb.ldR + c] = h; jb.R2l[(size_t)r * jb.ldR + c] = l; }
        }
    }
    __syncthreads();
    if (!jb.Th) return;
    for (int i = ty; i < 32; i += 8) {
        int c = c0 + i, r = r0 + tx;
        if (r < jb.rows) {
            float v = tile[tx][i];
            __nv_bfloat16 h = __float2bfloat16(v);
            size_t idx = (size_t)c * jb.rows + r;
            jb.Th[idx] = h;
            jb.Tl[idx] = __float2bfloat16(v - __bfloat162float(h));
        }
    }
}

// ================= input linear =================
struct LJob { const float *x, *W, *b; float* y; int rows, rowStart; };
struct LParams { LJob j[3]; int n; };

__global__ void linb_kernel(LParams P)
{
    __shared__ float xs[CC];
    int b = blockIdx.x;
    int ji = 0;
#pragma unroll 1
    while (ji + 1 < P.n && b >= P.j[ji + 1].rowStart) ji++;
    const LJob jb = P.j[ji];
    int n = b - jb.rowStart, o = threadIdx.x;
    xs[o] = jb.x[(size_t)n * CC + o];
    __syncthreads();
    float acc = jb.b[o];
    const float* wr = &jb.W[(size_t)o * CC];
#pragma unroll 8
    for (int i = 0; i < CC; i++) acc += xs[i] * wr[i];
    jb.y[(size_t)n * CC + o] = acc;
}

// ================= batched Horner weight builder =================
// Wt[o, s*128+i] = w[i, o, map_s]  (map_s < 0 -> 0)
struct WJob { const float* w; __nv_bfloat16 *dh, *dl; int korig, m0, m1, blkStart; };
struct WParams { WJob j[9]; int n; };

__global__ void wbuild_kernel(WParams P)
{
    int b = blockIdx.x;
    int ji = 0;
#pragma unroll 1
    while (ji + 1 < P.n && b >= P.j[ji + 1].blkStart) ji++;
    const WJob jb = P.j[ji];
    int rel = b - jb.blkStart;
    int s = rel >> 7, o = rel & 127;
    int i = threadIdx.x;
    int S = (jb.m1 >= -1 && jb.m1 != -2) ? 2 : 1;   // m1 == -2 means S=1
    int k = (s == 0) ? jb.m0 : jb.m1;
    float v = (k >= 0) ? jb.w[((size_t)i * CC + o) * jb.korig + k] : 0.f;
    __nv_bfloat16 h = __float2bfloat16(v);
    size_t idx = (size_t)o * (S * 128) + s * 128 + i;
    jb.dh[idx] = h;
    jb.dl[idx] = __float2bfloat16(v - __bfloat162float(h));
}

__global__ void head_kernel(const float* __restrict__ h0, const float* __restrict__ ow,
                            const float* __restrict__ ob, float* __restrict__ out, int total)
{
    int idx = blockIdx.x * blockDim.x + threadIdx.x;
    if (idx >= total) return;
    int n = idx >> 1, c = idx & 1;
    float acc = ob[c];
    const float* hr = &h0[(size_t)n * CC];
    const float* wr = &ow[(size_t)c * CC];
#pragma unroll 8
    for (int i = 0; i < CC; i++) acc += hr[i] * wr[i];
    out[idx] = 1.f / (1.f + expf(-acc));
}

// ================= host-side builders =================
struct MMBatch { MMParams p; int tiles; };
static void mmAdd(MMBatch& b,
                  const __nv_bfloat16* Ah, const __nv_bfloat16* Al, int lda,
                  const __nv_bfloat16* Bh, const __nv_bfloat16* Bl, int ldb,
                  int M, int N, int K, float* Cf, int ldc)
{
    MMJob& j = b.p.j[b.p.n++];
    j.Ah = Ah; j.Al = Al; j.Bh = Bh; j.Bl = Bl; j.Cf = Cf;
    j.M = M; j.K = K; j.lda = lda; j.ldb = ldb; j.ldc = ldc;
    j.tileStart = b.tiles; j.tilesX = (M + 127) / 128;
    b.tiles += j.tilesX * (N / 128);
}
static void mmAddSplit(MMBatch& b,
                       const __nv_bfloat16* Ah, const __nv_bfloat16* Al, int lda,
                       const __nv_bfloat16* Bh, const __nv_bfloat16* Bl, int ldb,
                       int M, int N, int K, int nsp, float* part)
{
    int chunk = (((K + nsp - 1) / nsp) + 7) & ~7;
    for (int s = 0; s < nsp; s++) {
        int k0 = s * chunk;
        int kl = (K - k0 < chunk) ? (K - k0) : chunk;
        mmAdd(b, Ah + k0, Al + k0, lda, Bh + k0, Bl + k0, ldb, M, N, kl,
              part + (size_t)s * M * N, N);
    }
}
static void mmRun(MMBatch& b)
{
    if (b.p.n) mmb_kernel<<<b.tiles, 256, MM_SMEM>>>(b.p);
    b.p.n = 0; b.tiles = 0;
}

struct RBatch { RParams p; int tiles; };
static void rAdd(RBatch& b, const float* base, int nP, int M, int N,
                 __nv_bfloat16* Rh, __nv_bfloat16* Rl, int ldR,
                 __nv_bfloat16* Th, __nv_bfloat16* Tl, int ldT,
                 float* Cf = nullptr, int ldc = 0)
{
    RJob& j = b.p.j[b.p.n++];
    j.base = base; j.nP = nP; j.pStride = M * N; j.M = M; j.N = N;
    j.Rh = Rh; j.Rl = Rl; j.ldR = ldR; j.Th = Th; j.Tl = Tl; j.ldT = ldT;
    j.Cf = Cf; j.ldc = ldc;
    j.tileStart = b.tiles; j.tilesR = (M + 31) / 32;
    b.tiles += j.tilesR * (N / 32);
}
static void rRun(RBatch& b)
{
    if (b.p.n) rcvt_kernel<<<b.tiles, dim3(32, 8)>>>(b.p);
    b.p.n = 0; b.tiles = 0;
}

#define SYM(v, g) { void* p_; cudaGetSymbolAddress(&p_, g); v = (decltype(v))p_; }

extern "C" void kernel_launch(void* const* d_in, const int* in_sizes, int n_in,
                              void* d_out, int out_size)
{
    (void)in_sizes; (void)n_in; (void)out_size;
    const float* x0    = (const float*)d_in[0];
    const float* x1    = (const float*)d_in[1];
    const float* x2    = (const float*)d_in[2];
    const float* L0    = (const float*)d_in[3];
    const float* L1d   = (const float*)d_in[4];
    const float* L1u   = (const float*)d_in[5];
    const float* B1    = (const float*)d_in[8];
    const float* B2    = (const float*)d_in[9];
    const float* in_w0 = (const float*)d_in[10];
    const float* in_b0 = (const float*)d_in[11];
    const float* in_w1 = (const float*)d_in[12];
    const float* in_b1 = (const float*)d_in[13];
    const float* in_w2 = (const float*)d_in[14];
    const float* in_b2 = (const float*)d_in[15];
    const float* l0_w0 = (const float*)d_in[16];
    const float* l0_w1 = (const float*)d_in[17];
    const float* l1_w0 = (const float*)d_in[19];
    const float* out_w = (const float*)d_in[22];
    const float* out_b = (const float*)d_in[23];
    float* out = (float*)d_out;

    cudaFuncSetAttribute(mmb_kernel, cudaFuncAttributeMaxDynamicSharedMemorySize, MM_SMEM);

    float *h0, *h1, *h2, *pool;
    SYM(h0, g_h0); SYM(h1, g_h1); SYM(h2, g_h2); SYM(pool, g_part);
    __nv_bfloat16 *L0h, *L0l, *L1dh, *L1dl, *L1uh, *L1ul;
    __nv_bfloat16 *B1h, *B1l, *B1th, *B1tl, *B2h, *B2l;
    SYM(L0h, g_L0h); SYM(L0l, g_L0l);
    SYM(L1dh, g_L1dh); SYM(L1dl, g_L1dl); SYM(L1uh, g_L1uh); SYM(L1ul, g_L1ul);
    SYM(B1h, g_B1h); SYM(B1l, g_B1l); SYM(B1th, g_B1th); SYM(B1tl, g_B1tl);
    SYM(B2h, g_B2h); SYM(B2l, g_B2l);
    __nv_bfloat16 *X0qh, *X0ql, *X1qh, *X1ql;
    SYM(X0qh, g_X0qh); SYM(X0ql, g_X0ql); SYM(X1qh, g_X1qh); SYM(X1ql, g_X1ql);
    __nv_bfloat16 *bt0h, *bt0l, *bt1ah, *bt1al, *bt2h, *bt2l;
    SYM(bt0h, g_bt0h); SYM(bt0l, g_bt0l);
    SYM(bt1ah, g_bt1ah); SYM(bt1al, g_bt1al);
    SYM(bt2h, g_bt2h); SYM(bt2l, g_bt2l);
    __nv_bfloat16 *bb0h, *bb0l, *bb1ah, *bb1al, *bb1bh, *bb1bl;
    SYM(bb0h, g_bb0h); SYM(bb0l, g_bb0l);
    SYM(bb1ah, g_bb1ah); SYM(bb1al, g_bb1al);
    SYM(bb1bh, g_bb1bh); SYM(bb1bl, g_bb1bl);
    __nv_bfloat16 *Wn0h, *Wn0l, *Wn1h, *Wn1l, *Wn2h, *Wn2l;
    __nv_bfloat16 *We0h, *We0l, *WeD1h, *WeD1l, *WeD2h, *WeD2l;
    __nv_bfloat16 *WeU1h, *WeU1l, *WeU2h, *WeU2l, *Werh, *Werl;
    SYM(Wn0h, g_Wn0h); SYM(Wn0l, g_Wn0l);
    SYM(Wn1h, g_Wn1h); SYM(Wn1l, g_Wn1l);
    SYM(Wn2h, g_Wn2h); SYM(Wn2l, g_Wn2l);
    SYM(We0h, g_We0h); SYM(We0l, g_We0l);
    SYM(WeD1h, g_WeD1h); SYM(WeD1l, g_WeD1l);
    SYM(WeD2h, g_WeD2h); SYM(WeD2l, g_WeD2l);
    SYM(WeU1h, g_WeU1h); SYM(WeU1l, g_WeU1l);
    SYM(WeU2h, g_WeU2h); SYM(WeU2l, g_WeU2l);
    SYM(Werh, g_Werh); SYM(Werl, g_Werl);

    const size_t SZ0 = (size_t)Nn0 * 128, SZ1 = (size_t)Nn1 * 128;
    // pool offsets (floats)
    const size_t OFF_Pp = 0;                  // 4*SZ0
    const size_t OFF_Pq = 1100000;            // 2*SZ1
    const size_t OFF_Pr = 2700000;            // 3*SZ1
    const size_t OFF_InN = 5100000;           // SZ0
    const size_t OFF_InD = 5400000;           // SZ1
    const size_t OFF_InU = 6200000;           // SZ1
    const size_t OFF_PN = 7100000;            // 3*SZ0
    const size_t OFF_PD = 8000000;            // 5*SZ1
    const size_t OFF_PU = 11900000;           // 5*SZ1
    const size_t OFF_H0 = 0;                  // 3*SZ0
    const size_t OFF_H1 = 1000000;            // 10*SZ1
    const size_t OFF_L1P = 9000000;           // 6*SZ0
    const size_t OFF_L1A = 10700000;          // SZ0
    const size_t OFF_L1B = 11000000;          // 3*SZ0
    const size_t OFF_L1C = 11800000;          // 3*SZ0

    MMBatch mb = {}; RBatch rb = {};

    // ---- operator splits ----
    {
        SParams sp = {};
        int blks = 0;
        auto add = [&](const float* s, __nv_bfloat16* dh, __nv_bfloat16* dl, size_t cnt) {
            SJob& j = sp.j[sp.n++];
            j.src = s; j.dh = dh; j.dl = dl; j.n8 = (int)(cnt / 8); j.blkStart = blks;
            blks += (j.n8 + 255) / 256;
        };
        add(L1d, L1dh, L1dl, (size_t)Nn1 * Nn1);
        add(L1u, L1uh, L1ul, (size_t)Nn1 * Nn1);
        add(B1,  B1h,  B1l,  (size_t)Nn0 * Nn1);
        add(B2,  B2h,  B2l,  (size_t)Nn1 * Nn2);
        add(L0,  L0h,  L0l,  (size_t)Nn0 * Nn0);
        splitb_kernel<<<blks, 256>>>(sp);
    }
    tsplit1_kernel<<<((Nn0 + 31) / 32) * ((Nn1 + 31) / 32), dim3(32, 8)>>>(
        B1, B1th, B1tl, Nn1, Nn0, Nn1, (Nn0 + 31) / 32);

    // ---- input linears ----
    {
        LParams lp = {};
        lp.j[0] = { x0, in_w0, in_b0, h0, Nn0, 0 };
        lp.j[1] = { x1, in_w1, in_b1, h1, Nn1, Nn0 };
        lp.j[2] = { x2, in_w2, in_b2, h2, Nn2, Nn0 + Nn1 };
        lp.n = 3;
        linb_kernel<<<Nn0 + Nn1 + Nn2, CC>>>(lp);
    }

    // ---- layer-0 Horner weights (one launch, 9 jobs) ----
    {
        WParams wp = {};
        int blk = 0;
        auto add = [&](const float* w, __nv_bfloat16* dh, __nv_bfloat16* dl,
                       int korig, int m0, int m1) {
            WJob& j = wp.j[wp.n++];
            j.w = w; j.dh = dh; j.dl = dl; j.korig = korig; j.m0 = m0; j.m1 = m1;
            j.blkStart = blk;
            blk += ((m1 == -2) ? 1 : 2) * 128;
        };
        add(l0_w0, Wn0h, Wn0l, 6, 0, 3);
        add(l0_w0, Wn1h, Wn1l, 6, 1, 4);
        add(l0_w0, Wn2h, Wn2l, 6, 2, 5);
        add(l0_w1, We0h, We0l, 11, 0, 5);
        add(l0_w1, WeD1h, WeD1l, 11, 1, 6);
        add(l0_w1, WeD2h, WeD2l, 11, 2, 7);
        add(l0_w1, WeU1h, WeU1l, 11, 3, 9);
        add(l0_w1, WeU2h, WeU2l, 11, 4, 10);
        add(l0_w1, Werh, Werl, 11, 8, -2);
        wbuild_kernel<<<blk, 128>>>(wp);
    }

    // ---- hconv: rows + transposed h ----
    {
        HParams hp = {};
        int tiles = 0;
        int tr0 = (Nn0 + 31) / 32, tr1 = (Nn1 + 31) / 32, tr2 = (Nn2 + 31) / 32;
        hp.j[0] = { h0, X0qh, X0ql, nullptr, nullptr, bt0h, bt0l, Nn0, 256, tiles, tr0 };
        tiles += tr0 * 4;
        hp.j[1] = { h1, X1qh, X1ql, X1qh + 256, X1ql + 256, bt1ah, bt1al, Nn1, 512, tiles, tr1 };
        tiles += tr1 * 4;
        hp.j[2] = { h2, nullptr, nullptr, nullptr, nullptr, bt2h, bt2l, Nn2, 0, tiles, tr2 };
        tiles += tr2 * 4;
        hp.n = 3;
        hconv_kernel<<<tiles, dim3(32, 8)>>>(hp);
    }

    // P2: projections
    mmAddSplit(mb, B1h,  B1l,  Nn1, bt1ah, bt1al, Nn1, Nn0, 128, Nn1, 4, pool + OFF_Pp);
    mmAddSplit(mb, B2h,  B2l,  Nn2, bt2h,  bt2l,  Nn2, Nn1, 128, Nn2, 3, pool + OFF_Pr);
    mmAddSplit(mb, B1th, B1tl, Nn0, bt0h,  bt0l,  Nn0, Nn1, 128, Nn0, 2, pool + OFF_Pq);
    mmRun(mb);
    rAdd(rb, pool + OFF_Pp, 4, Nn0, 128, X0qh + 128, X0ql + 128, 256, nullptr, nullptr, 0);
    rAdd(rb, pool + OFF_Pr, 3, Nn1, 128, X1qh + 384, X1ql + 384, 512, nullptr, nullptr, 0);
    rAdd(rb, pool + OFF_Pq, 2, Nn1, 128, X1qh + 128, X1ql + 128, 512, nullptr, nullptr, 0);
    rRun(rb);

    // P4: inner channel mixes (K=256)
    mmAdd(mb, X1qh, X1ql, 512, WeD2h, WeD2l, 256, Nn1, 128, 256, pool + OFF_InD, 128);
    mmAdd(mb, X1qh + 256, X1ql + 256, 512, WeU2h, WeU2l, 256, Nn1, 128, 256, pool + OFF_InU, 128);
    mmAdd(mb, X0qh, X0ql, 256, Wn2h, Wn2l, 256, Nn0, 128, 256, pool + OFF_InN, 128);
    mmRun(mb);
    rAdd(rb, pool + OFF_InD, 1, Nn1, 128, nullptr, nullptr, 0, bb1ah, bb1al, Nn1);
    rAdd(rb, pool + OFF_InU, 1, Nn1, 128, nullptr, nullptr, 0, bb1bh, bb1bl, Nn1);
    rAdd(rb, pool + OFF_InN, 1, Nn0, 128, nullptr, nullptr, 0, bb0h, bb0l, Nn0);
    rRun(rb);

    // P6: first Horner hop + u-terms
    mmAddSplit(mb, L1dh, L1dl, Nn1, bb1ah, bb1al, Nn1, Nn1, 128, Nn1, 4, pool + OFF_PD);
    mmAddSplit(mb, L1uh, L1ul, Nn1, bb1bh, bb1bl, Nn1, Nn1, 128, Nn1, 4, pool + OFF_PU);
    mmAddSplit(mb, L0h,  L0l,  Nn0, bb0h,  bb0l,  Nn0, Nn0, 128, Nn0, 2, pool + OFF_PN);
    mmAdd(mb, X1qh, X1ql, 512, WeD1h, WeD1l, 256, Nn1, 128, 256, pool + OFF_PD + 4 * SZ1, 128);
    mmAdd(mb, X1qh + 256, X1ql + 256, 512, WeU1h, WeU1l, 256, Nn1, 128, 256, pool + OFF_PU + 4 * SZ1, 128);
    mmAdd(mb, X0qh, X0ql, 256, Wn1h, Wn1l, 256, Nn0, 128, 256, pool + OFF_PN + 2 * SZ0, 128);
    mmRun(mb);
    rAdd(rb, pool + OFF_PD, 5, Nn1, 128, nullptr, nullptr, 0, bb1ah, bb1al, Nn1);
    rAdd(rb, pool + OFF_PU, 5, Nn1, 128, nullptr, nullptr, 0, bb1bh, bb1bl, Nn1);
    rAdd(rb, pool + OFF_PN, 3, Nn0, 128, nullptr, nullptr, 0, bb0h, bb0l, Nn0);
    rRun(rb);

    // P8: second Horner hop + bases
    mmAddSplit(mb, L1dh, L1dl, Nn1, bb1ah, bb1al, Nn1, Nn1, 128, Nn1, 4, pool + OFF_H1);
    mmAddSplit(mb, L1uh, L1ul, Nn1, bb1bh, bb1bl, Nn1, Nn1, 128, Nn1, 4, pool + OFF_H1 + 4 * SZ1);
    mmAddSplit(mb, L0h,  L0l,  Nn0, bb0h,  bb0l,  Nn0, Nn0, 128, Nn0, 2, pool + OFF_H0);
    mmAdd(mb, X1qh, X1ql, 512, We0h, We0l, 256, Nn1, 128, 256, pool + OFF_H1 + 8 * SZ1, 128);
    mmAdd(mb, X1qh + 384, X1ql + 384, 512, Werh, Werl, 128, Nn1, 128, 128, pool + OFF_H1 + 9 * SZ1, 128);
    mmAdd(mb, X0qh, X0ql, 256, Wn0h, Wn0l, 256, Nn0, 128, 256, pool + OFF_H0 + 2 * SZ0, 128);
    mmRun(mb);

    // layer-1 node weights (independent of P8 results)
    {
        WParams wp = {};
        wp.j[0] = { l1_w0, Wn0h, Wn0l, 6, 0, 3, 0 };
        wp.j[1] = { l1_w0, Wn1h, Wn1l, 6, 1, 4, 256 };
        wp.j[2] = { l1_w0, Wn2h, Wn2l, 6, 2, 5, 512 };
        wp.n = 3;
        wbuild_kernel<<<768, 128>>>(wp);
    }

    // P9: h0' (row) and h1' (transposed)
    rAdd(rb, pool + OFF_H1, 10, Nn1, 128, nullptr, nullptr, 0, bt1ah, bt1al, Nn1);
    rAdd(rb, pool + OFF_H0, 3, Nn0, 128, X0qh, X0ql, 256, nullptr, nullptr, 0);
    rRun(rb);

    // ============ LAYER 1 ============
    // p' = B1 @ h1'
    mmAddSplit(mb, B1h, B1l, Nn1, bt1ah, bt1al, Nn1, Nn0, 128, Nn1, 6, pool + OFF_L1P);
    mmRun(mb);
    rAdd(rb, pool + OFF_L1P, 6, Nn0, 128, X0qh + 128, X0ql + 128, 256, nullptr, nullptr, 0);
    rRun(rb);

    // inner
    mmAdd(mb, X0qh, X0ql, 256, Wn2h, Wn2l, 256, Nn0, 128, 256, pool + OFF_L1A, 128);
    mmRun(mb);
    rAdd(rb, pool + OFF_L1A, 1, Nn0, 128, nullptr, nullptr, 0, bb0h, bb0l, Nn0);
    rRun(rb);

    // hop1 + u
    mmAddSplit(mb, L0h, L0l, Nn0, bb0h, bb0l, Nn0, Nn0, 128, Nn0, 2, pool + OFF_L1B);
    mmAdd(mb, X0qh, X0ql, 256, Wn1h, Wn1l, 256, Nn0, 128, 256, pool + OFF_L1B + 2 * SZ0, 128);
    mmRun(mb);
    rAdd(rb, pool + OFF_L1B, 3, Nn0, 128, nullptr, nullptr, 0, bb0h, bb0l, Nn0);
    rRun(rb);

    // hop2 + base -> fp32 h0''
    mmAddSplit(mb, L0h, L0l, Nn0, bb0h, bb0l, Nn0, Nn0, 128, Nn0, 2, pool + OFF_L1C);
    mmAdd(mb, X0qh, X0ql, 256, Wn0h, Wn0l, 256, Nn0, 128, 256, pool + OFF_L1C + 2 * SZ0, 128);
    mmRun(mb);
    rAdd(rb, pool + OFF_L1C, 3, Nn0, 128, nullptr, nullptr, 0, nullptr, nullptr, 0, h0, 128);
    rRun(rb);

    head_kernel<<<(Nn0 * 2 + 255) / 256, 256>>>(h0, out_w, out_b, out, Nn0 * 2);
}

// round 13
// speedup vs baseline: 5.2370x; 1.0231x over previous
#include <cuda_runtime.h>
#include <cuda_bf16.h>
#include <math.h>
#include <stdint.h>

#define Nn0 2000
#define Nn1 6000
#define Nn2 4000
#define CC  128

// ================= static scratch (no allocation) =================
__device__ float g_h0[Nn0 * CC];
__device__ float g_h1[Nn1 * CC];
__device__ float g_h2[Nn2 * CC];

__device__ float g_part[24 * 1024 * 1024];   // fp32 partial pool (96MB)

// operators bf16 hi/lo
__device__ __nv_bfloat16 g_L0h[Nn0 * Nn0],  g_L0l[Nn0 * Nn0];
__device__ __nv_bfloat16 g_L1dh[Nn1 * Nn1], g_L1dl[Nn1 * Nn1];
__device__ __nv_bfloat16 g_L1uh[Nn1 * Nn1], g_L1ul[Nn1 * Nn1];
__device__ __nv_bfloat16 g_B1h[Nn0 * Nn1],  g_B1l[Nn0 * Nn1];
__device__ __nv_bfloat16 g_B1th[Nn1 * Nn0], g_B1tl[Nn1 * Nn0];
__device__ __nv_bfloat16 g_B2h[Nn1 * Nn2],  g_B2l[Nn1 * Nn2];

// row-major bf16 A operands: X0 = [h0|p] (ld 256), X1 = [h1|q|h1|r] (ld 512)
__device__ __nv_bfloat16 g_X0qh[Nn0 * 256], g_X0ql[Nn0 * 256];
__device__ __nv_bfloat16 g_X1qh[Nn1 * 512], g_X1ql[Nn1 * 512];

// transposed bf16 buffers
__device__ __nv_bfloat16 g_bt0h[128 * Nn0],  g_bt0l[128 * Nn0];
__device__ __nv_bfloat16 g_bt1ah[128 * Nn1], g_bt1al[128 * Nn1];
__device__ __nv_bfloat16 g_bt2h[128 * Nn2],  g_bt2l[128 * Nn2];
__device__ __nv_bfloat16 g_bb0h[128 * Nn0],  g_bb0l[128 * Nn0];
__device__ __nv_bfloat16 g_bb1ah[128 * Nn1], g_bb1al[128 * Nn1];
__device__ __nv_bfloat16 g_bb1bh[128 * Nn1], g_bb1bl[128 * Nn1];

// combined Horner weights, transposed bf16 hi/lo
#define WSZ (2 * 128 * 128)
__device__ __nv_bfloat16 g_Wn0h[WSZ], g_Wn0l[WSZ];
__device__ __nv_bfloat16 g_Wn1h[WSZ], g_Wn1l[WSZ];
__device__ __nv_bfloat16 g_Wn2h[WSZ], g_Wn2l[WSZ];
__device__ __nv_bfloat16 g_We0h[WSZ], g_We0l[WSZ];
__device__ __nv_bfloat16 g_WeD1h[WSZ], g_WeD1l[WSZ];
__device__ __nv_bfloat16 g_WeD2h[WSZ], g_WeD2l[WSZ];
__device__ __nv_bfloat16 g_WeU1h[WSZ], g_WeU1l[WSZ];
__device__ __nv_bfloat16 g_WeU2h[WSZ], g_WeU2l[WSZ];
__device__ __nv_bfloat16 g_Werh[128 * 128], g_Werl[128 * 128];

// ================= PTX helpers =================
__device__ __forceinline__ uint32_t smem_u32(const void* p) {
    uint32_t a;
    asm("{ .reg .u64 t; cvta.to.shared.u64 t, %1; cvt.u32.u64 %0, t; }" : "=r"(a) : "l"(p));
    return a;
}
__device__ __forceinline__ void ldsm_x4(uint32_t* r, uint32_t a) {
    asm volatile("ldmatrix.sync.aligned.m8n8.x4.shared.b16 {%0,%1,%2,%3}, [%4];"
                 : "=r"(r[0]), "=r"(r[1]), "=r"(r[2]), "=r"(r[3]) : "r"(a));
}
__device__ __forceinline__ void mma_bf16(float* c, const uint32_t* a, const uint32_t* b) {
    asm volatile(
        "mma.sync.aligned.m16n8k16.row.col.f32.bf16.bf16.f32 "
        "{%0,%1,%2,%3}, {%4,%5,%6,%7}, {%8,%9}, {%0,%1,%2,%3};"
        : "+f"(c[0]), "+f"(c[1]), "+f"(c[2]), "+f"(c[3])
        : "r"(a[0]), "r"(a[1]), "r"(a[2]), "r"(a[3]), "r"(b[0]), "r"(b[1]));
}
__device__ __forceinline__ void cp_async16(uint32_t dst, const void* src, int sz) {
    asm volatile("cp.async.cg.shared.global [%0], [%1], 16, %2;"
                 :: "r"(dst), "l"(src), "r"(sz));
}
__device__ __forceinline__ uint32_t sw_addr(uint32_t tile_base, int r, int chunk) {
    return tile_base + (uint32_t)(r * 64) + (uint32_t)((chunk ^ ((r >> 1) & 3)) << 4);
}

// ================= batched bf16x3 HMMA GEMM + fused epilogue =================
#define MM_SMEM (3 * 4 * 8192)
#define MAXJOB 14

struct MMJob {
    const __nv_bfloat16 *Ah, *Al, *Bh, *Bl;
    float* Cf;
    __nv_bfloat16 *Rh, *Rl;
    __nv_bfloat16 *Th, *Tl;
    int M, K, lda, ldb, ldc, ldR, ldT, tileStart, tilesX;
};
struct MMParams { MMJob j[MAXJOB]; int n; };

__global__ __launch_bounds__(256, 2)
void mmb_kernel(MMParams P)
{
    extern __shared__ __align__(128) char smem[];
    const uint32_t sbase = smem_u32(smem);
    const int tid = threadIdx.x, lane = tid & 31, wid = tid >> 5;
    const int wm = wid & 1, wn = wid >> 1;

    int bt = blockIdx.x;
    int ji = 0;
#pragma unroll 1
    while (ji + 1 < P.n && bt >= P.j[ji + 1].tileStart) ji++;
    const MMJob jb = P.j[ji];
    const int rel = bt - jb.tileStart;
    const int m0 = (rel % jb.tilesX) * 128;
    const int n0 = (rel / jb.tilesX) * 128;
    const int M = jb.M, K = jb.K, lda = jb.lda, ldb = jb.ldb;
    const int mrows = (M - m0 < 128) ? (M - m0) : 128;
    const __nv_bfloat16* Ah = jb.Ah + (size_t)m0 * lda;
    const __nv_bfloat16* Al = jb.Al + (size_t)m0 * lda;
    const __nv_bfloat16* Bh = jb.Bh + (size_t)n0 * ldb;
    const __nv_bfloat16* Bl = jb.Bl + (size_t)n0 * ldb;
    const int nk = (K + 31) >> 5;

    float acc[4][4][4];
#pragma unroll
    for (int i = 0; i < 4; i++)
#pragma unroll
        for (int j = 0; j < 4; j++)
#pragma unroll
            for (int v = 0; v < 4; v++) acc[i][j][v] = 0.f;

    auto load_stage = [&](int t) {
        const uint32_t sb = sbase + (uint32_t)(t % 3) * 32768;
        const int k0 = t << 5;
#pragma unroll
        for (int i = 0; i < 8; i++) {
            int idx = tid + i * 256;
            int tile = idx >> 9;
            int rem  = idx & 511;
            int r = rem >> 2, c = rem & 3;
            const __nv_bfloat16* gp;
            int ok;
            if (tile < 2) {
                gp = (tile == 0 ? Ah : Al) + (size_t)r * lda + k0 + c * 8;
                ok = (r < mrows) && (k0 + c * 8 < K);
            } else {
                gp = (tile == 2 ? Bh : Bl) + (size_t)r * ldb + k0 + c * 8;
                ok = (k0 + c * 8 < K);
            }
            cp_async16(sb + (uint32_t)tile * 8192 + sw_addr(0, r, c), gp, ok ? 16 : 0);
        }
    };

#pragma unroll
    for (int s = 0; s < 2; s++) {
        if (s < nk) load_stage(s);
        asm volatile("cp.async.commit_group;" ::: "memory");
    }

    const int frag_r = lane & 15;
    const int frag_c = lane >> 4;

    for (int t = 0; t < nk; t++) {
        asm volatile("cp.async.wait_group 1;" ::: "memory");
        __syncthreads();
        const uint32_t sb = sbase + (uint32_t)(t % 3) * 32768;
        const uint32_t tAh = sb, tAl = sb + 8192, tBh = sb + 16384, tBl = sb + 24576;

#pragma unroll
        for (int ks = 0; ks < 2; ks++) {
            const int ch = ks * 2 + frag_c;
            uint32_t bh[4][2], bl[4][2];
#pragma unroll
            for (int j = 0; j < 2; j++) {
                int r = wn * 32 + j * 16 + frag_r;
                uint32_t rr[4];
                ldsm_x4(rr, sw_addr(tBh, r, ch));
                bh[2 * j][0] = rr[0]; bh[2 * j][1] = rr[2];
                bh[2 * j + 1][0] = rr[1]; bh[2 * j + 1][1] = rr[3];
                ldsm_x4(rr, sw_addr(tBl, r, ch));
                bl[2 * j][0] = rr[0]; bl[2 * j][1] = rr[2];
                bl[2 * j + 1][0] = rr[1]; bl[2 * j + 1][1] = rr[3];
            }
#pragma unroll
            for (int mt = 0; mt < 4; mt++) {
                int r = wm * 64 + mt * 16 + frag_r;
                uint32_t ah[4], al[4];
                ldsm_x4(ah, sw_addr(tAh, r, ch));
                ldsm_x4(al, sw_addr(tAl, r, ch));
#pragma unroll
                for (int nt = 0; nt < 4; nt++) mma_bf16(acc[mt][nt], ah, bh[nt]);
#pragma unroll
                for (int nt = 0; nt < 4; nt++) mma_bf16(acc[mt][nt], ah, bl[nt]);
#pragma unroll
                for (int nt = 0; nt < 4; nt++) mma_bf16(acc[mt][nt], al, bh[nt]);
            }
        }
        if (t + 2 < nk) load_stage(t + 2);
        asm volatile("cp.async.commit_group;" ::: "memory");
    }

    // ---- fused epilogue: fp32 / row-bf16 / transposed-bf16 ----
    const int er = lane >> 2, ec = (lane & 3) * 2;
    const bool doBF = (jb.Rh != nullptr) || (jb.Th != nullptr);
#pragma unroll
    for (int mt = 0; mt < 4; mt++) {
        int r0 = m0 + wm * 64 + mt * 16 + er;
        int r1 = r0 + 8;
#pragma unroll
        for (int nt = 0; nt < 4; nt++) {
            int col = n0 + wn * 32 + nt * 8 + ec;
            float f0 = acc[mt][nt][0], f1 = acc[mt][nt][1];
            float f2 = acc[mt][nt][2], f3 = acc[mt][nt][3];
            if (jb.Cf) {
                if (r0 < M) *(float2*)&jb.Cf[(size_t)r0 * jb.ldc + col] = make_float2(f0, f1);
                if (r1 < M) *(float2*)&jb.Cf[(size_t)r1 * jb.ldc + col] = make_float2(f2, f3);
            }
            if (doBF) {
                __nv_bfloat16 h0 = __float2bfloat16(f0), h1 = __float2bfloat16(f1);
                __nv_bfloat16 h2 = __float2bfloat16(f2), h3 = __float2bfloat16(f3);
                __nv_bfloat16 l0 = __float2bfloat16(f0 - __bfloat162float(h0));
                __nv_bfloat16 l1 = __float2bfloat16(f1 - __bfloat162float(h1));
                __nv_bfloat16 l2 = __float2bfloat16(f2 - __bfloat162float(h2));
                __nv_bfloat16 l3 = __float2bfloat16(f3 - __bfloat162float(h3));
                if (jb.Rh) {
                    if (r0 < M) {
                        *(__nv_bfloat162*)&jb.Rh[(size_t)r0 * jb.ldR + col] = __halves2bfloat162(h0, h1);
                        *(__nv_bfloat162*)&jb.Rl[(size_t)r0 * jb.ldR + col] = __halves2bfloat162(l0, l1);
                    }
                    if (r1 < M) {
                        *(__nv_bfloat162*)&jb.Rh[(size_t)r1 * jb.ldR + col] = __halves2bfloat162(h2, h3);
                        *(__nv_bfloat162*)&jb.Rl[(size_t)r1 * jb.ldR + col] = __halves2bfloat162(l2, l3);
                    }
                }
                if (jb.Th) {
                    size_t cA = (size_t)col * jb.ldT, cB = (size_t)(col + 1) * jb.ldT;
                    if (r0 < M) {
                        jb.Th[cA + r0] = h0; jb.Th[cB + r0] = h1;
                        jb.Tl[cA + r0] = l0; jb.Tl[cB + r0] = l1;
                    }
                    if (r1 < M) {
                        jb.Th[cA + r1] = h2; jb.Th[cB + r1] = h3;
                        jb.Tl[cA + r1] = l2; jb.Tl[cB + r1] = l3;
                    }
                }
            }
        }
    }
}

// ================= reduce-convert =================
struct RJob {
    const float* base; int nP, pStride, M, N;
    __nv_bfloat16 *Rh, *Rl; int ldR;
    __nv_bfloat16 *Th, *Tl; int ldT;
    float* Cf; int ldc;
    int tileStart, tilesR;
};
struct RParams { RJob j[4]; int n; };

__global__ void rcvt_kernel(RParams P)
{
    __shared__ float tile[32][33];
    int b = blockIdx.x;
    int ji = 0;
#pragma unroll 1
    while (ji + 1 < P.n && b >= P.j[ji + 1].tileStart) ji++;
    const RJob jb = P.j[ji];
    int rel = b - jb.tileStart;
    int r0 = (rel % jb.tilesR) * 32, c0 = (rel / jb.tilesR) * 32;
    int tx = threadIdx.x, ty = threadIdx.y;
    for (int i = ty; i < 32; i += 8) {
        int r = r0 + i, c = c0 + tx;
        float v = 0.f;
        if (r < jb.M) {
            size_t off = (size_t)r * jb.N + c;
#pragma unroll 1
            for (int s = 0; s < jb.nP; s++) v += jb.base[off + (size_t)s * jb.pStride];
        }
        tile[i][tx] = v;
        if (r < jb.M) {
            if (jb.Cf) jb.Cf[(size_t)r * jb.ldc + c] = v;
            if (jb.Rh) {
                __nv_bfloat16 h = __float2bfloat16(v);
                jb.Rh[(size_t)r * jb.ldR + c] = h;
                jb.Rl[(size_t)r * jb.ldR + c] = __float2bfloat16(v - __bfloat162float(h));
            }
        }
    }
    __syncthreads();
    if (!jb.Th) return;
    for (int i = ty; i < 32; i += 8) {
        int c = c0 + i, r = r0 + tx;
        if (r < jb.M) {
            float v = tile[tx][i];
            __nv_bfloat16 h = __float2bfloat16(v);
            size_t idx = (size_t)c * jb.ldT + r;
            jb.Th[idx] = h;
            jb.Tl[idx] = __float2bfloat16(v - __bfloat162float(h));
        }
    }
}

// ================= operator split =================
struct SJob { const float* src; __nv_bfloat16 *dh, *dl; int n8, blkStart; };
struct SParams { SJob j[8]; int n; };

__global__ void splitb_kernel(SParams P)
{
    int b = blockIdx.x;
    int ji = 0;
#pragma unroll 1
    while (ji + 1 < P.n && b >= P.j[ji + 1].blkStart) ji++;
    const SJob jb = P.j[ji];
    int i = (b - jb.blkStart) * 256 + threadIdx.x;
    if (i >= jb.n8) return;
    float4 v0 = ((const float4*)jb.src)[i * 2];
    float4 v1 = ((const float4*)jb.src)[i * 2 + 1];
    __nv_bfloat162 h[4], l[4];
    h[0] = __floats2bfloat162_rn(v0.x, v0.y);
    h[1] = __floats2bfloat162_rn(v0.z, v0.w);
    h[2] = __floats2bfloat162_rn(v1.x, v1.y);
    h[3] = __floats2bfloat162_rn(v1.z, v1.w);
    l[0] = __floats2bfloat162_rn(v0.x - __bfloat162float(h[0].x), v0.y - __bfloat162float(h[0].y));
    l[1] = __floats2bfloat162_rn(v0.z - __bfloat162float(h[1].x), v0.w - __bfloat162float(h[1].y));
    l[2] = __floats2bfloat162_rn(v1.x - __bfloat162float(h[2].x), v1.y - __bfloat162float(h[2].y));
    l[3] = __floats2bfloat162_rn(v1.z - __bfloat162float(h[3].x), v1.w - __bfloat162float(h[3].y));
    ((uint4*)jb.dh)[i] = *(uint4*)h;
    ((uint4*)jb.dl)[i] = *(uint4*)l;
}

// ================= transpose-split (B1^T) =================
__global__ void tsplit1_kernel(const float* __restrict__ src,
                               __nv_bfloat16* __restrict__ dh, __nv_bfloat16* __restrict__ dl,
                               int lds, int rows, int cols, int tilesR)
{
    __shared__ float tile[32][33];
    int rel = blockIdx.x;
    int k0 = (rel % tilesR) * 32, n0 = (rel / tilesR) * 32;
    int tx = threadIdx.x, ty = threadIdx.y;
    for (int i = ty; i < 32; i += 8) {
        int k = k0 + i, n = n0 + tx;
        tile[i][tx] = (k < rows && n < cols) ? src[(size_t)k * lds + n] : 0.f;
    }
    __syncthreads();
    for (int i = ty; i < 32; i += 8) {
        int n = n0 + i, k = k0 + tx;
        if (n < cols && k < rows) {
            float v = tile[tx][i];
            __nv_bfloat16 h = __float2bfloat16(v);
            dh[(size_t)n * rows + k] = h;
            dl[(size_t)n * rows + k] = __float2bfloat16(v - __bfloat162float(h));
        }
    }
}

// ================= hconv =================
struct HJob {
    const float* src;
    __nv_bfloat16 *Rh, *Rl, *R2h, *R2l;
    __nv_bfloat16 *Th, *Tl;
    int rows, ldR, tileStart, tilesR;
};
struct HParams { HJob j[3]; int n; };

__global__ void hconv_kernel(HParams P)
{
    __shared__ float tile[32][33];
    int b = blockIdx.x;
    int ji = 0;
#pragma unroll 1
    while (ji + 1 < P.n && b >= P.j[ji + 1].tileStart) ji++;
    const HJob jb = P.j[ji];
    int rel = b - jb.tileStart;
    int r0 = (rel % jb.tilesR) * 32, c0 = (rel / jb.tilesR) * 32;
    int tx = threadIdx.x, ty = threadIdx.y;
    for (int i = ty; i < 32; i += 8) {
        int r = r0 + i, c = c0 + tx;
        float v = (r < jb.rows) ? jb.src[(size_t)r * CC + c] : 0.f;
        tile[i][tx] = v;
        if (r < jb.rows && jb.Rh) {
            __nv_bfloat16 h = __float2bfloat16(v);
            __nv_bfloat16 l = __float2bfloat16(v - __bfloat162float(h));
            jb.Rh[(size_t)r * jb.ldR + c] = h;
            jb.Rl[(size_t)r * jb.ldR + c] = l;
            if (jb.R2h) { jb.R2h[(size_t)r * jb.ldR + c] = h; jb.R2l[(size_t)r * jb.ldR + c] = l; }
        }
    }
    __syncthreads();
    if (!jb.Th) return;
    for (int i = ty; i < 32; i += 8) {
        int c = c0 + i, r = r0 + tx;
        if (r < jb.rows) {
            float v = tile[tx][i];
            __nv_bfloat16 h = __float2bfloat16(v);
            size_t idx = (size_t)c * jb.rows + r;
            jb.Th[idx] = h;
            jb.Tl[idx] = __float2bfloat16(v - __bfloat162float(h));
        }
    }
}

// ================= input linear =================
struct LJob { const float *x, *W, *b; float* y; int rows, rowStart; };
struct LParams { LJob j[3]; int n; };

__global__ void linb_kernel(LParams P)
{
    __shared__ float xs[CC];
    int b = blockIdx.x;
    int ji = 0;
#pragma unroll 1
    while (ji + 1 < P.n && b >= P.j[ji + 1].rowStart) ji++;
    const LJob jb = P.j[ji];
    int n = b - jb.rowStart, o = threadIdx.x;
    xs[o] = jb.x[(size_t)n * CC + o];
    __syncthreads();
    float acc = jb.b[o];
    const float* wr = &jb.W[(size_t)o * CC];
#pragma unroll 8
    for (int i = 0; i < CC; i++) acc += xs[i] * wr[i];
    jb.y[(size_t)n * CC + o] = acc;
}

// ================= Horner weight builder =================
struct WJob { const float* w; __nv_bfloat16 *dh, *dl; int korig, m0, m1, blkStart; };
struct WParams { WJob j[9]; int n; };

__global__ void wbuild_kernel(WParams P)
{
    int b = blockIdx.x;
    int ji = 0;
#pragma unroll 1
    while (ji + 1 < P.n && b >= P.j[ji + 1].blkStart) ji++;
    const WJob jb = P.j[ji];
    int rel = b - jb.blkStart;
    int s = rel >> 7, o = rel & 127;
    int i = threadIdx.x;
    int S = (jb.m1 == -2) ? 1 : 2;
    int k = (s == 0) ? jb.m0 : jb.m1;
    float v = (k >= 0) ? jb.w[((size_t)i * CC + o) * jb.korig + k] : 0.f;
    __nv_bfloat16 h = __float2bfloat16(v);
    size_t idx = (size_t)o * (S * 128) + s * 128 + i;
    jb.dh[idx] = h;
    jb.dl[idx] = __float2bfloat16(v - __bfloat162float(h));
}

__global__ void head_kernel(const float* __restrict__ h0, const float* __restrict__ ow,
                            const float* __restrict__ ob, float* __restrict__ out, int total)
{
    int idx = blockIdx.x * blockDim.x + threadIdx.x;
    if (idx >= total) return;
    int n = idx >> 1, c = idx & 1;
    float acc = ob[c];
    const float* hr = &h0[(size_t)n * CC];
    const float* wr = &ow[(size_t)c * CC];
#pragma unroll 8
    for (int i = 0; i < CC; i++) acc += hr[i] * wr[i];
    out[idx] = 1.f / (1.f + expf(-acc));
}

// ================= host-side builders =================
struct MMBatch { MMParams p; int tiles; };
static void mmAdd(MMBatch& b,
                  const __nv_bfloat16* Ah, const __nv_bfloat16* Al, int lda,
                  const __nv_bfloat16* Bh, const __nv_bfloat16* Bl, int ldb,
                  int M, int N, int K,
                  float* Cf, int ldc,
                  __nv_bfloat16* Rh = nullptr, __nv_bfloat16* Rl = nullptr, int ldR = 0,
                  __nv_bfloat16* Th = nullptr, __nv_bfloat16* Tl = nullptr, int ldT = 0)
{
    MMJob& j = b.p.j[b.p.n++];
    j.Ah = Ah; j.Al = Al; j.Bh = Bh; j.Bl = Bl;
    j.Cf = Cf; j.Rh = Rh; j.Rl = Rl; j.Th = Th; j.Tl = Tl;
    j.M = M; j.K = K; j.lda = lda; j.ldb = ldb; j.ldc = ldc; j.ldR = ldR; j.ldT = ldT;
    j.tileStart = b.tiles; j.tilesX = (M + 127) / 128;
    b.tiles += j.tilesX * (N / 128);
}
static void mmAddSplit(MMBatch& b,
                       const __nv_bfloat16* Ah, const __nv_bfloat16* Al, int lda,
                       const __nv_bfloat16* Bh, const __nv_bfloat16* Bl, int ldb,
                       int M, int N, int K, int nsp, float* part)
{
    int chunk = (((K + nsp - 1) / nsp) + 7) & ~7;
    for (int s = 0; s < nsp; s++) {
        int k0 = s * chunk;
        int kl = (K - k0 < chunk) ? (K - k0) : chunk;
        mmAdd(b, Ah + k0, Al + k0, lda, Bh + k0, Bl + k0, ldb, M, N, kl,
              part + (size_t)s * M * N, N);
    }
}
static void mmRun(MMBatch& b)
{
    if (b.p.n) mmb_kernel<<<b.tiles, 256, MM_SMEM>>>(b.p);
    b.p.n = 0; b.tiles = 0;
}

struct RBatch { RParams p; int tiles; };
static void rAdd(RBatch& b, const float* base, int nP, int M, int N,
                 __nv_bfloat16* Rh, __nv_bfloat16* Rl, int ldR,
                 __nv_bfloat16* Th, __nv_bfloat16* Tl, int ldT,
                 float* Cf = nullptr, int ldc = 0)
{
    RJob& j = b.p.j[b.p.n++];
    j.base = base; j.nP = nP; j.pStride = M * N; j.M = M; j.N = N;
    j.Rh = Rh; j.Rl = Rl; j.ldR = ldR; j.Th = Th; j.Tl = Tl; j.ldT = ldT;
    j.Cf = Cf; j.ldc = ldc;
    j.tileStart = b.tiles; j.tilesR = (M + 31) / 32;
    b.tiles += j.tilesR * (N / 32);
}
static void rRun(RBatch& b)
{
    if (b.p.n) rcvt_kernel<<<b.tiles, dim3(32, 8)>>>(b.p);
    b.p.n = 0; b.tiles = 0;
}

#define SYM(v, g) { void* p_; cudaGetSymbolAddress(&p_, g); v = (decltype(v))p_; }

extern "C" void kernel_launch(void* const* d_in, const int* in_sizes, int n_in,
                              void* d_out, int out_size)
{
    (void)in_sizes; (void)n_in; (void)out_size;
    const float* x0    = (const float*)d_in[0];
    const float* x1    = (const float*)d_in[1];
    const float* x2    = (const float*)d_in[2];
    const float* L0    = (const float*)d_in[3];
    const float* L1d   = (const float*)d_in[4];
    const float* L1u   = (const float*)d_in[5];
    const float* B1    = (const float*)d_in[8];
    const float* B2    = (const float*)d_in[9];
    const float* in_w0 = (const float*)d_in[10];
    const float* in_b0 = (const float*)d_in[11];
    const float* in_w1 = (const float*)d_in[12];
    const float* in_b1 = (const float*)d_in[13];
    const float* in_w2 = (const float*)d_in[14];
    const float* in_b2 = (const float*)d_in[15];
    const float* l0_w0 = (const float*)d_in[16];
    const float* l0_w1 = (const float*)d_in[17];
    const float* l1_w0 = (const float*)d_in[19];
    const float* out_w = (const float*)d_in[22];
    const float* out_b = (const float*)d_in[23];
    float* out = (float*)d_out;

    cudaFuncSetAttribute(mmb_kernel, cudaFuncAttributeMaxDynamicSharedMemorySize, MM_SMEM);

    float *h0, *h1, *h2, *pool;
    SYM(h0, g_h0); SYM(h1, g_h1); SYM(h2, g_h2); SYM(pool, g_part);
    __nv_bfloat16 *L0h, *L0l, *L1dh, *L1dl, *L1uh, *L1ul;
    __nv_bfloat16 *B1h, *B1l, *B1th, *B1tl, *B2h, *B2l;
    SYM(L0h, g_L0h); SYM(L0l, g_L0l);
    SYM(L1dh, g_L1dh); SYM(L1dl, g_L1dl); SYM(L1uh, g_L1uh); SYM(L1ul, g_L1ul);
    SYM(B1h, g_B1h); SYM(B1l, g_B1l); SYM(B1th, g_B1th); SYM(B1tl, g_B1tl);
    SYM(B2h, g_B2h); SYM(B2l, g_B2l);
    __nv_bfloat16 *X0qh, *X0ql, *X1qh, *X1ql;
    SYM(X0qh, g_X0qh); SYM(X0ql, g_X0ql); SYM(X1qh, g_X1qh); SYM(X1ql, g_X1ql);
    __nv_bfloat16 *bt0h, *bt0l, *bt1ah, *bt1al, *bt2h, *bt2l;
    SYM(bt0h, g_bt0h); SYM(bt0l, g_bt0l);
    SYM(bt1ah, g_bt1ah); SYM(bt1al, g_bt1al);
    SYM(bt2h, g_bt2h); SYM(bt2l, g_bt2l);
    __nv_bfloat16 *bb0h, *bb0l, *bb1ah, *bb1al, *bb1bh, *bb1bl;
    SYM(bb0h, g_bb0h); SYM(bb0l, g_bb0l);
    SYM(bb1ah, g_bb1ah); SYM(bb1al, g_bb1al);
    SYM(bb1bh, g_bb1bh); SYM(bb1bl, g_bb1bl);
    __nv_bfloat16 *Wn0h, *Wn0l, *Wn1h, *Wn1l, *Wn2h, *Wn2l;
    __nv_bfloat16 *We0h, *We0l, *WeD1h, *WeD1l, *WeD2h, *WeD2l;
    __nv_bfloat16 *WeU1h, *WeU1l, *WeU2h, *WeU2l, *Werh, *Werl;
    SYM(Wn0h, g_Wn0h); SYM(Wn0l, g_Wn0l);
    SYM(Wn1h, g_Wn1h); SYM(Wn1l, g_Wn1l);
    SYM(Wn2h, g_Wn2h); SYM(Wn2l, g_Wn2l);
    SYM(We0h, g_We0h); SYM(We0l, g_We0l);
    SYM(WeD1h, g_WeD1h); SYM(WeD1l, g_WeD1l);
    SYM(WeD2h, g_WeD2h); SYM(WeD2l, g_WeD2l);
    SYM(WeU1h, g_WeU1h); SYM(WeU1l, g_WeU1l);
    SYM(WeU2h, g_WeU2h); SYM(WeU2l, g_WeU2l);
    SYM(Werh, g_Werh); SYM(Werl, g_Werl);

    const size_t SZ0 = (size_t)Nn0 * 128, SZ1 = (size_t)Nn1 * 128;
    // pool offsets (floats)
    const size_t OFF_Pp = 0;           // 4*SZ0
    const size_t OFF_Pq = 1100000;     // 2*SZ1
    const size_t OFF_Pr = 2700000;     // 3*SZ1
    const size_t OFF_PD = 5100000;     // 5*SZ1 (4 splits + u-term)
    const size_t OFF_PU = 9000000;     // 5*SZ1
    const size_t OFF_PN = 12900000;    // 4*SZ0 (3 splits + u-term)
    const size_t OFF_H1 = 14000000;    // 10*SZ1 (4+4 splits + base We0 + base Wer)
    const size_t OFF_H0 = 21700000;    // 4*SZ0 (3 splits + base)
    const size_t OFF_L1P = 0;          // 6*SZ0
    const size_t OFF_R1 = 2000000;     // 5*SZ0 (4 splits + u)
    const size_t OFF_R2 = 3500000;     // 5*SZ0 (4 splits + base)

    MMBatch mb = {}; RBatch rb = {};

    // ---- operator splits ----
    {
        SParams sp = {};
        int blks = 0;
        auto add = [&](const float* s, __nv_bfloat16* dh, __nv_bfloat16* dl, size_t cnt) {
            SJob& j = sp.j[sp.n++];
            j.src = s; j.dh = dh; j.dl = dl; j.n8 = (int)(cnt / 8); j.blkStart = blks;
            blks += (j.n8 + 255) / 256;
        };
        add(L1d, L1dh, L1dl, (size_t)Nn1 * Nn1);
        add(L1u, L1uh, L1ul, (size_t)Nn1 * Nn1);
        add(B1,  B1h,  B1l,  (size_t)Nn0 * Nn1);
        add(B2,  B2h,  B2l,  (size_t)Nn1 * Nn2);
        add(L0,  L0h,  L0l,  (size_t)Nn0 * Nn0);
        splitb_kernel<<<blks, 256>>>(sp);
    }
    tsplit1_kernel<<<((Nn0 + 31) / 32) * ((Nn1 + 31) / 32), dim3(32, 8)>>>(
        B1, B1th, B1tl, Nn1, Nn0, Nn1, (Nn0 + 31) / 32);

    // ---- input linears ----
    {
        LParams lp = {};
        lp.j[0] = { x0, in_w0, in_b0, h0, Nn0, 0 };
        lp.j[1] = { x1, in_w1, in_b1, h1, Nn1, Nn0 };
        lp.j[2] = { x2, in_w2, in_b2, h2, Nn2, Nn0 + Nn1 };
        lp.n = 3;
        linb_kernel<<<Nn0 + Nn1 + Nn2, CC>>>(lp);
    }

    // ---- layer-0 Horner weights ----
    {
        WParams wp = {};
        int blk = 0;
        auto add = [&](const float* w, __nv_bfloat16* dh, __nv_bfloat16* dl,
                       int korig, int m0, int m1) {
            WJob& j = wp.j[wp.n++];
            j.w = w; j.dh = dh; j.dl = dl; j.korig = korig; j.m0 = m0; j.m1 = m1;
            j.blkStart = blk;
            blk += ((m1 == -2) ? 1 : 2) * 128;
        };
        add(l0_w0, Wn0h, Wn0l, 6, 0, 3);
        add(l0_w0, Wn1h, Wn1l, 6, 1, 4);
        add(l0_w0, Wn2h, Wn2l, 6, 2, 5);
        add(l0_w1, We0h, We0l, 11, 0, 5);
        add(l0_w1, WeD1h, WeD1l, 11, 1, 6);
        add(l0_w1, WeD2h, WeD2l, 11, 2, 7);
        add(l0_w1, WeU1h, WeU1l, 11, 3, 9);
        add(l0_w1, WeU2h, WeU2l, 11, 4, 10);
        add(l0_w1, Werh, Werl, 11, 8, -2);
        wbuild_kernel<<<blk, 128>>>(wp);
    }

    // ---- hconv ----
    {
        HParams hp = {};
        int tiles = 0;
        int tr0 = (Nn0 + 31) / 32, tr1 = (Nn1 + 31) / 32, tr2 = (Nn2 + 31) / 32;
        hp.j[0] = { h0, X0qh, X0ql, nullptr, nullptr, bt0h, bt0l, Nn0, 256, tiles, tr0 };
        tiles += tr0 * 4;
        hp.j[1] = { h1, X1qh, X1ql, X1qh + 256, X1ql + 256, bt1ah, bt1al, Nn1, 512, tiles, tr1 };
        tiles += tr1 * 4;
        hp.j[2] = { h2, nullptr, nullptr, nullptr, nullptr, bt2h, bt2l, Nn2, 0, tiles, tr2 };
        tiles += tr2 * 4;
        hp.n = 3;
        hconv_kernel<<<tiles, dim3(32, 8)>>>(hp);
    }

    // P2: projections
    mmAddSplit(mb, B1h,  B1l,  Nn1, bt1ah, bt1al, Nn1, Nn0, 128, Nn1, 4, pool + OFF_Pp);
    mmAddSplit(mb, B2h,  B2l,  Nn2, bt2h,  bt2l,  Nn2, Nn1, 128, Nn2, 3, pool + OFF_Pr);
    mmAddSplit(mb, B1th, B1tl, Nn0, bt0h,  bt0l,  Nn0, Nn1, 128, Nn0, 2, pool + OFF_Pq);
    mmRun(mb);
    rAdd(rb, pool + OFF_Pp, 4, Nn0, 128, X0qh + 128, X0ql + 128, 256, nullptr, nullptr, 0);
    rAdd(rb, pool + OFF_Pr, 3, Nn1, 128, X1qh + 384, X1ql + 384, 512, nullptr, nullptr, 0);
    rAdd(rb, pool + OFF_Pq, 2, Nn1, 128, X1qh + 128, X1ql + 128, 512, nullptr, nullptr, 0);
    rRun(rb);

    // P4: ALL channel mixes. Inner -> T-epilogue direct; u-terms/bases -> pool slots.
    mmAdd(mb, X1qh, X1ql, 512, WeD2h, WeD2l, 256, Nn1, 128, 256,
          nullptr, 0, nullptr, nullptr, 0, bb1ah, bb1al, Nn1);
    mmAdd(mb, X1qh + 256, X1ql + 256, 512, WeU2h, WeU2l, 256, Nn1, 128, 256,
          nullptr, 0, nullptr, nullptr, 0, bb1bh, bb1bl, Nn1);
    mmAdd(mb, X0qh, X0ql, 256, Wn2h, Wn2l, 256, Nn0, 128, 256,
          nullptr, 0, nullptr, nullptr, 0, bb0h, bb0l, Nn0);
    mmAdd(mb, X1qh, X1ql, 512, WeD1h, WeD1l, 256, Nn1, 128, 256, pool + OFF_PD + 4 * SZ1, 128);
    mmAdd(mb, X1qh + 256, X1ql + 256, 512, WeU1h, WeU1l, 256, Nn1, 128, 256, pool + OFF_PU + 4 * SZ1, 128);
    mmAdd(mb, X0qh, X0ql, 256, Wn1h, Wn1l, 256, Nn0, 128, 256, pool + OFF_PN + 3 * SZ0, 128);
    mmAdd(mb, X1qh, X1ql, 512, We0h, We0l, 256, Nn1, 128, 256, pool + OFF_H1 + 8 * SZ1, 128);
    mmAdd(mb, X1qh + 384, X1ql + 384, 512, Werh, Werl, 128, Nn1, 128, 128, pool + OFF_H1 + 9 * SZ1, 128);
    mmAdd(mb, X0qh, X0ql, 256, Wn0h, Wn0l, 256, Nn0, 128, 256, pool + OFF_H0 + 3 * SZ0, 128);
    mmRun(mb);

    // P6: first Horner hops (pure L chains)
    mmAddSplit(mb, L1dh, L1dl, Nn1, bb1ah, bb1al, Nn1, Nn1, 128, Nn1, 4, pool + OFF_PD);
    mmAddSplit(mb, L1uh, L1ul, Nn1, bb1bh, bb1bl, Nn1, Nn1, 128, Nn1, 4, pool + OFF_PU);
    mmAddSplit(mb, L0h,  L0l,  Nn0, bb0h,  bb0l,  Nn0, Nn0, 128, Nn0, 3, pool + OFF_PN);
    mmRun(mb);
    rAdd(rb, pool + OFF_PD, 5, Nn1, 128, nullptr, nullptr, 0, bb1ah, bb1al, Nn1);
    rAdd(rb, pool + OFF_PU, 5, Nn1, 128, nullptr, nullptr, 0, bb1bh, bb1bl, Nn1);
    rAdd(rb, pool + OFF_PN, 4, Nn0, 128, nullptr, nullptr, 0, bb0h, bb0l, Nn0);
    rRun(rb);

    // P8: second Horner hops
    mmAddSplit(mb, L1dh, L1dl, Nn1, bb1ah, bb1al, Nn1, Nn1, 128, Nn1, 4, pool + OFF_H1);
    mmAddSplit(mb, L1uh, L1ul, Nn1, bb1bh, bb1bl, Nn1, Nn1, 128, Nn1, 4, pool + OFF_H1 + 4 * SZ1);
    mmAddSplit(mb, L0h,  L0l,  Nn0, bb0h,  bb0l,  Nn0, Nn0, 128, Nn0, 3, pool + OFF_H0);
    mmRun(mb);

    // layer-1 node weights (Wn* free after P4)
    {
        WParams wp = {};
        wp.j[0] = { l1_w0, Wn0h, Wn0l, 6, 0, 3, 0 };
        wp.j[1] = { l1_w0, Wn1h, Wn1l, 6, 1, 4, 256 };
        wp.j[2] = { l1_w0, Wn2h, Wn2l, 6, 2, 5, 512 };
        wp.n = 3;
        wbuild_kernel<<<768, 128>>>(wp);
    }

    // h1' (transposed) and h0' (row)
    rAdd(rb, pool + OFF_H1, 10, Nn1, 128, nullptr, nullptr, 0, bt1ah, bt1al, Nn1);
    rAdd(rb, pool + OFF_H0, 4, Nn0, 128, X0qh, X0ql, 256, nullptr, nullptr, 0);
    rRun(rb);

    // ============ LAYER 1 ============
    // p' = B1 @ h1'
    mmAddSplit(mb, B1h, B1l, Nn1, bt1ah, bt1al, Nn1, Nn0, 128, Nn1, 6, pool + OFF_L1P);
    mmRun(mb);
    rAdd(rb, pool + OFF_L1P, 6, Nn0, 128, X0qh + 128, X0ql + 128, 256, nullptr, nullptr, 0);
    rRun(rb);

    // inner (T-epi) + u-term + base in one launch
    mmAdd(mb, X0qh, X0ql, 256, Wn2h, Wn2l, 256, Nn0, 128, 256,
          nullptr, 0, nullptr, nullptr, 0, bb0h, bb0l, Nn0);
    mmAdd(mb, X0qh, X0ql, 256, Wn1h, Wn1l, 256, Nn0, 128, 256, pool + OFF_R1 + 4 * SZ0, 128);
    mmAdd(mb, X0qh, X0ql, 256, Wn0h, Wn0l, 256, Nn0, 128, 256, pool + OFF_R2 + 4 * SZ0, 128);
    mmRun(mb);

    // hop1 + u
    mmAddSplit(mb, L0h, L0l, Nn0, bb0h, bb0l, Nn0, Nn0, 128, Nn0, 4, pool + OFF_R1);
    mmRun(mb);
    rAdd(rb, pool + OFF_R1, 5, Nn0, 128, nullptr, nullptr, 0, bb0h, bb0l, Nn0);
    rRun(rb);

    // hop2 + base -> fp32 h0''
    mmAddSplit(mb, L0h, L0l, Nn0, bb0h, bb0l, Nn0, Nn0, 128, Nn0, 4, pool + OFF_R2);
    mmRun(mb);
    rAdd(rb, pool + OFF_R2, 5, Nn0, 128, nullptr, nullptr, 0, nullptr, nullptr, 0, h0, 128);
    rRun(rb);

    head_kernel<<<(Nn0 * 2 + 255) / 256, 256>>>(h0, out_w, out_b, out, Nn0 * 2);
}